// round 3
// baseline (speedup 1.0000x reference)
#include <cuda_runtime.h>
#include <cstdint>

// ---------------------------------------------------------------------------
// SelfAttentionWithPE: B=8, E=512, H=W=32 (S=1024), heads=8, head_dim=64, fp32
//
//   k_transpose_pe : x[b,E,32,32] -> xt[b*s, E]  (+positional encoding)
//   k_gemm_3xtf32  : projections on tensor cores with split-precision
//                    (hi+lo) 3xTF32 compensation -> ~fp32 accuracy
//   k_flash        : online-softmax attention -> att[b*s, E]   (fp32)
// ---------------------------------------------------------------------------

#define BATCH 8
#define EMB   512
#define SEQ   1024
#define NH    8
#define HD    64
#define MTOT  (BATCH * SEQ)         // 8192
#define SCALE 0.125f
#define FULLMASK 0xffffffffu

__device__ float g_scratch[5u * MTOT * EMB];

// ---------------------------------------------------------------------------
// Kernel 1: transpose + positional encoding
// ---------------------------------------------------------------------------
__global__ void k_transpose_pe(const float* __restrict__ x,
                               const float* __restrict__ pos_w,
                               const float* __restrict__ pos_b,
                               float* __restrict__ xt)
{
    __shared__ float tile[32][33];
    const int e0 = blockIdx.x * 32;
    const int s0 = blockIdx.y * 32;
    const int b  = blockIdx.z;
    const int tx = threadIdx.x;
    const int ty = threadIdx.y;

#pragma unroll
    for (int i = 0; i < 4; i++) {
        int el = ty + i * 8;
        tile[el][tx] = x[((size_t)(b * EMB + e0 + el)) * SEQ + s0 + tx];
    }
    __syncthreads();

    const int e = e0 + tx;
    const float pw0 = pos_w[e];
    const float pw1 = pos_w[EMB + e];
    const float pb  = pos_b[e];
#pragma unroll
    for (int i = 0; i < 4; i++) {
        int sl = ty + i * 8;
        int s  = s0 + sl;
        float row = (float)(s >> 5);
        float col = (float)(s & 31);
        float v = tile[tx][sl] + row * pw0 + col * pw1 + pb;
        xt[((size_t)(b * SEQ + s)) * EMB + e] = v;
    }
}

// ---------------------------------------------------------------------------
// Kernel 2: 3xTF32 tensor-core GEMM  C[8192,512] = A @ W[512,512] + bias
// BM=128, BN=64, BK=16. 256 threads, 8 warps (4x2), warp tile 32x32
// = 2 m16 x 4 n8 tiles of mma.sync.m16n8k8.tf32, 3 mmas each (hi/lo).
//
// smem planes (fragment-permuted; one LDS.128/LDS.64 per consumer frag):
//   A_hi [2 ks][8 mt][128]   A_lo same   (pitch A_KS = 1028)
//   B_hi [2 ks][8 nt][64]    B_lo same   (pitch B_KS = 514)
// ---------------------------------------------------------------------------
#define GK    512
#define A_KS  1028
#define B_KS  514
#define AHI   0
#define ALO   (2 * A_KS)            // 2056
#define BHI   (4 * A_KS)            // 4112
#define BLO   (BHI + 2 * B_KS)      // 5140
#define SMEMF (BLO + 2 * B_KS)      // 6168 floats = 24.7 KB

__device__ __forceinline__ float f2tf32f(float x)
{
    unsigned u;
    asm("cvt.rna.tf32.f32 %0, %1;" : "=r"(u) : "f"(x));
    return __uint_as_float(u);
}

__device__ __forceinline__ void mma_tf32(float* d, const uint4& a, const uint2& b)
{
    asm volatile(
        "mma.sync.aligned.m16n8k8.row.col.f32.tf32.tf32.f32 "
        "{%0,%1,%2,%3}, {%4,%5,%6,%7}, {%8,%9}, {%0,%1,%2,%3};\n"
        : "+f"(d[0]), "+f"(d[1]), "+f"(d[2]), "+f"(d[3])
        : "r"(a.x), "r"(a.y), "r"(a.z), "r"(a.w), "r"(b.x), "r"(b.y));
}

__global__ __launch_bounds__(256) void k_gemm_3xtf32(
    const float* __restrict__ A,
    const float* __restrict__ W,
    const float* __restrict__ bias,
    float* __restrict__ out,
    int mode)
{
    __shared__ float smem[SMEMF];

    const int tid  = threadIdx.x;
    const int lane = tid & 31;
    const int w    = tid >> 5;
    const int wm   = w >> 1;
    const int wn   = w & 1;
    const int m0   = blockIdx.y * 128;
    const int n0   = blockIdx.x * 64;

    float4 pa[2];
    float4 pb;

    // A tile 128x16: 512 float4, 2/thread. qi: row = qi>>2, kq = qi&3 (k=kq*4)
    // B tile 16x64: 256 float4, 1/thread (tid<256). row = tid>>4 (k), nq=tid&15
#define LDG_TILES(k0)                                                          \
    {                                                                          \
        _Pragma("unroll")                                                      \
        for (int p = 0; p < 2; p++) {                                          \
            int qi = p * 256 + tid;                                            \
            int row = qi >> 2, kq = qi & 3;                                    \
            pa[p] = *(const float4*)&A[(size_t)(m0 + row) * GK + (k0) + kq*4]; \
        }                                                                      \
        {                                                                      \
            int row = tid >> 4, nq = tid & 15;                                 \
            pb = *(const float4*)&W[(size_t)((k0) + row) * EMB + n0 + nq*4];   \
        }                                                                      \
    }

#define STS_TILES()                                                            \
    {                                                                          \
        _Pragma("unroll")                                                      \
        for (int p = 0; p < 2; p++) {                                          \
            int qi = p * 256 + tid;                                            \
            int row = qi >> 2, kq = qi & 3;                                    \
            int mt = row >> 4, mm = row & 15;                                  \
            int g = mm & 7, hm = mm >> 3;                                      \
            int ks = kq >> 1, hk = kq & 1;                                     \
            int base = ks * A_KS + mt * 128 + g * 16 + (hk * 2 + hm);          \
            float v[4] = {pa[p].x, pa[p].y, pa[p].z, pa[p].w};                 \
            _Pragma("unroll")                                                  \
            for (int u = 0; u < 4; u++) {                                      \
                float hi = f2tf32f(v[u]);                                      \
                float lo = f2tf32f(v[u] - hi);                                 \
                smem[AHI + base + u * 4] = hi;                                 \
                smem[ALO + base + u * 4] = lo;                                 \
            }                                                                  \
        }                                                                      \
        {                                                                      \
            int row = tid >> 4, nq = tid & 15;                                 \
            int ks = row >> 3, kk = row & 7;                                   \
            int t = kk & 3, hk = kk >> 2;                                      \
            float v[4] = {pb.x, pb.y, pb.z, pb.w};                             \
            _Pragma("unroll")                                                  \
            for (int u = 0; u < 4; u++) {                                      \
                int n = nq * 4 + u;                                            \
                int nt = n >> 3, nn = n & 7;                                   \
                int addr = ks * B_KS + nt * 64 + (nn * 4 + t) * 2 + hk;        \
                float hi = f2tf32f(v[u]);                                      \
                float lo = f2tf32f(v[u] - hi);                                 \
                smem[BHI + addr] = hi;                                         \
                smem[BLO + addr] = lo;                                         \
            }                                                                  \
        }                                                                      \
    }

    float acc[2][4][4];
#pragma unroll
    for (int i = 0; i < 2; i++)
#pragma unroll
        for (int j = 0; j < 4; j++)
#pragma unroll
            for (int r = 0; r < 4; r++) acc[i][j][r] = 0.0f;

    LDG_TILES(0);
    STS_TILES();
    __syncthreads();

    for (int it = 0; it < 32; ++it) {
        if (it < 31) LDG_TILES((it + 1) * 16);

#pragma unroll
        for (int ks = 0; ks < 2; ks++) {
            uint4 ah[2], al[2];
            uint2 bh[4], bl[4];
#pragma unroll
            for (int i = 0; i < 2; i++) {
                int off = ks * A_KS + (wm * 2 + i) * 128 + lane * 4;
                ah[i] = *(const uint4*)&smem[AHI + off];
                al[i] = *(const uint4*)&smem[ALO + off];
            }
#pragma unroll
            for (int j = 0; j < 4; j++) {
                int off = ks * B_KS + (wn * 4 + j) * 64 + lane * 2;
                bh[j] = *(const uint2*)&smem[BHI + off];
                bl[j] = *(const uint2*)&smem[BLO + off];
            }
#pragma unroll
            for (int i = 0; i < 2; i++)
#pragma unroll
                for (int j = 0; j < 4; j++) {
                    mma_tf32(acc[i][j], ah[i], bl[j]);   // hi * lo
                    mma_tf32(acc[i][j], al[i], bh[j]);   // lo * hi
                    mma_tf32(acc[i][j], ah[i], bh[j]);   // hi * hi
                }
        }
        __syncthreads();
        if (it < 31) {
            STS_TILES();
            __syncthreads();
        }
    }

    // ---- epilogue ----
    const int g = lane >> 2;
    const int t = lane & 3;
#pragma unroll
    for (int i = 0; i < 2; i++) {
#pragma unroll
        for (int j = 0; j < 4; j++) {
#pragma unroll
            for (int r = 0; r < 4; r++) {
                int m = m0 + wm * 32 + i * 16 + g + (r >> 1) * 8;
                int n = n0 + wn * 32 + j * 8 + 2 * t + (r & 1);
                float v = acc[i][j][r] + bias[n];
                int b = m >> 10;
                int s = m & 1023;
                if (mode == 0) {
                    int h = n >> 6, d = n & 63;
                    out[((size_t)((b * NH + h) * SEQ + s)) * HD + d] = v;
                } else {
                    out[((size_t)(b * EMB + n)) * SEQ + s] = v;
                }
            }
        }
    }
}
#undef LDG_TILES
#undef STS_TILES

// ---------------------------------------------------------------------------
// Kernel 3: flash attention (fp32, unchanged — R4 target).
// ---------------------------------------------------------------------------
__global__ void k_flash(const float* __restrict__ Q,
                        const float* __restrict__ K,
                        const float* __restrict__ V,
                        float* __restrict__ O)
{
    __shared__ __align__(16) float Qs[64][64];
    __shared__ __align__(16) float Ks[32][68];
    __shared__ __align__(16) float Vs[32][64];

    const int bh = blockIdx.y;
    const int q0 = blockIdx.x * 64;
    const size_t base = (size_t)bh * SEQ * HD;
    const float* Qb = Q + base;
    const float* Kb = K + base;
    const float* Vb = V + base;

    const int tid  = threadIdx.x;
    const int warp = tid >> 5;
    const int lane = tid & 31;
    const int r0   = warp * 8;

    for (int i = tid; i < 64 * 64; i += 256) {
        Qs[i >> 6][i & 63] = Qb[(size_t)(q0 + (i >> 6)) * HD + (i & 63)];
    }

    float m_run[8], l_run[8], o0[8], o1[8];
#pragma unroll
    for (int r = 0; r < 8; r++) {
        m_run[r] = -1e30f; l_run[r] = 0.0f; o0[r] = 0.0f; o1[r] = 0.0f;
    }

    for (int kt = 0; kt < SEQ; kt += 32) {
        __syncthreads();
        for (int i = tid; i < 32 * 64; i += 256) {
            int rr = i >> 6, cc = i & 63;
            Ks[rr][cc] = Kb[(size_t)(kt + rr) * HD + cc];
            Vs[rr][cc] = Vb[(size_t)(kt + rr) * HD + cc];
        }
        __syncthreads();

        float sacc[8];
#pragma unroll
        for (int r = 0; r < 8; r++) sacc[r] = 0.0f;
#pragma unroll
        for (int d4 = 0; d4 < 16; d4++) {
            float4 kv = *reinterpret_cast<const float4*>(&Ks[lane][d4 * 4]);
#pragma unroll
            for (int r = 0; r < 8; r++) {
                float4 qv = *reinterpret_cast<const float4*>(&Qs[r0 + r][d4 * 4]);
                sacc[r] += qv.x * kv.x + qv.y * kv.y + qv.z * kv.z + qv.w * kv.w;
            }
        }

        float p[8];
#pragma unroll
        for (int r = 0; r < 8; r++) {
            float s = sacc[r] * SCALE;
            float mt = s;
#pragma unroll
            for (int off = 16; off > 0; off >>= 1)
                mt = fmaxf(mt, __shfl_xor_sync(FULLMASK, mt, off));
            float m_new = fmaxf(m_run[r], mt);
            float alpha = __expf(m_run[r] - m_new);
            float pv    = __expf(s - m_new);
            float ls = pv;
#pragma unroll
            for (int off = 16; off > 0; off >>= 1)
                ls += __shfl_xor_sync(FULLMASK, ls, off);
            l_run[r] = l_run[r] * alpha + ls;
            m_run[r] = m_new;
            o0[r] *= alpha;
            o1[r] *= alpha;
            p[r] = pv;
        }

#pragma unroll
        for (int c = 0; c < 32; c++) {
            float v0 = Vs[c][lane];
            float v1 = Vs[c][lane + 32];
#pragma unroll
            for (int r = 0; r < 8; r++) {
                float pc = __shfl_sync(FULLMASK, p[r], c);
                o0[r] += pc * v0;
                o1[r] += pc * v1;
            }
        }
    }

    const int b = bh >> 3, h = bh & 7;
#pragma unroll
    for (int r = 0; r < 8; r++) {
        float inv = 1.0f / l_run[r];
        int s = q0 + r0 + r;
        float* orow = O + ((size_t)(b * SEQ + s)) * EMB + h * HD;
        orow[lane]      = o0[r] * inv;
        orow[lane + 32] = o1[r] * inv;
    }
}

// ---------------------------------------------------------------------------
extern "C" void kernel_launch(void* const* d_in, const int* in_sizes, int n_in,
                              void* d_out, int out_size)
{
    const float* x     = (const float*)d_in[0];
    const float* pos_w = (const float*)d_in[1];
    const float* pos_b = (const float*)d_in[2];
    const float* wq    = (const float*)d_in[3];
    const float* bq    = (const float*)d_in[4];
    const float* wk    = (const float*)d_in[5];
    const float* bk    = (const float*)d_in[6];
    const float* wv    = (const float*)d_in[7];
    const float* bv    = (const float*)d_in[8];
    const float* wo    = (const float*)d_in[9];
    const float* bo    = (const float*)d_in[10];
    float* out = (float*)d_out;

    void* scratch_ptr = nullptr;
    cudaGetSymbolAddress(&scratch_ptr, g_scratch);
    float* g_xt  = (float*)scratch_ptr;
    float* g_q   = g_xt  + (size_t)MTOT * EMB;
    float* g_k   = g_q   + (size_t)MTOT * EMB;
    float* g_v   = g_k   + (size_t)MTOT * EMB;
    float* g_att = g_v   + (size_t)MTOT * EMB;

    {
        dim3 grid(EMB / 32, SEQ / 32, BATCH);
        dim3 block(32, 8);
        k_transpose_pe<<<grid, block>>>(x, pos_w, pos_b, g_xt);
    }
    {
        dim3 grid(EMB / 64, MTOT / 128);
        k_gemm_3xtf32<<<grid, 256>>>(g_xt, wq, bq, g_q, 0);
        k_gemm_3xtf32<<<grid, 256>>>(g_xt, wk, bk, g_k, 0);
        k_gemm_3xtf32<<<grid, 256>>>(g_xt, wv, bv, g_v, 0);
    }
    {
        dim3 grid(SEQ / 64, BATCH * NH);
        k_flash<<<grid, 256>>>(g_q, g_k, g_v, g_att);
    }
    {
        dim3 grid(EMB / 64, MTOT / 128);
        k_gemm_3xtf32<<<grid, 256>>>(g_att, wo, bo, out, 1);
    }
}

// round 5
// speedup vs baseline: 1.0770x; 1.0770x over previous
#include <cuda_runtime.h>
#include <cstdint>

// ---------------------------------------------------------------------------
// SelfAttentionWithPE: B=8, E=512, H=W=32 (S=1024), heads=8, head_dim=64, fp32
//
// All heavy math on tensor cores via 3xTF32 (hi/lo split) mma.sync.m16n8k8.
// hi/lo splits of all GEMM/attention operands are precomputed in global
// scratch so hot loops do zero conversion work.
//
//   k_transpose_pe : x -> xt_hi/xt_lo  (+positional encoding)
//   k_split        : weights -> w_hi/w_lo
//   k_gemm         : 3xTF32, double-buffered; writes q/k/v as hi/lo splits
//                    (softmax scale folded into Q via oscale=0.125)
//   k_flash_mma    : mma-based flash attention (QK^T and PV both 3xTF32),
//                    writes att_hi/att_lo
//   k_gemm mode1   : att @ wo + bo -> out[b,E,32,32]  (fp32 out)
// ---------------------------------------------------------------------------

#define BATCH 8
#define EMB   512
#define SEQ   1024
#define NH    8
#define HD    64
#define MTOT  (BATCH * SEQ)
#define FULLMASK 0xffffffffu

// scratch: xt(2) + qkv(6) + att(2) planes of MTOT*EMB, + 8 weight planes
#define PLANE   ((size_t)MTOT * EMB)        // 4,194,304
#define WPLANE  ((size_t)EMB * EMB)         // 262,144
__device__ float g_scratch[10 * 4194304 + 8 * 262144];

__device__ __forceinline__ float f2tf32f(float x)
{
    unsigned u;
    asm("cvt.rna.tf32.f32 %0, %1;" : "=r"(u) : "f"(x));
    return __uint_as_float(u);
}
__device__ __forceinline__ unsigned f2tf32u(float x)
{
    unsigned u;
    asm("cvt.rna.tf32.f32 %0, %1;" : "=r"(u) : "f"(x));
    return u;
}

__device__ __forceinline__ void mma_tf32(float* d, const uint4& a, const uint2& b)
{
    asm volatile(
        "mma.sync.aligned.m16n8k8.row.col.f32.tf32.tf32.f32 "
        "{%0,%1,%2,%3}, {%4,%5,%6,%7}, {%8,%9}, {%0,%1,%2,%3};\n"
        : "+f"(d[0]), "+f"(d[1]), "+f"(d[2]), "+f"(d[3])
        : "r"(a.x), "r"(a.y), "r"(a.z), "r"(a.w), "r"(b.x), "r"(b.y));
}

// ---------------------------------------------------------------------------
// Kernel: transpose + positional encoding -> hi/lo planes
// ---------------------------------------------------------------------------
__global__ void k_transpose_pe(const float* __restrict__ x,
                               const float* __restrict__ pos_w,
                               const float* __restrict__ pos_b,
                               float* __restrict__ xt_hi,
                               float* __restrict__ xt_lo)
{
    __shared__ float tile[32][33];
    const int e0 = blockIdx.x * 32;
    const int s0 = blockIdx.y * 32;
    const int b  = blockIdx.z;
    const int tx = threadIdx.x;
    const int ty = threadIdx.y;

#pragma unroll
    for (int i = 0; i < 4; i++) {
        int el = ty + i * 8;
        tile[el][tx] = x[((size_t)(b * EMB + e0 + el)) * SEQ + s0 + tx];
    }
    __syncthreads();

    const int e = e0 + tx;
    const float pw0 = pos_w[e];
    const float pw1 = pos_w[EMB + e];
    const float pb  = pos_b[e];
#pragma unroll
    for (int i = 0; i < 4; i++) {
        int sl = ty + i * 8;
        int s  = s0 + sl;
        float row = (float)(s >> 5);
        float col = (float)(s & 31);
        float v = tile[tx][sl] + row * pw0 + col * pw1 + pb;
        size_t idx = ((size_t)(b * SEQ + s)) * EMB + e;
        float hi = f2tf32f(v);
        xt_hi[idx] = hi;
        xt_lo[idx] = f2tf32f(v - hi);
    }
}

// ---------------------------------------------------------------------------
// Kernel: split weights into hi/lo
// ---------------------------------------------------------------------------
__global__ void k_split(const float* __restrict__ in,
                        float* __restrict__ out_hi,
                        float* __restrict__ out_lo, int n)
{
    int i = blockIdx.x * blockDim.x + threadIdx.x;
    if (i < n) {
        float v = in[i];
        float hi = f2tf32f(v);
        out_hi[i] = hi;
        out_lo[i] = f2tf32f(v - hi);
    }
}

// ---------------------------------------------------------------------------
// Kernel: 3xTF32 GEMM, BM=128 BN=64 BK=16, double-buffered smem,
// inputs pre-split. Fragment-permuted smem (validated layout from R3):
//   A plane: ks*1028 + mt*128 + g*16 + hk*2 + hm + u*4    (2 ks per stage)
//   B plane: ks*514  + nt*64  + (nn*4+t)*2 + hk
// Stage layout: [A_hi 2056][A_lo 2056][B_hi 1028][B_lo 1028] = 6168 floats.
// ---------------------------------------------------------------------------
#define G_STAGE 6168
#define G_SMEMB (2 * G_STAGE * 4)   // 49344 bytes

__global__ __launch_bounds__(256) void k_gemm(
    const float* __restrict__ A_hi, const float* __restrict__ A_lo,
    const float* __restrict__ W_hi, const float* __restrict__ W_lo,
    const float* __restrict__ bias,
    float* __restrict__ out_hi, float* __restrict__ out_lo,
    int mode, float oscale)
{
    extern __shared__ float sg[];

    const int tid  = threadIdx.x;
    const int lane = tid & 31;
    const int w    = tid >> 5;
    const int wm   = w >> 1;
    const int wn   = w & 1;
    const int m0   = blockIdx.y * 128;
    const int n0   = blockIdx.x * 64;

    float4 pah[2], pal[2], pbh, pbl;

#define G_LDG(k0)                                                              \
    {                                                                          \
        _Pragma("unroll")                                                      \
        for (int p = 0; p < 2; p++) {                                          \
            int qi = p * 256 + tid;                                            \
            int row = qi >> 2, kq = qi & 3;                                    \
            size_t off = (size_t)(m0 + row) * EMB + (k0) + kq * 4;             \
            pah[p] = *(const float4*)&A_hi[off];                               \
            pal[p] = *(const float4*)&A_lo[off];                               \
        }                                                                      \
        {                                                                      \
            int row = tid >> 4, nq = tid & 15;                                 \
            size_t off = (size_t)((k0) + row) * EMB + n0 + nq * 4;             \
            pbh = *(const float4*)&W_hi[off];                                  \
            pbl = *(const float4*)&W_lo[off];                                  \
        }                                                                      \
    }

#define G_STS(st)                                                              \
    {                                                                          \
        float* S = sg + (st) * G_STAGE;                                        \
        _Pragma("unroll")                                                      \
        for (int p = 0; p < 2; p++) {                                          \
            int qi = p * 256 + tid;                                            \
            int row = qi >> 2, kq = qi & 3;                                    \
            int mt = row >> 4, mm = row & 15;                                  \
            int g = mm & 7, hm = mm >> 3;                                      \
            int ks = kq >> 1, hk = kq & 1;                                     \
            int base = ks * 1028 + mt * 128 + g * 16 + hk * 2 + hm;            \
            float vh[4] = {pah[p].x, pah[p].y, pah[p].z, pah[p].w};            \
            float vl[4] = {pal[p].x, pal[p].y, pal[p].z, pal[p].w};            \
            _Pragma("unroll")                                                  \
            for (int u = 0; u < 4; u++) {                                      \
                S[base + u * 4]        = vh[u];                                \
                S[2056 + base + u * 4] = vl[u];                                \
            }                                                                  \
        }                                                                      \
        {                                                                      \
            int row = tid >> 4, nq = tid & 15;                                 \
            int ks = row >> 3, kk = row & 7;                                   \
            int t = kk & 3, hk = kk >> 2;                                      \
            float vh[4] = {pbh.x, pbh.y, pbh.z, pbh.w};                        \
            float vl[4] = {pbl.x, pbl.y, pbl.z, pbl.w};                        \
            _Pragma("unroll")                                                  \
            for (int u = 0; u < 4; u++) {                                      \
                int n = nq * 4 + u;                                            \
                int nt = n >> 3, nn = n & 7;                                   \
                int addr = 4112 + ks * 514 + nt * 64 + (nn * 4 + t) * 2 + hk;  \
                S[addr]        = vh[u];                                        \
                S[1028 + addr] = vl[u];                                        \
            }                                                                  \
        }                                                                      \
    }

    float acc[2][4][4];
#pragma unroll
    for (int i = 0; i < 2; i++)
#pragma unroll
        for (int j = 0; j < 4; j++)
#pragma unroll
            for (int r = 0; r < 4; r++) acc[i][j][r] = 0.0f;

    G_LDG(0);
    G_STS(0);
    __syncthreads();

    for (int it = 0; it < 32; ++it) {
        if (it < 31) G_LDG((it + 1) * 16);

        const float* S = sg + (it & 1) * G_STAGE;
#pragma unroll
        for (int ks = 0; ks < 2; ks++) {
            uint4 ah[2], al[2];
            uint2 bh[4], bl[4];
#pragma unroll
            for (int i = 0; i < 2; i++) {
                int off = ks * 1028 + (wm * 2 + i) * 128 + lane * 4;
                ah[i] = *(const uint4*)&S[off];
                al[i] = *(const uint4*)&S[2056 + off];
            }
#pragma unroll
            for (int j = 0; j < 4; j++) {
                int off = 4112 + ks * 514 + (wn * 4 + j) * 64 + lane * 2;
                bh[j] = *(const uint2*)&S[off];
                bl[j] = *(const uint2*)&S[1028 + off];
            }
#pragma unroll
            for (int i = 0; i < 2; i++)
#pragma unroll
                for (int j = 0; j < 4; j++) {
                    mma_tf32(acc[i][j], ah[i], bl[j]);
                    mma_tf32(acc[i][j], al[i], bh[j]);
                    mma_tf32(acc[i][j], ah[i], bh[j]);
                }
        }
        if (it < 31) {
            G_STS((it + 1) & 1);
            __syncthreads();
        }
    }

    const int g = lane >> 2;
    const int t = lane & 3;
#pragma unroll
    for (int i = 0; i < 2; i++) {
#pragma unroll
        for (int j = 0; j < 4; j++) {
#pragma unroll
            for (int r = 0; r < 4; r++) {
                int m = m0 + wm * 32 + i * 16 + g + (r >> 1) * 8;
                int n = n0 + wn * 32 + j * 8 + 2 * t + (r & 1);
                float v = (acc[i][j][r] + bias[n]) * oscale;
                int b = m >> 10;
                int s = m & 1023;
                if (mode == 0) {
                    int h = n >> 6, d = n & 63;
                    size_t idx = ((size_t)((b * NH + h) * SEQ + s)) * HD + d;
                    float hi = f2tf32f(v);
                    out_hi[idx] = hi;
                    out_lo[idx] = f2tf32f(v - hi);
                } else {
                    out_hi[((size_t)(b * EMB + n)) * SEQ + s] = v;
                }
            }
        }
    }
}
#undef G_LDG
#undef G_STS

// ---------------------------------------------------------------------------
// Kernel: mma flash attention. BM=64 q rows/block, 32-key tiles, 256 threads.
// QK^T warps: wm=w&3 (m16 tile), wn=w>>2 (16-key half: n8 tiles {2wn,2wn+1}).
// PV warps:   mt=w&3 (m16 tile), nh=w>>2 (d half: n8 tiles nh*4..nh*4+3).
// Q/K/V pre-split hi/lo in gmem; Q scattered to A-frag smem once;
// K/V scattered to B-frag smem per tile; P via smem round-trip.
// Deferred-stats online softmax (4 barriers/tile).
// smem floats: QH 0(4128) QL 4128 KH 8256(2064) KL 10320 VH 12384(2056)
//              VL 14440 PS 16496(64*34) MRUN 18672 LRUN 18736
//              SMAX 18800(128) SSUM 18928(128)  total 19056
// ---------------------------------------------------------------------------
#define F_QH   0
#define F_QL   4128
#define F_KH   8256
#define F_KL   10320
#define F_VH   12384
#define F_VL   14440
#define F_PS   16496
#define F_MRUN 18672
#define F_LRUN 18736
#define F_SMAX 18800
#define F_SSUM 18928
#define F_SMEMB (19056 * 4)

__global__ __launch_bounds__(256) void k_flash_mma(
    const float* __restrict__ q_hi, const float* __restrict__ q_lo,
    const float* __restrict__ k_hi, const float* __restrict__ k_lo,
    const float* __restrict__ v_hi, const float* __restrict__ v_lo,
    float* __restrict__ att_hi, float* __restrict__ att_lo)
{
    extern __shared__ float sm[];

    const int tid  = threadIdx.x;
    const int lane = tid & 31;
    const int w    = tid >> 5;
    const int bh   = blockIdx.y;
    const int q0   = blockIdx.x * 64;
    const size_t kvbase = (size_t)bh * SEQ * HD;

    if (tid < 64) {
        sm[F_MRUN + tid] = -1e30f;
        sm[F_LRUN + tid] = 0.0f;
    }

    // ---- load + scatter Q (A-fragment layout, pitch 516) ----
    {
        int m  = tid >> 2;
        int d0 = (tid & 3) * 16;
        int mt = m >> 4, mm = m & 15;
        int g = mm & 7, hm = mm >> 3;
        size_t grow = kvbase + (size_t)(q0 + m) * HD;
#pragma unroll
        for (int u4 = 0; u4 < 4; u4++) {
            int dd = d0 + u4 * 4;
            float4 vh = *(const float4*)&q_hi[grow + dd];
            float4 vl = *(const float4*)&q_lo[grow + dd];
            float eh[4] = {vh.x, vh.y, vh.z, vh.w};
            float el[4] = {vl.x, vl.y, vl.z, vl.w};
#pragma unroll
            for (int e = 0; e < 4; e++) {
                int d = dd + e;
                int ks = d >> 3, hk = (d >> 2) & 1, u = d & 3;
                int addr = ks * 516 + mt * 128 + g * 16 + hk * 2 + hm + u * 4;
                sm[F_QH + addr] = eh[e];
                sm[F_QL + addr] = el[e];
            }
        }
    }

    const int wm = w & 3, wn = w >> 2;      // QK roles
    const int mt_pv = w & 3, nh = w >> 2;   // PV roles
    const int t = lane & 3;
    const int qrow = lane >> 2;

    const int rA = wm * 16 + qrow, rB = rA + 8;         // QK rows
    const int prA = mt_pv * 16 + qrow, prB = prA + 8;   // PV rows

    float o[4][4];
#pragma unroll
    for (int j = 0; j < 4; j++)
#pragma unroll
        for (int r = 0; r < 4; r++) o[j][r] = 0.0f;

    for (int kt = 0; kt < SEQ; kt += 32) {
        __syncthreads();    // S0: prior PV/LDS done; also covers initial Q/stat init

        // deferred stats update for previous tile (owner lanes)
        if (kt > 0 && wn == 0 && t == 0) {
#pragma unroll
            for (int rr = 0; rr < 2; rr++) {
                int row = rA + rr * 8;
                float mold = sm[F_MRUN + row];
                float mt_  = fmaxf(sm[F_SMAX + row], sm[F_SMAX + 64 + row]);
                float mnew = fmaxf(mold, mt_);
                sm[F_LRUN + row] = sm[F_LRUN + row] * __expf(mold - mnew)
                                 + sm[F_SSUM + row] + sm[F_SSUM + 64 + row];
                sm[F_MRUN + row] = mnew;
            }
        }

        // ---- load + scatter K, V tiles (B-fragment layouts) ----
        {
            int kidx = tid >> 3;
            int d0   = (tid & 7) * 8;
            size_t krow = kvbase + (size_t)(kt + kidx) * HD;
            int knt = kidx >> 3, knn = kidx & 7;
            int vks = kidx >> 3;
            int vt = kidx & 3, vhk = (kidx >> 2) & 1;
#pragma unroll
            for (int u4 = 0; u4 < 2; u4++) {
                int dd = d0 + u4 * 4;
                float4 kh4 = *(const float4*)&k_hi[krow + dd];
                float4 kl4 = *(const float4*)&k_lo[krow + dd];
                float4 vh4 = *(const float4*)&v_hi[krow + dd];
                float4 vl4 = *(const float4*)&v_lo[krow + dd];
                float keh[4] = {kh4.x, kh4.y, kh4.z, kh4.w};
                float kel[4] = {kl4.x, kl4.y, kl4.z, kl4.w};
                float veh[4] = {vh4.x, vh4.y, vh4.z, vh4.w};
                float vel[4] = {vl4.x, vl4.y, vl4.z, vl4.w};
#pragma unroll
                for (int e = 0; e < 4; e++) {
                    int d = dd + e;
                    // K: B[k=d][n=kidx]
                    int kks = d >> 3, kt_ = d & 3, khk = (d >> 2) & 1;
                    int kaddr = kks * 258 + knt * 64 + (knn * 4 + kt_) * 2 + khk;
                    sm[F_KH + kaddr] = keh[e];
                    sm[F_KL + kaddr] = kel[e];
                    // V: B[k=kidx][n=d]
                    int vnt = d >> 3, vnn = d & 7;
                    int vaddr = vks * 514 + vnt * 64 + (vnn * 4 + vt) * 2 + vhk;
                    sm[F_VH + vaddr] = veh[e];
                    sm[F_VL + vaddr] = vel[e];
                }
            }
        }
        __syncthreads();    // S1: K/V + stats visible

        // ---- QK^T mma (3xTF32) ----
        float sacc[2][4];
#pragma unroll
        for (int j = 0; j < 2; j++)
#pragma unroll
            for (int r = 0; r < 4; r++) sacc[j][r] = 0.0f;

#pragma unroll
        for (int ks = 0; ks < 8; ks++) {
            int aoff = ks * 516 + wm * 128 + lane * 4;
            uint4 ah = *(const uint4*)&sm[F_QH + aoff];
            uint4 al = *(const uint4*)&sm[F_QL + aoff];
#pragma unroll
            for (int j = 0; j < 2; j++) {
                int jj = wn * 2 + j;
                int boff = ks * 258 + jj * 64 + lane * 2;
                uint2 bh = *(const uint2*)&sm[F_KH + boff];
                uint2 bl = *(const uint2*)&sm[F_KL + boff];
                mma_tf32(sacc[j], ah, bl);
                mma_tf32(sacc[j], al, bh);
                mma_tf32(sacc[j], ah, bh);
            }
        }

        // ---- local row max -> smem ----
        float mA = fmaxf(fmaxf(sacc[0][0], sacc[0][1]), fmaxf(sacc[1][0], sacc[1][1]));
        float mB = fmaxf(fmaxf(sacc[0][2], sacc[0][3]), fmaxf(sacc[1][2], sacc[1][3]));
        mA = fmaxf(mA, __shfl_xor_sync(FULLMASK, mA, 1));
        mA = fmaxf(mA, __shfl_xor_sync(FULLMASK, mA, 2));
        mB = fmaxf(mB, __shfl_xor_sync(FULLMASK, mB, 1));
        mB = fmaxf(mB, __shfl_xor_sync(FULLMASK, mB, 2));
        if (t == 0) {
            sm[F_SMAX + wn * 64 + rA] = mA;
            sm[F_SMAX + wn * 64 + rB] = mB;
        }
        __syncthreads();    // S2: SMAX visible

        float mnewA = fmaxf(sm[F_MRUN + rA],
                            fmaxf(sm[F_SMAX + rA], sm[F_SMAX + 64 + rA]));
        float mnewB = fmaxf(sm[F_MRUN + rB],
                            fmaxf(sm[F_SMAX + rB], sm[F_SMAX + 64 + rB]));

        float p[2][4];
#pragma unroll
        for (int j = 0; j < 2; j++) {
            p[j][0] = __expf(sacc[j][0] - mnewA);
            p[j][1] = __expf(sacc[j][1] - mnewA);
            p[j][2] = __expf(sacc[j][2] - mnewB);
            p[j][3] = __expf(sacc[j][3] - mnewB);
        }
        float sA = p[0][0] + p[0][1] + p[1][0] + p[1][1];
        float sB = p[0][2] + p[0][3] + p[1][2] + p[1][3];
        sA += __shfl_xor_sync(FULLMASK, sA, 1);
        sA += __shfl_xor_sync(FULLMASK, sA, 2);
        sB += __shfl_xor_sync(FULLMASK, sB, 1);
        sB += __shfl_xor_sync(FULLMASK, sB, 2);
        if (t == 0) {
            sm[F_SSUM + wn * 64 + rA] = sA;
            sm[F_SSUM + wn * 64 + rB] = sB;
        }
        // write P (C-frag -> plain [row][col], pitch 34)
#pragma unroll
        for (int j = 0; j < 2; j++) {
            int c = wn * 16 + j * 8 + 2 * t;
            *(float2*)&sm[F_PS + rA * 34 + c] = make_float2(p[j][0], p[j][1]);
            *(float2*)&sm[F_PS + rB * 34 + c] = make_float2(p[j][2], p[j][3]);
        }
        __syncthreads();    // S3: P + SSUM visible

        // ---- PV (3xTF32), per-lane alpha from pre-tile stats ----
        float moldA = sm[F_MRUN + prA], moldB = sm[F_MRUN + prB];
        float mnA = fmaxf(moldA, fmaxf(sm[F_SMAX + prA], sm[F_SMAX + 64 + prA]));
        float mnB = fmaxf(moldB, fmaxf(sm[F_SMAX + prB], sm[F_SMAX + 64 + prB]));
        float alA = __expf(moldA - mnA);
        float alB = __expf(moldB - mnB);
#pragma unroll
        for (int j = 0; j < 4; j++) {
            o[j][0] *= alA; o[j][1] *= alA;
            o[j][2] *= alB; o[j][3] *= alB;
        }
#pragma unroll
        for (int ks = 0; ks < 4; ks++) {
            float p0 = sm[F_PS + prA * 34 + ks * 8 + t];
            float p1 = sm[F_PS + prB * 34 + ks * 8 + t];
            float p2 = sm[F_PS + prA * 34 + ks * 8 + t + 4];
            float p3 = sm[F_PS + prB * 34 + ks * 8 + t + 4];
            uint4 ah, al;
            ah.x = f2tf32u(p0); al.x = f2tf32u(p0 - __uint_as_float(ah.x));
            ah.y = f2tf32u(p1); al.y = f2tf32u(p1 - __uint_as_float(ah.y));
            ah.z = f2tf32u(p2); al.z = f2tf32u(p2 - __uint_as_float(ah.z));
            ah.w = f2tf32u(p3); al.w = f2tf32u(p3 - __uint_as_float(ah.w));
#pragma unroll
            for (int jl = 0; jl < 4; jl++) {
                int j = nh * 4 + jl;
                int boff = ks * 514 + j * 64 + lane * 2;
                uint2 bh = *(const uint2*)&sm[F_VH + boff];
                uint2 bl = *(const uint2*)&sm[F_VL + boff];
                mma_tf32(o[jl], ah, bl);
                mma_tf32(o[jl], al, bh);
                mma_tf32(o[jl], ah, bh);
            }
        }
    }

    // final deferred stats update
    __syncthreads();
    if (wn == 0 && t == 0) {
#pragma unroll
        for (int rr = 0; rr < 2; rr++) {
            int row = rA + rr * 8;
            float mold = sm[F_MRUN + row];
            float mt_  = fmaxf(sm[F_SMAX + row], sm[F_SMAX + 64 + row]);
            float mnew = fmaxf(mold, mt_);
            sm[F_LRUN + row] = sm[F_LRUN + row] * __expf(mold - mnew)
                             + sm[F_SSUM + row] + sm[F_SSUM + 64 + row];
        }
    }
    __syncthreads();

    // ---- epilogue: o /= l, split hi/lo, write att[b*s, E] ----
    const float invA = 1.0f / sm[F_LRUN + prA];
    const float invB = 1.0f / sm[F_LRUN + prB];
    const int b = bh >> 3, h = bh & 7;
    const size_t rowA = ((size_t)(b * SEQ + q0 + prA)) * EMB + h * HD;
    const size_t rowB = ((size_t)(b * SEQ + q0 + prB)) * EMB + h * HD;
#pragma unroll
    for (int jl = 0; jl < 4; jl++) {
        int e = nh * 32 + jl * 8 + 2 * t;
        float v0 = o[jl][0] * invA, v1 = o[jl][1] * invA;
        float v2 = o[jl][2] * invB, v3 = o[jl][3] * invB;
        float h0 = f2tf32f(v0), h1 = f2tf32f(v1);
        float h2 = f2tf32f(v2), h3 = f2tf32f(v3);
        *(float2*)&att_hi[rowA + e] = make_float2(h0, h1);
        *(float2*)&att_lo[rowA + e] = make_float2(f2tf32f(v0 - h0), f2tf32f(v1 - h1));
        *(float2*)&att_hi[rowB + e] = make_float2(h2, h3);
        *(float2*)&att_lo[rowB + e] = make_float2(f2tf32f(v2 - h2), f2tf32f(v3 - h3));
    }
}

// ---------------------------------------------------------------------------
extern "C" void kernel_launch(void* const* d_in, const int* in_sizes, int n_in,
                              void* d_out, int out_size)
{
    const float* x     = (const float*)d_in[0];
    const float* pos_w = (const float*)d_in[1];
    const float* pos_b = (const float*)d_in[2];
    const float* wq    = (const float*)d_in[3];
    const float* bq    = (const float*)d_in[4];
    const float* wk    = (const float*)d_in[5];
    const float* bk    = (const float*)d_in[6];
    const float* wv    = (const float*)d_in[7];
    const float* bv    = (const float*)d_in[8];
    const float* wo    = (const float*)d_in[9];
    const float* bo    = (const float*)d_in[10];
    float* out = (float*)d_out;

    void* sp = nullptr;
    cudaGetSymbolAddress(&sp, g_scratch);
    float* base   = (float*)sp;
    float* xt_hi  = base;
    float* xt_lo  = xt_hi + PLANE;
    float* q_hi   = xt_lo + PLANE;
    float* q_lo   = q_hi  + PLANE;
    float* k_hi   = q_lo  + PLANE;
    float* k_lo   = k_hi  + PLANE;
    float* v_hi   = k_lo  + PLANE;
    float* v_lo   = v_hi  + PLANE;
    float* att_hi = v_lo  + PLANE;
    float* att_lo = att_hi + PLANE;
    float* wsp    = att_lo + PLANE;
    float* wq_hi = wsp;              float* wq_lo = wq_hi + WPLANE;
    float* wk_hi = wq_lo + WPLANE;   float* wk_lo = wk_hi + WPLANE;
    float* wv_hi = wk_lo + WPLANE;   float* wv_lo = wv_hi + WPLANE;
    float* wo_hi = wv_lo + WPLANE;   float* wo_lo = wo_hi + WPLANE;

    cudaFuncSetAttribute(k_gemm, cudaFuncAttributeMaxDynamicSharedMemorySize, G_SMEMB);
    cudaFuncSetAttribute(k_flash_mma, cudaFuncAttributeMaxDynamicSharedMemorySize, F_SMEMB);

    // 1) transpose + PE -> xt hi/lo
    {
        dim3 grid(EMB / 32, SEQ / 32, BATCH);
        dim3 block(32, 8);
        k_transpose_pe<<<grid, block>>>(x, pos_w, pos_b, xt_hi, xt_lo);
    }
    // 2) weight splits
    {
        int n = EMB * EMB;
        int nb = (n + 255) / 256;
        k_split<<<nb, 256>>>(wq, wq_hi, wq_lo, n);
        k_split<<<nb, 256>>>(wk, wk_hi, wk_lo, n);
        k_split<<<nb, 256>>>(wv, wv_hi, wv_lo, n);
        k_split<<<nb, 256>>>(wo, wo_hi, wo_lo, n);
    }
    // 3) QKV projections (Q pre-scaled by 1/sqrt(d)=0.125)
    {
        dim3 grid(EMB / 64, MTOT / 128);
        k_gemm<<<grid, 256, G_SMEMB>>>(xt_hi, xt_lo, wq_hi, wq_lo, bq, q_hi, q_lo, 0, 0.125f);
        k_gemm<<<grid, 256, G_SMEMB>>>(xt_hi, xt_lo, wk_hi, wk_lo, bk, k_hi, k_lo, 0, 1.0f);
        k_gemm<<<grid, 256, G_SMEMB>>>(xt_hi, xt_lo, wv_hi, wv_lo, bv, v_hi, v_lo, 0, 1.0f);
    }
    // 4) flash attention (mma)
    {
        dim3 grid(SEQ / 64, BATCH * NH);
        k_flash_mma<<<grid, 256, F_SMEMB>>>(q_hi, q_lo, k_hi, k_lo, v_hi, v_lo,
                                            att_hi, att_lo);
    }
    // 5) output projection -> [b,c,h,w]
    {
        dim3 grid(EMB / 64, MTOT / 128);
        k_gemm<<<grid, 256, G_SMEMB>>>(att_hi, att_lo, wo_hi, wo_lo, bo, out, out, 1, 1.0f);
    }
}

// round 6
// speedup vs baseline: 1.0898x; 1.0119x over previous
#include <cuda_runtime.h>
#include <cstdint>

// ---------------------------------------------------------------------------
// SelfAttentionWithPE: B=8, E=512, H=W=32 (S=1024), heads=8, head_dim=64, fp32
// All heavy math on tensor cores via 3xTF32 (hi/lo split) mma.sync.m16n8k8.
// ---------------------------------------------------------------------------

#define BATCH 8
#define EMB   512
#define SEQ   1024
#define NH    8
#define HD    64
#define MTOT  (BATCH * SEQ)
#define FULLMASK 0xffffffffu

#define PLANE   ((size_t)MTOT * EMB)        // 4,194,304
#define WPLANE  ((size_t)EMB * EMB)         // 262,144
__device__ float g_scratch[10 * 4194304 + 8 * 262144];

__device__ __forceinline__ float f2tf32f(float x)
{
    unsigned u;
    asm("cvt.rna.tf32.f32 %0, %1;" : "=r"(u) : "f"(x));
    return __uint_as_float(u);
}
__device__ __forceinline__ unsigned f2tf32u(float x)
{
    unsigned u;
    asm("cvt.rna.tf32.f32 %0, %1;" : "=r"(u) : "f"(x));
    return u;
}

__device__ __forceinline__ void mma_tf32(float* d, const uint4& a, const uint2& b)
{
    asm volatile(
        "mma.sync.aligned.m16n8k8.row.col.f32.tf32.tf32.f32 "
        "{%0,%1,%2,%3}, {%4,%5,%6,%7}, {%8,%9}, {%0,%1,%2,%3};\n"
        : "+f"(d[0]), "+f"(d[1]), "+f"(d[2]), "+f"(d[3])
        : "r"(a.x), "r"(a.y), "r"(a.z), "r"(a.w), "r"(b.x), "r"(b.y));
}

// ---------------------------------------------------------------------------
// Kernel: transpose + positional encoding -> hi/lo planes
// ---------------------------------------------------------------------------
__global__ void k_transpose_pe(const float* __restrict__ x,
                               const float* __restrict__ pos_w,
                               const float* __restrict__ pos_b,
                               float* __restrict__ xt_hi,
                               float* __restrict__ xt_lo)
{
    __shared__ float tile[32][33];
    const int e0 = blockIdx.x * 32;
    const int s0 = blockIdx.y * 32;
    const int b  = blockIdx.z;
    const int tx = threadIdx.x;
    const int ty = threadIdx.y;

#pragma unroll
    for (int i = 0; i < 4; i++) {
        int el = ty + i * 8;
        tile[el][tx] = x[((size_t)(b * EMB + e0 + el)) * SEQ + s0 + tx];
    }
    __syncthreads();

    const int e = e0 + tx;
    const float pw0 = pos_w[e];
    const float pw1 = pos_w[EMB + e];
    const float pb  = pos_b[e];
#pragma unroll
    for (int i = 0; i < 4; i++) {
        int sl = ty + i * 8;
        int s  = s0 + sl;
        float row = (float)(s >> 5);
        float col = (float)(s & 31);
        float v = tile[tx][sl] + row * pw0 + col * pw1 + pb;
        size_t idx = ((size_t)(b * SEQ + s)) * EMB + e;
        float hi = f2tf32f(v);
        xt_hi[idx] = hi;
        xt_lo[idx] = f2tf32f(v - hi);
    }
}

// ---------------------------------------------------------------------------
// Kernel: split all 4 weight matrices into hi/lo in ONE launch.
// grid (WPLANE/256, 4)
// ---------------------------------------------------------------------------
__global__ void k_split4(const float* __restrict__ w0, const float* __restrict__ w1,
                         const float* __restrict__ w2, const float* __restrict__ w3,
                         float* __restrict__ base_hi_lo)   // 8 contiguous WPLANEs
{
    const float* src;
    switch (blockIdx.y) {
        case 0: src = w0; break;
        case 1: src = w1; break;
        case 2: src = w2; break;
        default: src = w3; break;
    }
    float* hi = base_hi_lo + (size_t)blockIdx.y * 2 * WPLANE;
    float* lo = hi + WPLANE;
    int i = blockIdx.x * 256 + threadIdx.x;
    float v = src[i];
    float h = f2tf32f(v);
    hi[i] = h;
    lo[i] = f2tf32f(v - h);
}

// ---------------------------------------------------------------------------
// Kernel: 3xTF32 GEMM, BM=128 BN=64 BK=32, double-buffered smem, one sync/iter.
// Fragment-permuted smem (layout validated in R3/R5):
//   A plane (per stage): ks*1028 + mt*128 + g*16 + hk*2 + hm + u*4  (4 ks)
//   B plane (per stage): ks*514  + nt*64  + (nn*4+t)*2 + hk         (4 ks)
// Stage: [A_hi 4112][A_lo 4112][B_hi 2056][B_lo 2056] = 12336 floats.
// ---------------------------------------------------------------------------
#define G_STAGE 12336
#define G_SMEMB (2 * G_STAGE * 4)   // 98688 bytes

__global__ __launch_bounds__(256) void k_gemm(
    const float* __restrict__ A_hi, const float* __restrict__ A_lo,
    const float* __restrict__ W_hi, const float* __restrict__ W_lo,
    const float* __restrict__ bias,
    float* __restrict__ out_hi, float* __restrict__ out_lo,
    int mode, float oscale)
{
    extern __shared__ float sg[];

    const int tid  = threadIdx.x;
    const int lane = tid & 31;
    const int w    = tid >> 5;
    const int wm   = w >> 1;
    const int wn   = w & 1;
    const int m0   = blockIdx.y * 128;
    const int n0   = blockIdx.x * 64;

    float4 pah[4], pal[4], pbh[2], pbl[2];

    // A tile 128x32: 1024 f4 -> 4/thread/plane. row=qi>>3, kq=qi&7 (k=kq*4)
    // B tile 32x64:  512 f4  -> 2/thread/plane. row=qi>>4, nq=qi&15
#define G_LDG(k0)                                                              \
    {                                                                          \
        _Pragma("unroll")                                                      \
        for (int p = 0; p < 4; p++) {                                          \
            int qi = p * 256 + tid;                                            \
            int row = qi >> 3, kq = qi & 7;                                    \
            size_t off = (size_t)(m0 + row) * EMB + (k0) + kq * 4;             \
            pah[p] = *(const float4*)&A_hi[off];                               \
            pal[p] = *(const float4*)&A_lo[off];                               \
        }                                                                      \
        _Pragma("unroll")                                                      \
        for (int p = 0; p < 2; p++) {                                          \
            int qi = p * 256 + tid;                                            \
            int row = qi >> 4, nq = qi & 15;                                   \
            size_t off = (size_t)((k0) + row) * EMB + n0 + nq * 4;             \
            pbh[p] = *(const float4*)&W_hi[off];                               \
            pbl[p] = *(const float4*)&W_lo[off];                               \
        }                                                                      \
    }

#define G_STS(st)                                                              \
    {                                                                          \
        float* S = sg + (st) * G_STAGE;                                        \
        _Pragma("unroll")                                                      \
        for (int p = 0; p < 4; p++) {                                          \
            int qi = p * 256 + tid;                                            \
            int row = qi >> 3, kq = qi & 7;                                    \
            int mt = row >> 4, mm = row & 15;                                  \
            int g = mm & 7, hm = mm >> 3;                                      \
            int ks = kq >> 1, hk = kq & 1;                                     \
            int base = ks * 1028 + mt * 128 + g * 16 + hk * 2 + hm;            \
            float vh[4] = {pah[p].x, pah[p].y, pah[p].z, pah[p].w};            \
            float vl[4] = {pal[p].x, pal[p].y, pal[p].z, pal[p].w};            \
            _Pragma("unroll")                                                  \
            for (int u = 0; u < 4; u++) {                                      \
                S[base + u * 4]        = vh[u];                                \
                S[4112 + base + u * 4] = vl[u];                                \
            }                                                                  \
        }                                                                      \
        _Pragma("unroll")                                                      \
        for (int p = 0; p < 2; p++) {                                          \
            int qi = p * 256 + tid;                                            \
            int row = qi >> 4, nq = qi & 15;                                   \
            int ks = row >> 3, kk = row & 7;                                   \
            int t = kk & 3, hk = kk >> 2;                                      \
            float vh[4] = {pbh[p].x, pbh[p].y, pbh[p].z, pbh[p].w};            \
            float vl[4] = {pbl[p].x, pbl[p].y, pbl[p].z, pbl[p].w};            \
            _Pragma("unroll")                                                  \
            for (int u = 0; u < 4; u++) {                                      \
                int n = nq * 4 + u;                                            \
                int nt = n >> 3, nn = n & 7;                                   \
                int addr = 8224 + ks * 514 + nt * 64 + (nn * 4 + t) * 2 + hk;  \
                S[addr]        = vh[u];                                        \
                S[2056 + addr] = vl[u];                                        \
            }                                                                  \
        }                                                                      \
    }

    float acc[2][4][4];
#pragma unroll
    for (int i = 0; i < 2; i++)
#pragma unroll
        for (int j = 0; j < 4; j++)
#pragma unroll
            for (int r = 0; r < 4; r++) acc[i][j][r] = 0.0f;

    G_LDG(0);
    G_STS(0);
    __syncthreads();

    for (int it = 0; it < 16; ++it) {
        if (it < 15) G_LDG((it + 1) * 32);

        const float* S = sg + (it & 1) * G_STAGE;
#pragma unroll
        for (int ks = 0; ks < 4; ks++) {
            uint4 ah[2], al[2];
            uint2 bh[4], bl[4];
#pragma unroll
            for (int i = 0; i < 2; i++) {
                int off = ks * 1028 + (wm * 2 + i) * 128 + lane * 4;
                ah[i] = *(const uint4*)&S[off];
                al[i] = *(const uint4*)&S[4112 + off];
            }
#pragma unroll
            for (int j = 0; j < 4; j++) {
                int off = 8224 + ks * 514 + (wn * 4 + j) * 64 + lane * 2;
                bh[j] = *(const uint2*)&S[off];
                bl[j] = *(const uint2*)&S[2056 + off];
            }
#pragma unroll
            for (int i = 0; i < 2; i++)
#pragma unroll
                for (int j = 0; j < 4; j++) {
                    mma_tf32(acc[i][j], ah[i], bl[j]);
                    mma_tf32(acc[i][j], al[i], bh[j]);
                    mma_tf32(acc[i][j], ah[i], bh[j]);
                }
        }
        if (it < 15) {
            G_STS((it + 1) & 1);
            __syncthreads();
        }
    }

    const int g = lane >> 2;
    const int t = lane & 3;
#pragma unroll
    for (int i = 0; i < 2; i++) {
#pragma unroll
        for (int j = 0; j < 4; j++) {
#pragma unroll
            for (int r = 0; r < 4; r++) {
                int m = m0 + wm * 32 + i * 16 + g + (r >> 1) * 8;
                int n = n0 + wn * 32 + j * 8 + 2 * t + (r & 1);
                float v = (acc[i][j][r] + bias[n]) * oscale;
                int b = m >> 10;
                int s = m & 1023;
                if (mode == 0) {
                    int h = n >> 6, d = n & 63;
                    size_t idx = ((size_t)((b * NH + h) * SEQ + s)) * HD + d;
                    float hi = f2tf32f(v);
                    out_hi[idx] = hi;
                    out_lo[idx] = f2tf32f(v - hi);
                } else {
                    out_hi[((size_t)(b * EMB + n)) * SEQ + s] = v;
                }
            }
        }
    }
}
#undef G_LDG
#undef G_STS

// ---------------------------------------------------------------------------
// Kernel: mma flash attention. BM=128 q rows/block, 32-key tiles, 512 threads.
// QK^T warps: wm=w&7 (m16 tile 0..7), wn=w>>3 (16-key half).
// PV warps:   mt=w&7 (m16 tile),      nh=w>>3 (d half: n8 tiles nh*4..nh*4+3).
// Deferred-stats online softmax (4 barriers/tile), P via smem round-trip.
// smem floats: QH 0(8224) QL 8224 KH 16448(2064) KL 18512 VH 20576(2056)
//              VL 22632 PS 24688(128*34) MRUN 29040(128) LRUN 29168(128)
//              SMAX 29296(256) SSUM 29552(256)  total 29808 = 119232 B
// ---------------------------------------------------------------------------
#define F_QH   0
#define F_QL   8224
#define F_KH   16448
#define F_KL   18512
#define F_VH   20576
#define F_VL   22632
#define F_PS   24688
#define F_MRUN 29040
#define F_LRUN 29168
#define F_SMAX 29296
#define F_SSUM 29552
#define F_SMEMB (29808 * 4)

__global__ __launch_bounds__(512) void k_flash_mma(
    const float* __restrict__ q_hi, const float* __restrict__ q_lo,
    const float* __restrict__ k_hi, const float* __restrict__ k_lo,
    const float* __restrict__ v_hi, const float* __restrict__ v_lo,
    float* __restrict__ att_hi, float* __restrict__ att_lo)
{
    extern __shared__ float sm[];

    const int tid  = threadIdx.x;
    const int lane = tid & 31;
    const int w    = tid >> 5;
    const int bh   = blockIdx.y;
    const int q0   = blockIdx.x * 128;
    const size_t kvbase = (size_t)bh * SEQ * HD;

    if (tid < 128) {
        sm[F_MRUN + tid] = -1e30f;
        sm[F_LRUN + tid] = 0.0f;
    }

    // ---- load + scatter Q (A-fragment layout, 8 ks, pitch 1028) ----
    {
        int m  = tid >> 2;                 // 0..127
        int d0 = (tid & 3) * 16;
        int mt = m >> 4, mm = m & 15;
        int g = mm & 7, hm = mm >> 3;
        size_t grow = kvbase + (size_t)(q0 + m) * HD;
#pragma unroll
        for (int u4 = 0; u4 < 4; u4++) {
            int dd = d0 + u4 * 4;
            float4 vh = *(const float4*)&q_hi[grow + dd];
            float4 vl = *(const float4*)&q_lo[grow + dd];
            float eh[4] = {vh.x, vh.y, vh.z, vh.w};
            float el[4] = {vl.x, vl.y, vl.z, vl.w};
#pragma unroll
            for (int e = 0; e < 4; e++) {
                int d = dd + e;
                int ks = d >> 3, hk = (d >> 2) & 1, u = d & 3;
                int addr = ks * 1028 + mt * 128 + g * 16 + hk * 2 + hm + u * 4;
                sm[F_QH + addr] = eh[e];
                sm[F_QL + addr] = el[e];
            }
        }
    }

    const int wm = w & 7, wn = w >> 3;      // QK roles (8 m-tiles, 2 key halves)
    const int mt_pv = w & 7, nh = w >> 3;   // PV roles (8 m-tiles, 2 d halves)
    const int t = lane & 3;
    const int qrow = lane >> 2;

    const int rA = wm * 16 + qrow, rB = rA + 8;         // QK rows (0..127)
    const int prA = mt_pv * 16 + qrow, prB = prA + 8;   // PV rows

    float o[4][4];
#pragma unroll
    for (int j = 0; j < 4; j++)
#pragma unroll
        for (int r = 0; r < 4; r++) o[j][r] = 0.0f;

    for (int kt = 0; kt < SEQ; kt += 32) {
        __syncthreads();    // S0

        // deferred stats update for previous tile (owner lanes)
        if (kt > 0 && wn == 0 && t == 0) {
#pragma unroll
            for (int rr = 0; rr < 2; rr++) {
                int row = rA + rr * 8;
                float mold = sm[F_MRUN + row];
                float mt_  = fmaxf(sm[F_SMAX + row], sm[F_SMAX + 128 + row]);
                float mnew = fmaxf(mold, mt_);
                sm[F_LRUN + row] = sm[F_LRUN + row] * __expf(mold - mnew)
                                 + sm[F_SSUM + row] + sm[F_SSUM + 128 + row];
                sm[F_MRUN + row] = mnew;
            }
        }

        // ---- load + scatter K, V tiles (B-fragment layouts) ----
        {
            int kidx = tid >> 4;           // 0..31
            int d0   = (tid & 15) * 4;     // 0..60
            size_t krow = kvbase + (size_t)(kt + kidx) * HD;
            int knt = kidx >> 3, knn = kidx & 7;
            int vks = kidx >> 3;
            int vt = kidx & 3, vhk = (kidx >> 2) & 1;
            float4 kh4 = *(const float4*)&k_hi[krow + d0];
            float4 kl4 = *(const float4*)&k_lo[krow + d0];
            float4 vh4 = *(const float4*)&v_hi[krow + d0];
            float4 vl4 = *(const float4*)&v_lo[krow + d0];
            float keh[4] = {kh4.x, kh4.y, kh4.z, kh4.w};
            float kel[4] = {kl4.x, kl4.y, kl4.z, kl4.w};
            float veh[4] = {vh4.x, vh4.y, vh4.z, vh4.w};
            float vel[4] = {vl4.x, vl4.y, vl4.z, vl4.w};
#pragma unroll
            for (int e = 0; e < 4; e++) {
                int d = d0 + e;
                int kks = d >> 3, kt_ = d & 3, khk = (d >> 2) & 1;
                int kaddr = kks * 258 + knt * 64 + (knn * 4 + kt_) * 2 + khk;
                sm[F_KH + kaddr] = keh[e];
                sm[F_KL + kaddr] = kel[e];
                int vnt = d >> 3, vnn = d & 7;
                int vaddr = vks * 514 + vnt * 64 + (vnn * 4 + vt) * 2 + vhk;
                sm[F_VH + vaddr] = veh[e];
                sm[F_VL + vaddr] = vel[e];
            }
        }
        __syncthreads();    // S1

        // ---- QK^T mma (3xTF32) ----
        float sacc[2][4];
#pragma unroll
        for (int j = 0; j < 2; j++)
#pragma unroll
            for (int r = 0; r < 4; r++) sacc[j][r] = 0.0f;

#pragma unroll
        for (int ks = 0; ks < 8; ks++) {
            int aoff = ks * 1028 + wm * 128 + lane * 4;
            uint4 ah = *(const uint4*)&sm[F_QH + aoff];
            uint4 al = *(const uint4*)&sm[F_QL + aoff];
#pragma unroll
            for (int j = 0; j < 2; j++) {
                int jj = wn * 2 + j;
                int boff = ks * 258 + jj * 64 + lane * 2;
                uint2 bh = *(const uint2*)&sm[F_KH + boff];
                uint2 bl = *(const uint2*)&sm[F_KL + boff];
                mma_tf32(sacc[j], ah, bl);
                mma_tf32(sacc[j], al, bh);
                mma_tf32(sacc[j], ah, bh);
            }
        }

        // ---- local row max -> smem ----
        float mA = fmaxf(fmaxf(sacc[0][0], sacc[0][1]), fmaxf(sacc[1][0], sacc[1][1]));
        float mB = fmaxf(fmaxf(sacc[0][2], sacc[0][3]), fmaxf(sacc[1][2], sacc[1][3]));
        mA = fmaxf(mA, __shfl_xor_sync(FULLMASK, mA, 1));
        mA = fmaxf(mA, __shfl_xor_sync(FULLMASK, mA, 2));
        mB = fmaxf(mB, __shfl_xor_sync(FULLMASK, mB, 1));
        mB = fmaxf(mB, __shfl_xor_sync(FULLMASK, mB, 2));
        if (t == 0) {
            sm[F_SMAX + wn * 128 + rA] = mA;
            sm[F_SMAX + wn * 128 + rB] = mB;
        }
        __syncthreads();    // S2

        float mnewA = fmaxf(sm[F_MRUN + rA],
                            fmaxf(sm[F_SMAX + rA], sm[F_SMAX + 128 + rA]));
        float mnewB = fmaxf(sm[F_MRUN + rB],
                            fmaxf(sm[F_SMAX + rB], sm[F_SMAX + 128 + rB]));

        float p[2][4];
#pragma unroll
        for (int j = 0; j < 2; j++) {
            p[j][0] = __expf(sacc[j][0] - mnewA);
            p[j][1] = __expf(sacc[j][1] - mnewA);
            p[j][2] = __expf(sacc[j][2] - mnewB);
            p[j][3] = __expf(sacc[j][3] - mnewB);
        }
        float sA = p[0][0] + p[0][1] + p[1][0] + p[1][1];
        float sB = p[0][2] + p[0][3] + p[1][2] + p[1][3];
        sA += __shfl_xor_sync(FULLMASK, sA, 1);
        sA += __shfl_xor_sync(FULLMASK, sA, 2);
        sB += __shfl_xor_sync(FULLMASK, sB, 1);
        sB += __shfl_xor_sync(FULLMASK, sB, 2);
        if (t == 0) {
            sm[F_SSUM + wn * 128 + rA] = sA;
            sm[F_SSUM + wn * 128 + rB] = sB;
        }
        // write P (C-frag -> plain [row][col], pitch 34)
#pragma unroll
        for (int j = 0; j < 2; j++) {
            int c = wn * 16 + j * 8 + 2 * t;
            *(float2*)&sm[F_PS + rA * 34 + c] = make_float2(p[j][0], p[j][1]);
            *(float2*)&sm[F_PS + rB * 34 + c] = make_float2(p[j][2], p[j][3]);
        }
        __syncthreads();    // S3

        // ---- PV (3xTF32), per-lane alpha from pre-tile stats ----
        float moldA = sm[F_MRUN + prA], moldB = sm[F_MRUN + prB];
        float mnA = fmaxf(moldA, fmaxf(sm[F_SMAX + prA], sm[F_SMAX + 128 + prA]));
        float mnB = fmaxf(moldB, fmaxf(sm[F_SMAX + prB], sm[F_SMAX + 128 + prB]));
        float alA = __expf(moldA - mnA);
        float alB = __expf(moldB - mnB);
#pragma unroll
        for (int j = 0; j < 4; j++) {
            o[j][0] *= alA; o[j][1] *= alA;
            o[j][2] *= alB; o[j][3] *= alB;
        }
#pragma unroll
        for (int ks = 0; ks < 4; ks++) {
            float p0 = sm[F_PS + prA * 34 + ks * 8 + t];
            float p1 = sm[F_PS + prB * 34 + ks * 8 + t];
            float p2 = sm[F_PS + prA * 34 + ks * 8 + t + 4];
            float p3 = sm[F_PS + prB * 34 + ks * 8 + t + 4];
            uint4 ah, al;
            ah.x = f2tf32u(p0); al.x = f2tf32u(p0 - __uint_as_float(ah.x));
            ah.y = f2tf32u(p1); al.y = f2tf32u(p1 - __uint_as_float(ah.y));
            ah.z = f2tf32u(p2); al.z = f2tf32u(p2 - __uint_as_float(ah.z));
            ah.w = f2tf32u(p3); al.w = f2tf32u(p3 - __uint_as_float(ah.w));
#pragma unroll
            for (int jl = 0; jl < 4; jl++) {
                int j = nh * 4 + jl;
                int boff = ks * 514 + j * 64 + lane * 2;
                uint2 bh = *(const uint2*)&sm[F_VH + boff];
                uint2 bl = *(const uint2*)&sm[F_VL + boff];
                mma_tf32(o[jl], ah, bl);
                mma_tf32(o[jl], al, bh);
                mma_tf32(o[jl], ah, bh);
            }
        }
    }

    // final deferred stats update
    __syncthreads();
    if (wn == 0 && t == 0) {
#pragma unroll
        for (int rr = 0; rr < 2; rr++) {
            int row = rA + rr * 8;
            float mold = sm[F_MRUN + row];
            float mt_  = fmaxf(sm[F_SMAX + row], sm[F_SMAX + 128 + row]);
            float mnew = fmaxf(mold, mt_);
            sm[F_LRUN + row] = sm[F_LRUN + row] * __expf(mold - mnew)
                             + sm[F_SSUM + row] + sm[F_SSUM + 128 + row];
        }
    }
    __syncthreads();

    // ---- epilogue: o /= l, split hi/lo, write att[b*s, E] ----
    const float invA = 1.0f / sm[F_LRUN + prA];
    const float invB = 1.0f / sm[F_LRUN + prB];
    const int b = bh >> 3, h = bh & 7;
    const size_t rowA = ((size_t)(b * SEQ + q0 + prA)) * EMB + h * HD;
    const size_t rowB = ((size_t)(b * SEQ + q0 + prB)) * EMB + h * HD;
#pragma unroll
    for (int jl = 0; jl < 4; jl++) {
        int e = nh * 32 + jl * 8 + 2 * t;
        float v0 = o[jl][0] * invA, v1 = o[jl][1] * invA;
        float v2 = o[jl][2] * invB, v3 = o[jl][3] * invB;
        float h0 = f2tf32f(v0), h1 = f2tf32f(v1);
        float h2 = f2tf32f(v2), h3 = f2tf32f(v3);
        *(float2*)&att_hi[rowA + e] = make_float2(h0, h1);
        *(float2*)&att_lo[rowA + e] = make_float2(f2tf32f(v0 - h0), f2tf32f(v1 - h1));
        *(float2*)&att_hi[rowB + e] = make_float2(h2, h3);
        *(float2*)&att_lo[rowB + e] = make_float2(f2tf32f(v2 - h2), f2tf32f(v3 - h3));
    }
}

// ---------------------------------------------------------------------------
extern "C" void kernel_launch(void* const* d_in, const int* in_sizes, int n_in,
                              void* d_out, int out_size)
{
    const float* x     = (const float*)d_in[0];
    const float* pos_w = (const float*)d_in[1];
    const float* pos_b = (const float*)d_in[2];
    const float* wq    = (const float*)d_in[3];
    const float* bq    = (const float*)d_in[4];
    const float* wk    = (const float*)d_in[5];
    const float* bk    = (const float*)d_in[6];
    const float* wv    = (const float*)d_in[7];
    const float* bv    = (const float*)d_in[8];
    const float* wo    = (const float*)d_in[9];
    const float* bo    = (const float*)d_in[10];
    float* out = (float*)d_out;

    void* sp = nullptr;
    cudaGetSymbolAddress(&sp, g_scratch);
    float* base   = (float*)sp;
    float* xt_hi  = base;
    float* xt_lo  = xt_hi + PLANE;
    float* q_hi   = xt_lo + PLANE;
    float* q_lo   = q_hi  + PLANE;
    float* k_hi   = q_lo  + PLANE;
    float* k_lo   = k_hi  + PLANE;
    float* v_hi   = k_lo  + PLANE;
    float* v_lo   = v_hi  + PLANE;
    float* att_hi = v_lo  + PLANE;
    float* att_lo = att_hi + PLANE;
    float* wsp    = att_lo + PLANE;
    float* wq_hi = wsp;              float* wq_lo = wq_hi + WPLANE;
    float* wk_hi = wq_lo + WPLANE;   float* wk_lo = wk_hi + WPLANE;
    float* wv_hi = wk_lo + WPLANE;   float* wv_lo = wv_hi + WPLANE;
    float* wo_hi = wv_lo + WPLANE;   float* wo_lo = wo_hi + WPLANE;

    cudaFuncSetAttribute(k_gemm, cudaFuncAttributeMaxDynamicSharedMemorySize, G_SMEMB);
    cudaFuncSetAttribute(k_flash_mma, cudaFuncAttributeMaxDynamicSharedMemorySize, F_SMEMB);

    // 1) transpose + PE -> xt hi/lo
    {
        dim3 grid(EMB / 32, SEQ / 32, BATCH);
        dim3 block(32, 8);
        k_transpose_pe<<<grid, block>>>(x, pos_w, pos_b, xt_hi, xt_lo);
    }
    // 2) all 4 weight splits in one launch
    {
        dim3 grid((unsigned)(WPLANE / 256), 4);
        k_split4<<<grid, 256>>>(wq, wk, wv, wo, wsp);
    }
    // 3) QKV projections (Q pre-scaled by 1/sqrt(d)=0.125)
    {
        dim3 grid(EMB / 64, MTOT / 128);
        k_gemm<<<grid, 256, G_SMEMB>>>(xt_hi, xt_lo, wq_hi, wq_lo, bq, q_hi, q_lo, 0, 0.125f);
        k_gemm<<<grid, 256, G_SMEMB>>>(xt_hi, xt_lo, wk_hi, wk_lo, bk, k_hi, k_lo, 0, 1.0f);
        k_gemm<<<grid, 256, G_SMEMB>>>(xt_hi, xt_lo, wv_hi, wv_lo, bv, v_hi, v_lo, 0, 1.0f);
    }
    // 4) flash attention (mma), BM=128
    {
        dim3 grid(SEQ / 128, BATCH * NH);
        k_flash_mma<<<grid, 512, F_SMEMB>>>(q_hi, q_lo, k_hi, k_lo, v_hi, v_lo,
                                            att_hi, att_lo);
    }
    // 5) output projection -> [b,c,h,w]
    {
        dim3 grid(EMB / 64, MTOT / 128);
        k_gemm<<<grid, 256, G_SMEMB>>>(att_hi, att_lo, wo_hi, wo_lo, bo, out, out, 1, 1.0f);
    }
}

// round 7
// speedup vs baseline: 1.8601x; 1.7068x over previous
#include <cuda_runtime.h>
#include <cstdint>

// ---------------------------------------------------------------------------
// SelfAttentionWithPE: B=8, E=512, H=W=32 (S=1024), heads=8, head_dim=64, fp32
// 3xTF32 (hi/lo) mma.sync.m16n8k8 everywhere. All operands stored in gmem in
// FRAGMENT-PERMUTED layouts so hot-loop smem fills are identity cp.async.
// ---------------------------------------------------------------------------

#define BATCH 8
#define EMB   512
#define SEQ   1024
#define NH    8
#define HD    64
#define MTOT  (BATCH * SEQ)
#define FULLMASK 0xffffffffu

#define PLANE   ((size_t)MTOT * EMB)        // 4,194,304 floats
#define WPLANE  ((size_t)EMB * EMB)         // 262,144
__device__ float g_scratch[10 * 4194304 + 8 * 262144];

__device__ __forceinline__ float f2tf32f(float x)
{
    unsigned u;
    asm("cvt.rna.tf32.f32 %0, %1;" : "=r"(u) : "f"(x));
    return __uint_as_float(u);
}
__device__ __forceinline__ unsigned f2tf32u(float x)
{
    unsigned u;
    asm("cvt.rna.tf32.f32 %0, %1;" : "=r"(u) : "f"(x));
    return u;
}

__device__ __forceinline__ void mma_tf32(float* d, const uint4& a, const uint2& b)
{
    asm volatile(
        "mma.sync.aligned.m16n8k8.row.col.f32.tf32.tf32.f32 "
        "{%0,%1,%2,%3}, {%4,%5,%6,%7}, {%8,%9}, {%0,%1,%2,%3};\n"
        : "+f"(d[0]), "+f"(d[1]), "+f"(d[2]), "+f"(d[3])
        : "r"(a.x), "r"(a.y), "r"(a.z), "r"(a.w), "r"(b.x), "r"(b.y));
}

__device__ __forceinline__ void cp_async16(uint32_t smem_byte, const void* g)
{
    asm volatile("cp.async.cg.shared.global [%0], [%1], 16;\n"
                 :: "r"(smem_byte), "l"(g));
}
#define CP_COMMIT() asm volatile("cp.async.commit_group;\n" ::: "memory")
#define CP_WAIT0()  asm volatile("cp.async.wait_group 0;\n" ::: "memory")

// ---------------------------------------------------------------------------
// Fragment-layout address helpers (bijections validated in R3/R5/R6 runs).
// A-frag (within 128 rows): (k>>3)*1024 + (m>>4)*128 + (m&7)*16
//                           + ((k>>2)&1)*2 + ((m>>3)&1) + (k&3)*4
// B-frag (within 64 cols):  (k>>3)*512 + (n>>3)*64 + ((n&7)*4+(k&3))*2
//                           + ((k>>2)&1)
// ---------------------------------------------------------------------------
__device__ __forceinline__ size_t afrag_xt(int m, int k)   // xt/att: [mblk64][ks64][8][128]
{
    return (size_t)(m >> 7) * 65536 + (size_t)(k >> 3) * 1024
         + ((m & 127) >> 4) * 128 + (m & 7) * 16
         + ((k >> 2) & 1) * 2 + ((m >> 3) & 1) + (k & 3) * 4;
}
__device__ __forceinline__ size_t bfrag_w(int k, int n)    // W: [nblk8][ks64][512]
{
    return (size_t)(n >> 6) * 32768 + (size_t)(k >> 3) * 512
         + ((n & 63) >> 3) * 64 + (((n & 7) * 4 + (k & 3)) * 2) + ((k >> 2) & 1);
}
__device__ __forceinline__ size_t qfrag(int bh, int s, int d)  // Q: [bh][sblk8][ks8][8][128]
{
    return (size_t)bh * 65536 + (size_t)(s >> 7) * 8192 + (size_t)(d >> 3) * 1024
         + ((s & 127) >> 4) * 128 + (s & 7) * 16
         + ((d >> 2) & 1) * 2 + ((s >> 3) & 1) + (d & 3) * 4;
}
__device__ __forceinline__ size_t kfrag(int bh, int s, int d)  // K: [bh][ktile32][ks8][256]
{
    return (size_t)bh * 65536 + (size_t)(s >> 5) * 2048 + (size_t)(d >> 3) * 256
         + ((s & 31) >> 3) * 64 + (((s & 7) * 4 + (d & 3)) * 2) + ((d >> 2) & 1);
}
__device__ __forceinline__ size_t vfrag(int bh, int s, int d)  // V: [bh][ktile32][vks4][8][64]
{
    return (size_t)bh * 65536 + (size_t)(s >> 5) * 2048 + ((size_t)((s & 31) >> 3)) * 512
         + (d >> 3) * 64 + (((d & 7) * 4 + (s & 3)) * 2) + ((s >> 2) & 1);
}

// ---------------------------------------------------------------------------
// Kernel: transpose + PE -> xt hi/lo in A-frag global layout
// ---------------------------------------------------------------------------
__global__ void k_transpose_pe(const float* __restrict__ x,
                               const float* __restrict__ pos_w,
                               const float* __restrict__ pos_b,
                               float* __restrict__ xt_hi,
                               float* __restrict__ xt_lo)
{
    __shared__ float tile[32][33];
    const int e0 = blockIdx.x * 32;
    const int s0 = blockIdx.y * 32;
    const int b  = blockIdx.z;
    const int tx = threadIdx.x;
    const int ty = threadIdx.y;

#pragma unroll
    for (int i = 0; i < 4; i++) {
        int el = ty + i * 8;
        tile[el][tx] = x[((size_t)(b * EMB + e0 + el)) * SEQ + s0 + tx];
    }
    __syncthreads();

    const int e = e0 + tx;
    const float pw0 = pos_w[e];
    const float pw1 = pos_w[EMB + e];
    const float pb  = pos_b[e];
#pragma unroll
    for (int i = 0; i < 4; i++) {
        int sl = ty + i * 8;
        int s  = s0 + sl;
        float row = (float)(s >> 5);
        float col = (float)(s & 31);
        float v = tile[tx][sl] + row * pw0 + col * pw1 + pb;
        size_t idx = afrag_xt(b * SEQ + s, e);
        float hi = f2tf32f(v);
        xt_hi[idx] = hi;
        xt_lo[idx] = f2tf32f(v - hi);
    }
}

// ---------------------------------------------------------------------------
// Kernel: split all 4 weight matrices into hi/lo B-frag layout, one launch.
// ---------------------------------------------------------------------------
__global__ void k_split4(const float* __restrict__ w0, const float* __restrict__ w1,
                         const float* __restrict__ w2, const float* __restrict__ w3,
                         float* __restrict__ base_hi_lo)
{
    const float* src;
    switch (blockIdx.y) {
        case 0: src = w0; break;
        case 1: src = w1; break;
        case 2: src = w2; break;
        default: src = w3; break;
    }
    float* hi = base_hi_lo + (size_t)blockIdx.y * 2 * WPLANE;
    float* lo = hi + WPLANE;
    int i = blockIdx.x * 256 + threadIdx.x;
    int k = i >> 9, n = i & 511;
    float v = src[i];
    float h = f2tf32f(v);
    size_t idx = bfrag_w(k, n);
    hi[idx] = h;
    lo[idx] = f2tf32f(v - h);
}

// ---------------------------------------------------------------------------
// Kernel: 3xTF32 GEMM. BM=128 BN=64 BK=32, cp.async double-buffered.
// Inputs in frag gmem layout -> identity copies.
// Stage (floats): [A_hi 4096][A_lo 4096][B_hi 2048][B_lo 2048] = 12288.
// mode: 0=Q(qfrag,hi/lo) 1=K(kfrag) 2=V(vfrag) 3=final out[b,E,32,32]
// ---------------------------------------------------------------------------
#define G_STAGE 12288
#define G_SMEMB (2 * G_STAGE * 4)   // 98304 bytes

__global__ __launch_bounds__(256) void k_gemm(
    const float* __restrict__ A_hi, const float* __restrict__ A_lo,
    const float* __restrict__ W_hi, const float* __restrict__ W_lo,
    const float* __restrict__ bias,
    float* __restrict__ out_hi, float* __restrict__ out_lo,
    int mode, float oscale)
{
    extern __shared__ float sg[];
    uint32_t sbase = (uint32_t)__cvta_generic_to_shared(sg);

    const int tid  = threadIdx.x;
    const int lane = tid & 31;
    const int w    = tid >> 5;
    const int wm   = w >> 1;
    const int wn   = w & 1;
    const int mblk = blockIdx.y;
    const int nblk = blockIdx.x;
    const int m0   = mblk * 128;
    const int n0   = nblk * 64;

#define G_ISSUE(it, st)                                                        \
    {                                                                          \
        uint32_t sb = sbase + (st) * 49152;                                    \
        size_t asrc = (size_t)mblk * 65536 + (size_t)(it) * 4096;              \
        size_t bsrc = (size_t)nblk * 32768 + (size_t)(it) * 2048;              \
        _Pragma("unroll")                                                      \
        for (int p = 0; p < 4; p++) {                                          \
            int u = p * 256 + tid;                                             \
            cp_async16(sb + u * 16,         A_hi + asrc + u * 4);              \
            cp_async16(sb + 16384 + u * 16, A_lo + asrc + u * 4);              \
        }                                                                      \
        _Pragma("unroll")                                                      \
        for (int p = 0; p < 2; p++) {                                          \
            int u = p * 256 + tid;                                             \
            cp_async16(sb + 32768 + u * 16, W_hi + bsrc + u * 4);              \
            cp_async16(sb + 40960 + u * 16, W_lo + bsrc + u * 4);              \
        }                                                                      \
        CP_COMMIT();                                                           \
    }

    float acc[2][4][4];
#pragma unroll
    for (int i = 0; i < 2; i++)
#pragma unroll
        for (int j = 0; j < 4; j++)
#pragma unroll
            for (int r = 0; r < 4; r++) acc[i][j][r] = 0.0f;

    G_ISSUE(0, 0);

    for (int it = 0; it < 16; ++it) {
        CP_WAIT0();
        __syncthreads();
        if (it < 15) G_ISSUE(it + 1, (it + 1) & 1);

        const float* S = sg + (it & 1) * G_STAGE;
#pragma unroll
        for (int ks = 0; ks < 4; ks++) {
            uint4 ah[2], al[2];
            uint2 bh[4], bl[4];
#pragma unroll
            for (int i = 0; i < 2; i++) {
                int off = ks * 1024 + (wm * 2 + i) * 128 + lane * 4;
                ah[i] = *(const uint4*)&S[off];
                al[i] = *(const uint4*)&S[4096 + off];
            }
#pragma unroll
            for (int j = 0; j < 4; j++) {
                int off = 8192 + ks * 512 + (wn * 4 + j) * 64 + lane * 2;
                bh[j] = *(const uint2*)&S[off];
                bl[j] = *(const uint2*)&S[2048 + off];
            }
#pragma unroll
            for (int i = 0; i < 2; i++)
#pragma unroll
                for (int j = 0; j < 4; j++) {
                    mma_tf32(acc[i][j], ah[i], bl[j]);
                    mma_tf32(acc[i][j], al[i], bh[j]);
                    mma_tf32(acc[i][j], ah[i], bh[j]);
                }
        }
        if (it < 15) __syncthreads();   // compute done before next buffer reuse
    }

    const int g = lane >> 2;
    const int t = lane & 3;
#pragma unroll
    for (int i = 0; i < 2; i++) {
#pragma unroll
        for (int j = 0; j < 4; j++) {
#pragma unroll
            for (int r = 0; r < 4; r++) {
                int m = m0 + wm * 32 + i * 16 + g + (r >> 1) * 8;
                int n = n0 + wn * 32 + j * 8 + 2 * t + (r & 1);
                float v = (acc[i][j][r] + bias[n]) * oscale;
                int b = m >> 10;
                int s = m & 1023;
                if (mode == 3) {
                    out_hi[((size_t)(b * EMB + n)) * SEQ + s] = v;
                } else {
                    int h = n >> 6, d = n & 63;
                    int bh = b * NH + h;
                    size_t idx;
                    if (mode == 0)      idx = qfrag(bh, s, d);
                    else if (mode == 1) idx = kfrag(bh, s, d);
                    else                idx = vfrag(bh, s, d);
                    float hi = f2tf32f(v);
                    out_hi[idx] = hi;
                    out_lo[idx] = f2tf32f(v - hi);
                }
            }
        }
    }
}
#undef G_ISSUE

// ---------------------------------------------------------------------------
// Kernel: mma flash attention. BM=128, 32-key tiles, 512 threads.
// Q + K/V arrive via identity cp.async (frag gmem layouts); K/V double-buffered.
// smem floats: QH 0(8192) QL 8192 | KV buf0 16384, buf1 24576
//   (per buf: KH+0 KL+2048 VH+4096 VL+6144)
// PS 32768(128*34=4352) MRUN 37120 LRUN 37248 SMAX 37376(256) SSUM 37632(256)
// total 37888 floats = 151552 B
// ---------------------------------------------------------------------------
#define F_QH   0
#define F_QL   8192
#define F_KV   16384
#define F_PS   32768
#define F_MRUN 37120
#define F_LRUN 37248
#define F_SMAX 37376
#define F_SSUM 37632
#define F_SMEMB (37888 * 4)

__global__ __launch_bounds__(512) void k_flash_mma(
    const float* __restrict__ q_hi, const float* __restrict__ q_lo,
    const float* __restrict__ k_hi, const float* __restrict__ k_lo,
    const float* __restrict__ v_hi, const float* __restrict__ v_lo,
    float* __restrict__ att_hi, float* __restrict__ att_lo)
{
    extern __shared__ float sm[];
    uint32_t sbase = (uint32_t)__cvta_generic_to_shared(sm);

    const int tid  = threadIdx.x;
    const int lane = tid & 31;
    const int w    = tid >> 5;
    const int bh   = blockIdx.y;
    const int q0   = blockIdx.x * 128;
    const size_t qbase = (size_t)bh * 65536 + (size_t)(q0 >> 7) * 8192;
    const size_t kvb   = (size_t)bh * 65536;

    if (tid < 128) {
        sm[F_MRUN + tid] = -1e30f;
        sm[F_LRUN + tid] = 0.0f;
    }

    // Q planes: 8192 floats each, identity cp.async
#pragma unroll
    for (int p = 0; p < 4; p++) {
        int u = p * 512 + tid;
        cp_async16(sbase + u * 16,          q_hi + qbase + u * 4);
        cp_async16(sbase + 32768 + u * 16,  q_lo + qbase + u * 4);
    }
    // KV tile 0 into buf 0: each plane 2048 floats = 512 units (1/thread)
    {
        size_t src = kvb;
        uint32_t db = sbase + 65536;
        cp_async16(db + tid * 16,         k_hi + src + tid * 4);
        cp_async16(db + 8192 + tid * 16,  k_lo + src + tid * 4);
        cp_async16(db + 16384 + tid * 16, v_hi + src + tid * 4);
        cp_async16(db + 24576 + tid * 16, v_lo + src + tid * 4);
    }
    CP_COMMIT();

    const int wm = w & 7, wn = w >> 3;      // QK roles
    const int mt_pv = w & 7, nh = w >> 3;   // PV roles
    const int t = lane & 3;
    const int qrow = lane >> 2;

    const int rA = wm * 16 + qrow, rB = rA + 8;
    const int prA = mt_pv * 16 + qrow, prB = prA + 8;

    float o[4][4];
#pragma unroll
    for (int j = 0; j < 4; j++)
#pragma unroll
        for (int r = 0; r < 4; r++) o[j][r] = 0.0f;

    for (int ti = 0; ti < 32; ++ti) {
        CP_WAIT0();
        __syncthreads();    // tile ti ready; prev iteration fully done

        if (ti < 31) {
            size_t src = kvb + (size_t)(ti + 1) * 2048;
            uint32_t db = sbase + 65536 + ((ti + 1) & 1) * 32768;
            cp_async16(db + tid * 16,         k_hi + src + tid * 4);
            cp_async16(db + 8192 + tid * 16,  k_lo + src + tid * 4);
            cp_async16(db + 16384 + tid * 16, v_hi + src + tid * 4);
            cp_async16(db + 24576 + tid * 16, v_lo + src + tid * 4);
            CP_COMMIT();
        }
        const float* KV = sm + F_KV + (ti & 1) * 8192;

        // deferred stats update for previous tile (owner lanes)
        if (ti > 0 && wn == 0 && t == 0) {
#pragma unroll
            for (int rr = 0; rr < 2; rr++) {
                int row = rA + rr * 8;
                float mold = sm[F_MRUN + row];
                float mt_  = fmaxf(sm[F_SMAX + row], sm[F_SMAX + 128 + row]);
                float mnew = fmaxf(mold, mt_);
                sm[F_LRUN + row] = sm[F_LRUN + row] * __expf(mold - mnew)
                                 + sm[F_SSUM + row] + sm[F_SSUM + 128 + row];
                sm[F_MRUN + row] = mnew;
            }
        }

        // ---- QK^T mma (3xTF32) ----
        float sacc[2][4];
#pragma unroll
        for (int j = 0; j < 2; j++)
#pragma unroll
            for (int r = 0; r < 4; r++) sacc[j][r] = 0.0f;

#pragma unroll
        for (int ks = 0; ks < 8; ks++) {
            int aoff = ks * 1024 + wm * 128 + lane * 4;
            uint4 ah = *(const uint4*)&sm[F_QH + aoff];
            uint4 al = *(const uint4*)&sm[F_QL + aoff];
#pragma unroll
            for (int j = 0; j < 2; j++) {
                int jj = wn * 2 + j;
                int boff = ks * 256 + jj * 64 + lane * 2;
                uint2 bh = *(const uint2*)&KV[boff];
                uint2 bl = *(const uint2*)&KV[2048 + boff];
                mma_tf32(sacc[j], ah, bl);
                mma_tf32(sacc[j], al, bh);
                mma_tf32(sacc[j], ah, bh);
            }
        }

        // ---- local row max -> smem ----
        float mA = fmaxf(fmaxf(sacc[0][0], sacc[0][1]), fmaxf(sacc[1][0], sacc[1][1]));
        float mB = fmaxf(fmaxf(sacc[0][2], sacc[0][3]), fmaxf(sacc[1][2], sacc[1][3]));
        mA = fmaxf(mA, __shfl_xor_sync(FULLMASK, mA, 1));
        mA = fmaxf(mA, __shfl_xor_sync(FULLMASK, mA, 2));
        mB = fmaxf(mB, __shfl_xor_sync(FULLMASK, mB, 1));
        mB = fmaxf(mB, __shfl_xor_sync(FULLMASK, mB, 2));
        if (t == 0) {
            sm[F_SMAX + wn * 128 + rA] = mA;
            sm[F_SMAX + wn * 128 + rB] = mB;
        }
        __syncthreads();    // S2: SMAX + stats updates visible

        float mnewA = fmaxf(sm[F_MRUN + rA],
                            fmaxf(sm[F_SMAX + rA], sm[F_SMAX + 128 + rA]));
        float mnewB = fmaxf(sm[F_MRUN + rB],
                            fmaxf(sm[F_SMAX + rB], sm[F_SMAX + 128 + rB]));

        float p[2][4];
#pragma unroll
        for (int j = 0; j < 2; j++) {
            p[j][0] = __expf(sacc[j][0] - mnewA);
            p[j][1] = __expf(sacc[j][1] - mnewA);
            p[j][2] = __expf(sacc[j][2] - mnewB);
            p[j][3] = __expf(sacc[j][3] - mnewB);
        }
        float sA = p[0][0] + p[0][1] + p[1][0] + p[1][1];
        float sB = p[0][2] + p[0][3] + p[1][2] + p[1][3];
        sA += __shfl_xor_sync(FULLMASK, sA, 1);
        sA += __shfl_xor_sync(FULLMASK, sA, 2);
        sB += __shfl_xor_sync(FULLMASK, sB, 1);
        sB += __shfl_xor_sync(FULLMASK, sB, 2);
        if (t == 0) {
            sm[F_SSUM + wn * 128 + rA] = sA;
            sm[F_SSUM + wn * 128 + rB] = sB;
        }
#pragma unroll
        for (int j = 0; j < 2; j++) {
            int c = wn * 16 + j * 8 + 2 * t;
            *(float2*)&sm[F_PS + rA * 34 + c] = make_float2(p[j][0], p[j][1]);
            *(float2*)&sm[F_PS + rB * 34 + c] = make_float2(p[j][2], p[j][3]);
        }
        __syncthreads();    // S3: P + SSUM visible

        // ---- PV (3xTF32) ----
        float moldA = sm[F_MRUN + prA], moldB = sm[F_MRUN + prB];
        float mnA = fmaxf(moldA, fmaxf(sm[F_SMAX + prA], sm[F_SMAX + 128 + prA]));
        float mnB = fmaxf(moldB, fmaxf(sm[F_SMAX + prB], sm[F_SMAX + 128 + prB]));
        float alA = __expf(moldA - mnA);
        float alB = __expf(moldB - mnB);
#pragma unroll
        for (int j = 0; j < 4; j++) {
            o[j][0] *= alA; o[j][1] *= alA;
            o[j][2] *= alB; o[j][3] *= alB;
        }
#pragma unroll
        for (int ks = 0; ks < 4; ks++) {
            float p0 = sm[F_PS + prA * 34 + ks * 8 + t];
            float p1 = sm[F_PS + prB * 34 + ks * 8 + t];
            float p2 = sm[F_PS + prA * 34 + ks * 8 + t + 4];
            float p3 = sm[F_PS + prB * 34 + ks * 8 + t + 4];
            uint4 ah, al;
            ah.x = f2tf32u(p0); al.x = f2tf32u(p0 - __uint_as_float(ah.x));
            ah.y = f2tf32u(p1); al.y = f2tf32u(p1 - __uint_as_float(ah.y));
            ah.z = f2tf32u(p2); al.z = f2tf32u(p2 - __uint_as_float(ah.z));
            ah.w = f2tf32u(p3); al.w = f2tf32u(p3 - __uint_as_float(ah.w));
#pragma unroll
            for (int jl = 0; jl < 4; jl++) {
                int j = nh * 4 + jl;
                int boff = 4096 + ks * 512 + j * 64 + lane * 2;
                uint2 bh = *(const uint2*)&KV[boff];
                uint2 bl = *(const uint2*)&KV[2048 + boff];
                mma_tf32(o[jl], ah, bl);
                mma_tf32(o[jl], al, bh);
                mma_tf32(o[jl], ah, bh);
            }
        }
    }

    // final deferred stats update
    __syncthreads();
    if (wn == 0 && t == 0) {
#pragma unroll
        for (int rr = 0; rr < 2; rr++) {
            int row = rA + rr * 8;
            float mold = sm[F_MRUN + row];
            float mt_  = fmaxf(sm[F_SMAX + row], sm[F_SMAX + 128 + row]);
            float mnew = fmaxf(mold, mt_);
            sm[F_LRUN + row] = sm[F_LRUN + row] * __expf(mold - mnew)
                             + sm[F_SSUM + row] + sm[F_SSUM + 128 + row];
        }
    }
    __syncthreads();

    // ---- epilogue: o /= l, hi/lo split, att in A-frag layout ----
    const float invA = 1.0f / sm[F_LRUN + prA];
    const float invB = 1.0f / sm[F_LRUN + prB];
    const int b = bh >> 3, h = bh & 7;
    const int mA_g = b * SEQ + q0 + prA;
    const int mB_g = b * SEQ + q0 + prB;
#pragma unroll
    for (int jl = 0; jl < 4; jl++) {
#pragma unroll
        for (int rr = 0; rr < 2; rr++) {
            int e = h * HD + nh * 32 + jl * 8 + 2 * t + rr;
            float vA = o[jl][rr]     * invA;
            float vB = o[jl][rr + 2] * invB;
            float hA = f2tf32f(vA), hB = f2tf32f(vB);
            size_t iA = afrag_xt(mA_g, e);
            size_t iB = afrag_xt(mB_g, e);
            att_hi[iA] = hA;  att_lo[iA] = f2tf32f(vA - hA);
            att_hi[iB] = hB;  att_lo[iB] = f2tf32f(vB - hB);
        }
    }
}

// ---------------------------------------------------------------------------
extern "C" void kernel_launch(void* const* d_in, const int* in_sizes, int n_in,
                              void* d_out, int out_size)
{
    const float* x     = (const float*)d_in[0];
    const float* pos_w = (const float*)d_in[1];
    const float* pos_b = (const float*)d_in[2];
    const float* wq    = (const float*)d_in[3];
    const float* bq    = (const float*)d_in[4];
    const float* wk    = (const float*)d_in[5];
    const float* bk    = (const float*)d_in[6];
    const float* wv    = (const float*)d_in[7];
    const float* bv    = (const float*)d_in[8];
    const float* wo    = (const float*)d_in[9];
    const float* bo    = (const float*)d_in[10];
    float* out = (float*)d_out;

    void* sp = nullptr;
    cudaGetSymbolAddress(&sp, g_scratch);
    float* base   = (float*)sp;
    float* xt_hi  = base;
    float* xt_lo  = xt_hi + PLANE;
    float* q_hi   = xt_lo + PLANE;
    float* q_lo   = q_hi  + PLANE;
    float* k_hi   = q_lo  + PLANE;
    float* k_lo   = k_hi  + PLANE;
    float* v_hi   = k_lo  + PLANE;
    float* v_lo   = v_hi  + PLANE;
    float* att_hi = v_lo  + PLANE;
    float* att_lo = att_hi + PLANE;
    float* wsp    = att_lo + PLANE;
    float* wq_hi = wsp;              float* wq_lo = wq_hi + WPLANE;
    float* wk_hi = wq_lo + WPLANE;   float* wk_lo = wk_hi + WPLANE;
    float* wv_hi = wk_lo + WPLANE;   float* wv_lo = wv_hi + WPLANE;
    float* wo_hi = wv_lo + WPLANE;   float* wo_lo = wo_hi + WPLANE;

    cudaFuncSetAttribute(k_gemm, cudaFuncAttributeMaxDynamicSharedMemorySize, G_SMEMB);
    cudaFuncSetAttribute(k_flash_mma, cudaFuncAttributeMaxDynamicSharedMemorySize, F_SMEMB);

    {
        dim3 grid(EMB / 32, SEQ / 32, BATCH);
        dim3 block(32, 8);
        k_transpose_pe<<<grid, block>>>(x, pos_w, pos_b, xt_hi, xt_lo);
    }
    {
        dim3 grid((unsigned)(WPLANE / 256), 4);
        k_split4<<<grid, 256>>>(wq, wk, wv, wo, wsp);
    }
    {
        dim3 grid(EMB / 64, MTOT / 128);
        k_gemm<<<grid, 256, G_SMEMB>>>(xt_hi, xt_lo, wq_hi, wq_lo, bq, q_hi, q_lo, 0, 0.125f);
        k_gemm<<<grid, 256, G_SMEMB>>>(xt_hi, xt_lo, wk_hi, wk_lo, bk, k_hi, k_lo, 1, 1.0f);
        k_gemm<<<grid, 256, G_SMEMB>>>(xt_hi, xt_lo, wv_hi, wv_lo, bv, v_hi, v_lo, 2, 1.0f);
    }
    {
        dim3 grid(SEQ / 128, BATCH * NH);
        k_flash_mma<<<grid, 512, F_SMEMB>>>(q_hi, q_lo, k_hi, k_lo, v_hi, v_lo,
                                            att_hi, att_lo);
    }
    {
        dim3 grid(EMB / 64, MTOT / 128);
        k_gemm<<<grid, 256, G_SMEMB>>>(att_hi, att_lo, wo_hi, wo_lo, bo, out, out, 3, 1.0f);
    }
}

// round 9
// speedup vs baseline: 2.0521x; 1.1032x over previous
#include <cuda_runtime.h>
#include <cstdint>

// ---------------------------------------------------------------------------
// SelfAttentionWithPE: B=8, E=512, H=W=32 (S=1024), heads=8, head_dim=64, fp32
// 3xTF32 (hi/lo) mma.sync.m16n8k8 everywhere. All operands stored in gmem in
// FRAGMENT-PERMUTED layouts so hot-loop smem fills are identity cp.async.
// Flash: 64-key tiles, 2 syncs/tile, local-base softmax, register stats.
// ---------------------------------------------------------------------------

#define BATCH 8
#define EMB   512
#define SEQ   1024
#define NH    8
#define HD    64
#define MTOT  (BATCH * SEQ)
#define FULLMASK 0xffffffffu

#define PLANE   ((size_t)MTOT * EMB)        // 4,194,304 floats
#define WPLANE  ((size_t)EMB * EMB)         // 262,144
__device__ float g_scratch[10 * 4194304 + 8 * 262144];

__device__ __forceinline__ float f2tf32f(float x)
{
    unsigned u;
    asm("cvt.rna.tf32.f32 %0, %1;" : "=r"(u) : "f"(x));
    return __uint_as_float(u);
}
__device__ __forceinline__ unsigned f2tf32u(float x)
{
    unsigned u;
    asm("cvt.rna.tf32.f32 %0, %1;" : "=r"(u) : "f"(x));
    return u;
}

__device__ __forceinline__ void mma_tf32(float* d, const uint4& a, const uint2& b)
{
    asm volatile(
        "mma.sync.aligned.m16n8k8.row.col.f32.tf32.tf32.f32 "
        "{%0,%1,%2,%3}, {%4,%5,%6,%7}, {%8,%9}, {%0,%1,%2,%3};\n"
        : "+f"(d[0]), "+f"(d[1]), "+f"(d[2]), "+f"(d[3])
        : "r"(a.x), "r"(a.y), "r"(a.z), "r"(a.w), "r"(b.x), "r"(b.y));
}

__device__ __forceinline__ void cp_async16(uint32_t smem_byte, const void* g)
{
    asm volatile("cp.async.cg.shared.global [%0], [%1], 16;\n"
                 :: "r"(smem_byte), "l"(g));
}
#define CP_COMMIT() asm volatile("cp.async.commit_group;\n" ::: "memory")
#define CP_WAIT0()  asm volatile("cp.async.wait_group 0;\n" ::: "memory")

// ---------------------------------------------------------------------------
// Fragment-layout address helpers (bijections validated R3..R7).
// ---------------------------------------------------------------------------
__device__ __forceinline__ size_t afrag_xt(int m, int k)   // xt/att: [mblk64][ks64][8][128]
{
    return (size_t)(m >> 7) * 65536 + (size_t)(k >> 3) * 1024
         + ((m & 127) >> 4) * 128 + (m & 7) * 16
         + ((k >> 2) & 1) * 2 + ((m >> 3) & 1) + (k & 3) * 4;
}
__device__ __forceinline__ size_t bfrag_w(int k, int n)    // W: [nblk8][ks64][512]
{
    return (size_t)(n >> 6) * 32768 + (size_t)(k >> 3) * 512
         + ((n & 63) >> 3) * 64 + (((n & 7) * 4 + (k & 3)) * 2) + ((k >> 2) & 1);
}
__device__ __forceinline__ size_t qfrag(int bh, int s, int d)  // Q: [bh][sblk8][ks8][8][128]
{
    return (size_t)bh * 65536 + (size_t)(s >> 7) * 8192 + (size_t)(d >> 3) * 1024
         + ((s & 127) >> 4) * 128 + (s & 7) * 16
         + ((d >> 2) & 1) * 2 + ((s >> 3) & 1) + (d & 3) * 4;
}
// K for 64-key tiles: [bh][ktile16][ks8][512]
__device__ __forceinline__ size_t kfrag64(int bh, int s, int d)
{
    return (size_t)bh * 65536 + (size_t)(s >> 6) * 4096 + (size_t)(d >> 3) * 512
         + ((s & 63) >> 3) * 64 + (((s & 7) * 4 + (d & 3)) * 2) + ((d >> 2) & 1);
}
// V for 64-key tiles: [bh][ktile16][vks8][8][64]
__device__ __forceinline__ size_t vfrag64(int bh, int s, int d)
{
    return (size_t)bh * 65536 + (size_t)(s >> 6) * 4096 + ((size_t)((s & 63) >> 3)) * 512
         + (d >> 3) * 64 + (((d & 7) * 4 + (s & 3)) * 2) + ((s >> 2) & 1);
}

// ---------------------------------------------------------------------------
// Kernel: transpose + PE -> xt hi/lo in A-frag global layout
// ---------------------------------------------------------------------------
__global__ void k_transpose_pe(const float* __restrict__ x,
                               const float* __restrict__ pos_w,
                               const float* __restrict__ pos_b,
                               float* __restrict__ xt_hi,
                               float* __restrict__ xt_lo)
{
    __shared__ float tile[32][33];
    const int e0 = blockIdx.x * 32;
    const int s0 = blockIdx.y * 32;
    const int b  = blockIdx.z;
    const int tx = threadIdx.x;
    const int ty = threadIdx.y;

#pragma unroll
    for (int i = 0; i < 4; i++) {
        int el = ty + i * 8;
        tile[el][tx] = x[((size_t)(b * EMB + e0 + el)) * SEQ + s0 + tx];
    }
    __syncthreads();

    const int e = e0 + tx;
    const float pw0 = pos_w[e];
    const float pw1 = pos_w[EMB + e];
    const float pb  = pos_b[e];
#pragma unroll
    for (int i = 0; i < 4; i++) {
        int sl = ty + i * 8;
        int s  = s0 + sl;
        float row = (float)(s >> 5);
        float col = (float)(s & 31);
        float v = tile[tx][sl] + row * pw0 + col * pw1 + pb;
        size_t idx = afrag_xt(b * SEQ + s, e);
        float hi = f2tf32f(v);
        xt_hi[idx] = hi;
        xt_lo[idx] = f2tf32f(v - hi);
    }
}

// ---------------------------------------------------------------------------
// Kernel: split all 4 weight matrices into hi/lo B-frag layout, one launch.
// ---------------------------------------------------------------------------
__global__ void k_split4(const float* __restrict__ w0, const float* __restrict__ w1,
                         const float* __restrict__ w2, const float* __restrict__ w3,
                         float* __restrict__ base_hi_lo)
{
    const float* src;
    switch (blockIdx.y) {
        case 0: src = w0; break;
        case 1: src = w1; break;
        case 2: src = w2; break;
        default: src = w3; break;
    }
    float* hi = base_hi_lo + (size_t)blockIdx.y * 2 * WPLANE;
    float* lo = hi + WPLANE;
    int i = blockIdx.x * 256 + threadIdx.x;
    int k = i >> 9, n = i & 511;
    float v = src[i];
    float h = f2tf32f(v);
    size_t idx = bfrag_w(k, n);
    hi[idx] = h;
    lo[idx] = f2tf32f(v - h);
}

// ---------------------------------------------------------------------------
// Kernel: 3xTF32 GEMM. BM=128 BN=64 BK=32, cp.async double-buffered.
// mode: 0=Q(qfrag,hi/lo) 1=K(kfrag64) 2=V(vfrag64) 3=final out[b,E,32,32]
// ---------------------------------------------------------------------------
#define G_STAGE 12288
#define G_SMEMB (2 * G_STAGE * 4)   // 98304 bytes

__global__ __launch_bounds__(256) void k_gemm(
    const float* __restrict__ A_hi, const float* __restrict__ A_lo,
    const float* __restrict__ W_hi, const float* __restrict__ W_lo,
    const float* __restrict__ bias,
    float* __restrict__ out_hi, float* __restrict__ out_lo,
    int mode, float oscale)
{
    extern __shared__ float sg[];
    uint32_t sbase = (uint32_t)__cvta_generic_to_shared(sg);

    const int tid  = threadIdx.x;
    const int lane = tid & 31;
    const int w    = tid >> 5;
    const int wm   = w >> 1;
    const int wn   = w & 1;
    const int mblk = blockIdx.y;
    const int nblk = blockIdx.x;
    const int m0   = mblk * 128;
    const int n0   = nblk * 64;

#define G_ISSUE(it, st)                                                        \
    {                                                                          \
        uint32_t sb = sbase + (st) * 49152;                                    \
        size_t asrc = (size_t)mblk * 65536 + (size_t)(it) * 4096;              \
        size_t bsrc = (size_t)nblk * 32768 + (size_t)(it) * 2048;              \
        _Pragma("unroll")                                                      \
        for (int p = 0; p < 4; p++) {                                          \
            int u = p * 256 + tid;                                             \
            cp_async16(sb + u * 16,         A_hi + asrc + u * 4);              \
            cp_async16(sb + 16384 + u * 16, A_lo + asrc + u * 4);              \
        }                                                                      \
        _Pragma("unroll")                                                      \
        for (int p = 0; p < 2; p++) {                                          \
            int u = p * 256 + tid;                                             \
            cp_async16(sb + 32768 + u * 16, W_hi + bsrc + u * 4);              \
            cp_async16(sb + 40960 + u * 16, W_lo + bsrc + u * 4);              \
        }                                                                      \
        CP_COMMIT();                                                           \
    }

    float acc[2][4][4];
#pragma unroll
    for (int i = 0; i < 2; i++)
#pragma unroll
        for (int j = 0; j < 4; j++)
#pragma unroll
            for (int r = 0; r < 4; r++) acc[i][j][r] = 0.0f;

    G_ISSUE(0, 0);

    for (int it = 0; it < 16; ++it) {
        CP_WAIT0();
        __syncthreads();
        if (it < 15) G_ISSUE(it + 1, (it + 1) & 1);

        const float* S = sg + (it & 1) * G_STAGE;
#pragma unroll
        for (int ks = 0; ks < 4; ks++) {
            uint4 ah[2], al[2];
            uint2 bh[4], bl[4];
#pragma unroll
            for (int i = 0; i < 2; i++) {
                int off = ks * 1024 + (wm * 2 + i) * 128 + lane * 4;
                ah[i] = *(const uint4*)&S[off];
                al[i] = *(const uint4*)&S[4096 + off];
            }
#pragma unroll
            for (int j = 0; j < 4; j++) {
                int off = 8192 + ks * 512 + (wn * 4 + j) * 64 + lane * 2;
                bh[j] = *(const uint2*)&S[off];
                bl[j] = *(const uint2*)&S[2048 + off];
            }
#pragma unroll
            for (int i = 0; i < 2; i++)
#pragma unroll
                for (int j = 0; j < 4; j++) {
                    mma_tf32(acc[i][j], ah[i], bl[j]);
                    mma_tf32(acc[i][j], al[i], bh[j]);
                    mma_tf32(acc[i][j], ah[i], bh[j]);
                }
        }
        if (it < 15) __syncthreads();
    }

    const int g = lane >> 2;
    const int t = lane & 3;
#pragma unroll
    for (int i = 0; i < 2; i++) {
#pragma unroll
        for (int j = 0; j < 4; j++) {
#pragma unroll
            for (int r = 0; r < 4; r++) {
                int m = m0 + wm * 32 + i * 16 + g + (r >> 1) * 8;
                int n = n0 + wn * 32 + j * 8 + 2 * t + (r & 1);
                float v = (acc[i][j][r] + bias[n]) * oscale;
                int b = m >> 10;
                int s = m & 1023;
                if (mode == 3) {
                    out_hi[((size_t)(b * EMB + n)) * SEQ + s] = v;
                } else {
                    int h = n >> 6, d = n & 63;
                    int bh = b * NH + h;
                    size_t idx;
                    if (mode == 0)      idx = qfrag(bh, s, d);
                    else if (mode == 1) idx = kfrag64(bh, s, d);
                    else                idx = vfrag64(bh, s, d);
                    float hi = f2tf32f(v);
                    out_hi[idx] = hi;
                    out_lo[idx] = f2tf32f(v - hi);
                }
            }
        }
    }
}
#undef G_ISSUE

// ---------------------------------------------------------------------------
// Kernel: mma flash attention v2. BM=128 q rows, 64-key tiles (16), 512 thr.
// Q_hi in registers, Q_lo in smem. K/V double-buffered identity cp.async.
// Local-base softmax: p = exp(s - local_half_rowmax); PV applies per-
// (row,half) correction exp(b_h - m_new). Running stats (m_run, l_run) are
// kept in REGISTERS, redundantly per warp (both d-half warps of an m-tile
// compute them identically from smem SMAX/SSUM) -> no cross-warp stat race,
// exactly 2 __syncthreads per tile.
// smem floats: QL 0(8192) | KV 8192 (2 bufs x 16384: KH+0 KL+4096 VH+8192
//   VL+12288) | PS 40960(128*66=8448) SMAX 49408(256) SSUM 49664(256)
//   total 49920 floats = 199680 B
// ---------------------------------------------------------------------------
#define F_QL   0
#define F_KV   8192
#define F_PS   40960
#define F_SMAX 49408
#define F_SSUM 49664
#define F_SMEMB (49920 * 4)

__global__ __launch_bounds__(512) void k_flash_mma(
    const float* __restrict__ q_hi, const float* __restrict__ q_lo,
    const float* __restrict__ k_hi, const float* __restrict__ k_lo,
    const float* __restrict__ v_hi, const float* __restrict__ v_lo,
    float* __restrict__ att_hi, float* __restrict__ att_lo)
{
    extern __shared__ float sm[];
    uint32_t sbase = (uint32_t)__cvta_generic_to_shared(sm);

    const int tid  = threadIdx.x;
    const int lane = tid & 31;
    const int w    = tid >> 5;
    const int bh   = blockIdx.y;
    const int q0   = blockIdx.x * 128;
    const size_t qbase = (size_t)bh * 65536 + (size_t)(q0 >> 7) * 8192;
    const size_t kvb   = (size_t)bh * 65536;

    // prologue copies: Q_lo (2048 x16B) + KV tile 0 (4 planes x 1024 x16B)
#pragma unroll
    for (int p = 0; p < 4; p++) {
        int u = p * 512 + tid;
        cp_async16(sbase + u * 16, q_lo + qbase + u * 4);
    }
    {
        uint32_t db = sbase + 32768;   // F_KV bytes
#pragma unroll
        for (int p = 0; p < 2; p++) {
            int u = p * 512 + tid;
            cp_async16(db + u * 16,         k_hi + kvb + u * 4);
            cp_async16(db + 16384 + u * 16, k_lo + kvb + u * 4);
            cp_async16(db + 32768 + u * 16, v_hi + kvb + u * 4);
            cp_async16(db + 49152 + u * 16, v_lo + kvb + u * 4);
        }
    }
    CP_COMMIT();

    const int wm = w & 7, wn = w >> 3;   // QK: m-tile, key half
    const int nh = w >> 3;               // PV: d half
    const int t = lane & 3;
    const int qrow = lane >> 2;

    const int rA = wm * 16 + qrow, rB = rA + 8;   // rows for QK and PV

    // Q_hi fragments in registers (direct frag-layout LDG)
    uint4 qh[8];
#pragma unroll
    for (int ks = 0; ks < 8; ks++)
        qh[ks] = *(const uint4*)&q_hi[qbase + ks * 1024 + wm * 128 + lane * 4];

    // running stats in registers (redundant across t lanes and nh halves)
    float m_runA = -1e30f, m_runB = -1e30f;
    float l_runA = 0.0f,   l_runB = 0.0f;

    float o[4][4];
#pragma unroll
    for (int j = 0; j < 4; j++)
#pragma unroll
        for (int r = 0; r < 4; r++) o[j][r] = 0.0f;

    for (int ti = 0; ti < 16; ++ti) {
        CP_WAIT0();
        __syncthreads();    // syncA: tile ti ready; prev PV done with PS/SMAX/SSUM

        if (ti < 15) {
            size_t src = kvb + (size_t)(ti + 1) * 4096;
            uint32_t db = sbase + 32768 + (((ti + 1) & 1) ? 65536u : 0u);
#pragma unroll
            for (int p = 0; p < 2; p++) {
                int u = p * 512 + tid;
                cp_async16(db + u * 16,         k_hi + src + u * 4);
                cp_async16(db + 16384 + u * 16, k_lo + src + u * 4);
                cp_async16(db + 32768 + u * 16, v_hi + src + u * 4);
                cp_async16(db + 49152 + u * 16, v_lo + src + u * 4);
            }
            CP_COMMIT();
        }
        const float* KV = sm + F_KV + (ti & 1) * 16384;

        // ---- QK^T mma (3xTF32), keys wn*32 .. wn*32+31 ----
        float sacc[4][4];
#pragma unroll
        for (int j = 0; j < 4; j++)
#pragma unroll
            for (int r = 0; r < 4; r++) sacc[j][r] = 0.0f;

#pragma unroll
        for (int ks = 0; ks < 8; ks++) {
            uint4 al = *(const uint4*)&sm[F_QL + ks * 1024 + wm * 128 + lane * 4];
            uint4 ah = qh[ks];
#pragma unroll
            for (int j = 0; j < 4; j++) {
                int jj = wn * 4 + j;
                int boff = ks * 512 + jj * 64 + lane * 2;
                uint2 bhf = *(const uint2*)&KV[boff];
                uint2 blf = *(const uint2*)&KV[4096 + boff];
                mma_tf32(sacc[j], ah, blf);
                mma_tf32(sacc[j], al, bhf);
                mma_tf32(sacc[j], ah, bhf);
            }
        }

        // ---- local-base softmax (own half only; no cross-half wait) ----
        float mA = sacc[0][0], mB = sacc[0][2];
#pragma unroll
        for (int j = 0; j < 4; j++) {
            mA = fmaxf(mA, fmaxf(sacc[j][0], sacc[j][1]));
            mB = fmaxf(mB, fmaxf(sacc[j][2], sacc[j][3]));
        }
        mA = fmaxf(mA, __shfl_xor_sync(FULLMASK, mA, 1));
        mA = fmaxf(mA, __shfl_xor_sync(FULLMASK, mA, 2));
        mB = fmaxf(mB, __shfl_xor_sync(FULLMASK, mB, 1));
        mB = fmaxf(mB, __shfl_xor_sync(FULLMASK, mB, 2));

        float p[4][4];
        float sA = 0.0f, sB = 0.0f;
#pragma unroll
        for (int j = 0; j < 4; j++) {
            p[j][0] = __expf(sacc[j][0] - mA);
            p[j][1] = __expf(sacc[j][1] - mA);
            p[j][2] = __expf(sacc[j][2] - mB);
            p[j][3] = __expf(sacc[j][3] - mB);
            sA += p[j][0] + p[j][1];
            sB += p[j][2] + p[j][3];
        }
        sA += __shfl_xor_sync(FULLMASK, sA, 1);
        sA += __shfl_xor_sync(FULLMASK, sA, 2);
        sB += __shfl_xor_sync(FULLMASK, sB, 1);
        sB += __shfl_xor_sync(FULLMASK, sB, 2);
        if (t == 0) {
            sm[F_SMAX + wn * 128 + rA] = mA;
            sm[F_SMAX + wn * 128 + rB] = mB;
            sm[F_SSUM + wn * 128 + rA] = sA;
            sm[F_SSUM + wn * 128 + rB] = sB;
        }
#pragma unroll
        for (int j = 0; j < 4; j++) {
            int c = wn * 32 + j * 8 + 2 * t;
            *(float2*)&sm[F_PS + rA * 66 + c] = make_float2(p[j][0], p[j][1]);
            *(float2*)&sm[F_PS + rB * 66 + c] = make_float2(p[j][2], p[j][3]);
        }
        __syncthreads();    // syncB: P, SMAX, SSUM visible

        // ---- PV (3xTF32) with per-(row,half) correction; stats in regs ----
        float bA0 = sm[F_SMAX + rA], bA1 = sm[F_SMAX + 128 + rA];
        float bB0 = sm[F_SMAX + rB], bB1 = sm[F_SMAX + 128 + rB];
        float ssA0 = sm[F_SSUM + rA], ssA1 = sm[F_SSUM + 128 + rA];
        float ssB0 = sm[F_SSUM + rB], ssB1 = sm[F_SSUM + 128 + rB];
        float mnA = fmaxf(m_runA, fmaxf(bA0, bA1));
        float mnB = fmaxf(m_runB, fmaxf(bB0, bB1));
        float alA = __expf(m_runA - mnA), alB = __expf(m_runB - mnB);
        float cA0 = __expf(bA0 - mnA), cA1 = __expf(bA1 - mnA);
        float cB0 = __expf(bB0 - mnB), cB1 = __expf(bB1 - mnB);
        l_runA = l_runA * alA + cA0 * ssA0 + cA1 * ssA1;
        l_runB = l_runB * alB + cB0 * ssB0 + cB1 * ssB1;
        m_runA = mnA;
        m_runB = mnB;
#pragma unroll
        for (int j = 0; j < 4; j++) {
            o[j][0] *= alA; o[j][1] *= alA;
            o[j][2] *= alB; o[j][3] *= alB;
        }
#pragma unroll
        for (int ks = 0; ks < 8; ks++) {
            float cA = (ks < 4) ? cA0 : cA1;
            float cB = (ks < 4) ? cB0 : cB1;
            float p0 = sm[F_PS + rA * 66 + ks * 8 + t]     * cA;
            float p1 = sm[F_PS + rB * 66 + ks * 8 + t]     * cB;
            float p2 = sm[F_PS + rA * 66 + ks * 8 + t + 4] * cA;
            float p3 = sm[F_PS + rB * 66 + ks * 8 + t + 4] * cB;
            uint4 ah, al;
            ah.x = f2tf32u(p0); al.x = f2tf32u(p0 - __uint_as_float(ah.x));
            ah.y = f2tf32u(p1); al.y = f2tf32u(p1 - __uint_as_float(ah.y));
            ah.z = f2tf32u(p2); al.z = f2tf32u(p2 - __uint_as_float(ah.z));
            ah.w = f2tf32u(p3); al.w = f2tf32u(p3 - __uint_as_float(ah.w));
#pragma unroll
            for (int jl = 0; jl < 4; jl++) {
                int j = nh * 4 + jl;
                int boff = ks * 512 + j * 64 + lane * 2;
                uint2 bhf = *(const uint2*)&KV[8192 + boff];
                uint2 blf = *(const uint2*)&KV[12288 + boff];
                mma_tf32(o[jl], ah, blf);
                mma_tf32(o[jl], al, bhf);
                mma_tf32(o[jl], ah, bhf);
            }
        }
    }

    // ---- epilogue: o /= l, hi/lo split, att in A-frag layout ----
    const float invA = 1.0f / l_runA;
    const float invB = 1.0f / l_runB;
    const int b = bh >> 3, h = bh & 7;
    const int mA_g = b * SEQ + q0 + rA;
    const int mB_g = b * SEQ + q0 + rB;
#pragma unroll
    for (int jl = 0; jl < 4; jl++) {
#pragma unroll
        for (int rr = 0; rr < 2; rr++) {
            int e = h * HD + nh * 32 + jl * 8 + 2 * t + rr;
            float vA = o[jl][rr]     * invA;
            float vB = o[jl][rr + 2] * invB;
            float hA = f2tf32f(vA), hB = f2tf32f(vB);
            size_t iA = afrag_xt(mA_g, e);
            size_t iB = afrag_xt(mB_g, e);
            att_hi[iA] = hA;  att_lo[iA] = f2tf32f(vA - hA);
            att_hi[iB] = hB;  att_lo[iB] = f2tf32f(vB - hB);
        }
    }
}

// ---------------------------------------------------------------------------
extern "C" void kernel_launch(void* const* d_in, const int* in_sizes, int n_in,
                              void* d_out, int out_size)
{
    const float* x     = (const float*)d_in[0];
    const float* pos_w = (const float*)d_in[1];
    const float* pos_b = (const float*)d_in[2];
    const float* wq    = (const float*)d_in[3];
    const float* bq    = (const float*)d_in[4];
    const float* wk    = (const float*)d_in[5];
    const float* bk    = (const float*)d_in[6];
    const float* wv    = (const float*)d_in[7];
    const float* bv    = (const float*)d_in[8];
    const float* wo    = (const float*)d_in[9];
    const float* bo    = (const float*)d_in[10];
    float* out = (float*)d_out;

    void* sp = nullptr;
    cudaGetSymbolAddress(&sp, g_scratch);
    float* base   = (float*)sp;
    float* xt_hi  = base;
    float* xt_lo  = xt_hi + PLANE;
    float* q_hi   = xt_lo + PLANE;
    float* q_lo   = q_hi  + PLANE;
    float* k_hi   = q_lo  + PLANE;
    float* k_lo   = k_hi  + PLANE;
    float* v_hi   = k_lo  + PLANE;
    float* v_lo   = v_hi  + PLANE;
    float* att_hi = v_lo  + PLANE;
    float* att_lo = att_hi + PLANE;
    float* wsp    = att_lo + PLANE;
    float* wq_hi = wsp;              float* wq_lo = wq_hi + WPLANE;
    float* wk_hi = wq_lo + WPLANE;   float* wk_lo = wk_hi + WPLANE;
    float* wv_hi = wk_lo + WPLANE;   float* wv_lo = wv_hi + WPLANE;
    float* wo_hi = wv_lo + WPLANE;   float* wo_lo = wo_hi + WPLANE;

    cudaFuncSetAttribute(k_gemm, cudaFuncAttributeMaxDynamicSharedMemorySize, G_SMEMB);
    cudaFuncSetAttribute(k_flash_mma, cudaFuncAttributeMaxDynamicSharedMemorySize, F_SMEMB);

    {
        dim3 grid(EMB / 32, SEQ / 32, BATCH);
        dim3 block(32, 8);
        k_transpose_pe<<<grid, block>>>(x, pos_w, pos_b, xt_hi, xt_lo);
    }
    {
        dim3 grid((unsigned)(WPLANE / 256), 4);
        k_split4<<<grid, 256>>>(wq, wk, wv, wo, wsp);
    }
    {
        dim3 grid(EMB / 64, MTOT / 128);
        k_gemm<<<grid, 256, G_SMEMB>>>(xt_hi, xt_lo, wq_hi, wq_lo, bq, q_hi, q_lo, 0, 0.125f);
        k_gemm<<<grid, 256, G_SMEMB>>>(xt_hi, xt_lo, wk_hi, wk_lo, bk, k_hi, k_lo, 1, 1.0f);
        k_gemm<<<grid, 256, G_SMEMB>>>(xt_hi, xt_lo, wv_hi, wv_lo, bv, v_hi, v_lo, 2, 1.0f);
    }
    {
        dim3 grid(SEQ / 128, BATCH * NH);
        k_flash_mma<<<grid, 512, F_SMEMB>>>(q_hi, q_lo, k_hi, k_lo, v_hi, v_lo,
                                            att_hi, att_lo);
    }
    {
        dim3 grid(EMB / 64, MTOT / 128);
        k_gemm<<<grid, 256, G_SMEMB>>>(att_hi, att_lo, wo_hi, wo_lo, bo, out, out, 3, 1.0f);
    }
}

// round 10
// speedup vs baseline: 2.0522x; 1.0000x over previous
#include <cuda_runtime.h>
#include <cstdint>

// ---------------------------------------------------------------------------
// SelfAttentionWithPE: B=8, E=512, H=W=32 (S=1024), heads=8, head_dim=64, fp32
// 3xTF32 (hi/lo) mma.sync.m16n8k8 everywhere. All operands stored in gmem in
// FRAGMENT-PERMUTED layouts so hot-loop smem fills are identity cp.async.
// Flash: 64-key tiles, 2 syncs/tile, local-base softmax, register stats.
// R10: pass-major mma ordering (no dependent mma triples), non-volatile mma.
// ---------------------------------------------------------------------------

#define BATCH 8
#define EMB   512
#define SEQ   1024
#define NH    8
#define HD    64
#define MTOT  (BATCH * SEQ)
#define FULLMASK 0xffffffffu

#define PLANE   ((size_t)MTOT * EMB)        // 4,194,304 floats
#define WPLANE  ((size_t)EMB * EMB)         // 262,144
__device__ float g_scratch[10 * 4194304 + 8 * 262144];

__device__ __forceinline__ float f2tf32f(float x)
{
    unsigned u;
    asm("cvt.rna.tf32.f32 %0, %1;" : "=r"(u) : "f"(x));
    return __uint_as_float(u);
}
__device__ __forceinline__ unsigned f2tf32u(float x)
{
    unsigned u;
    asm("cvt.rna.tf32.f32 %0, %1;" : "=r"(u) : "f"(x));
    return u;
}

// NOTE: non-volatile — register-only effects; lets ptxas schedule freely.
__device__ __forceinline__ void mma_tf32(float* d, const uint4& a, const uint2& b)
{
    asm("mma.sync.aligned.m16n8k8.row.col.f32.tf32.tf32.f32 "
        "{%0,%1,%2,%3}, {%4,%5,%6,%7}, {%8,%9}, {%0,%1,%2,%3};\n"
        : "+f"(d[0]), "+f"(d[1]), "+f"(d[2]), "+f"(d[3])
        : "r"(a.x), "r"(a.y), "r"(a.z), "r"(a.w), "r"(b.x), "r"(b.y));
}

__device__ __forceinline__ void cp_async16(uint32_t smem_byte, const void* g)
{
    asm volatile("cp.async.cg.shared.global [%0], [%1], 16;\n"
                 :: "r"(smem_byte), "l"(g));
}
#define CP_COMMIT() asm volatile("cp.async.commit_group;\n" ::: "memory")
#define CP_WAIT0()  asm volatile("cp.async.wait_group 0;\n" ::: "memory")

// ---------------------------------------------------------------------------
// Fragment-layout address helpers (bijections validated R3..R9).
// ---------------------------------------------------------------------------
__device__ __forceinline__ size_t afrag_xt(int m, int k)   // xt/att: [mblk64][ks64][8][128]
{
    return (size_t)(m >> 7) * 65536 + (size_t)(k >> 3) * 1024
         + ((m & 127) >> 4) * 128 + (m & 7) * 16
         + ((k >> 2) & 1) * 2 + ((m >> 3) & 1) + (k & 3) * 4;
}
__device__ __forceinline__ size_t bfrag_w(int k, int n)    // W: [nblk8][ks64][512]
{
    return (size_t)(n >> 6) * 32768 + (size_t)(k >> 3) * 512
         + ((n & 63) >> 3) * 64 + (((n & 7) * 4 + (k & 3)) * 2) + ((k >> 2) & 1);
}
__device__ __forceinline__ size_t qfrag(int bh, int s, int d)  // Q: [bh][sblk8][ks8][8][128]
{
    return (size_t)bh * 65536 + (size_t)(s >> 7) * 8192 + (size_t)(d >> 3) * 1024
         + ((s & 127) >> 4) * 128 + (s & 7) * 16
         + ((d >> 2) & 1) * 2 + ((s >> 3) & 1) + (d & 3) * 4;
}
// K for 64-key tiles: [bh][ktile16][ks8][512]
__device__ __forceinline__ size_t kfrag64(int bh, int s, int d)
{
    return (size_t)bh * 65536 + (size_t)(s >> 6) * 4096 + (size_t)(d >> 3) * 512
         + ((s & 63) >> 3) * 64 + (((s & 7) * 4 + (d & 3)) * 2) + ((d >> 2) & 1);
}
// V for 64-key tiles: [bh][ktile16][vks8][8][64]
__device__ __forceinline__ size_t vfrag64(int bh, int s, int d)
{
    return (size_t)bh * 65536 + (size_t)(s >> 6) * 4096 + ((size_t)((s & 63) >> 3)) * 512
         + (d >> 3) * 64 + (((d & 7) * 4 + (s & 3)) * 2) + ((s >> 2) & 1);
}

// ---------------------------------------------------------------------------
// Kernel: transpose + PE -> xt hi/lo in A-frag global layout
// ---------------------------------------------------------------------------
__global__ void k_transpose_pe(const float* __restrict__ x,
                               const float* __restrict__ pos_w,
                               const float* __restrict__ pos_b,
                               float* __restrict__ xt_hi,
                               float* __restrict__ xt_lo)
{
    __shared__ float tile[32][33];
    const int e0 = blockIdx.x * 32;
    const int s0 = blockIdx.y * 32;
    const int b  = blockIdx.z;
    const int tx = threadIdx.x;
    const int ty = threadIdx.y;

#pragma unroll
    for (int i = 0; i < 4; i++) {
        int el = ty + i * 8;
        tile[el][tx] = x[((size_t)(b * EMB + e0 + el)) * SEQ + s0 + tx];
    }
    __syncthreads();

    const int e = e0 + tx;
    const float pw0 = pos_w[e];
    const float pw1 = pos_w[EMB + e];
    const float pb  = pos_b[e];
#pragma unroll
    for (int i = 0; i < 4; i++) {
        int sl = ty + i * 8;
        int s  = s0 + sl;
        float row = (float)(s >> 5);
        float col = (float)(s & 31);
        float v = tile[tx][sl] + row * pw0 + col * pw1 + pb;
        size_t idx = afrag_xt(b * SEQ + s, e);
        float hi = f2tf32f(v);
        xt_hi[idx] = hi;
        xt_lo[idx] = f2tf32f(v - hi);
    }
}

// ---------------------------------------------------------------------------
// Kernel: split all 4 weight matrices into hi/lo B-frag layout, one launch.
// ---------------------------------------------------------------------------
__global__ void k_split4(const float* __restrict__ w0, const float* __restrict__ w1,
                         const float* __restrict__ w2, const float* __restrict__ w3,
                         float* __restrict__ base_hi_lo)
{
    const float* src;
    switch (blockIdx.y) {
        case 0: src = w0; break;
        case 1: src = w1; break;
        case 2: src = w2; break;
        default: src = w3; break;
    }
    float* hi = base_hi_lo + (size_t)blockIdx.y * 2 * WPLANE;
    float* lo = hi + WPLANE;
    int i = blockIdx.x * 256 + threadIdx.x;
    int k = i >> 9, n = i & 511;
    float v = src[i];
    float h = f2tf32f(v);
    size_t idx = bfrag_w(k, n);
    hi[idx] = h;
    lo[idx] = f2tf32f(v - h);
}

// ---------------------------------------------------------------------------
// Kernel: 3xTF32 GEMM. BM=128 BN=64 BK=32, cp.async double-buffered.
// Pass-major mma ordering: 3 passes (hl, lh, hh) x 8 independent accs.
// mode: 0=Q(qfrag,hi/lo) 1=K(kfrag64) 2=V(vfrag64) 3=final out[b,E,32,32]
// ---------------------------------------------------------------------------
#define G_STAGE 12288
#define G_SMEMB (2 * G_STAGE * 4)   // 98304 bytes

__global__ __launch_bounds__(256) void k_gemm(
    const float* __restrict__ A_hi, const float* __restrict__ A_lo,
    const float* __restrict__ W_hi, const float* __restrict__ W_lo,
    const float* __restrict__ bias,
    float* __restrict__ out_hi, float* __restrict__ out_lo,
    int mode, float oscale)
{
    extern __shared__ float sg[];
    uint32_t sbase = (uint32_t)__cvta_generic_to_shared(sg);

    const int tid  = threadIdx.x;
    const int lane = tid & 31;
    const int w    = tid >> 5;
    const int wm   = w >> 1;
    const int wn   = w & 1;
    const int mblk = blockIdx.y;
    const int nblk = blockIdx.x;
    const int m0   = mblk * 128;
    const int n0   = nblk * 64;

#define G_ISSUE(it, st)                                                        \
    {                                                                          \
        uint32_t sb = sbase + (st) * 49152;                                    \
        size_t asrc = (size_t)mblk * 65536 + (size_t)(it) * 4096;              \
        size_t bsrc = (size_t)nblk * 32768 + (size_t)(it) * 2048;              \
        _Pragma("unroll")                                                      \
        for (int p = 0; p < 4; p++) {                                          \
            int u = p * 256 + tid;                                             \
            cp_async16(sb + u * 16,         A_hi + asrc + u * 4);              \
            cp_async16(sb + 16384 + u * 16, A_lo + asrc + u * 4);              \
        }                                                                      \
        _Pragma("unroll")                                                      \
        for (int p = 0; p < 2; p++) {                                          \
            int u = p * 256 + tid;                                             \
            cp_async16(sb + 32768 + u * 16, W_hi + bsrc + u * 4);              \
            cp_async16(sb + 40960 + u * 16, W_lo + bsrc + u * 4);              \
        }                                                                      \
        CP_COMMIT();                                                           \
    }

    float acc[2][4][4];
#pragma unroll
    for (int i = 0; i < 2; i++)
#pragma unroll
        for (int j = 0; j < 4; j++)
#pragma unroll
            for (int r = 0; r < 4; r++) acc[i][j][r] = 0.0f;

    G_ISSUE(0, 0);

    for (int it = 0; it < 16; ++it) {
        CP_WAIT0();
        __syncthreads();
        if (it < 15) G_ISSUE(it + 1, (it + 1) & 1);

        const float* S = sg + (it & 1) * G_STAGE;
#pragma unroll
        for (int ks = 0; ks < 4; ks++) {
            uint4 ah[2], al[2];
            uint2 bh[4], bl[4];
#pragma unroll
            for (int i = 0; i < 2; i++) {
                int off = ks * 1024 + (wm * 2 + i) * 128 + lane * 4;
                ah[i] = *(const uint4*)&S[off];
                al[i] = *(const uint4*)&S[4096 + off];
            }
#pragma unroll
            for (int j = 0; j < 4; j++) {
                int off = 8192 + ks * 512 + (wn * 4 + j) * 64 + lane * 2;
                bh[j] = *(const uint2*)&S[off];
                bl[j] = *(const uint2*)&S[2048 + off];
            }
            // pass-major: per-acc term order stays hl, lh, hh (bitwise same),
            // but 8 independent mmas sit between accumulator reuses.
#pragma unroll
            for (int i = 0; i < 2; i++)
#pragma unroll
                for (int j = 0; j < 4; j++)
                    mma_tf32(acc[i][j], ah[i], bl[j]);
#pragma unroll
            for (int i = 0; i < 2; i++)
#pragma unroll
                for (int j = 0; j < 4; j++)
                    mma_tf32(acc[i][j], al[i], bh[j]);
#pragma unroll
            for (int i = 0; i < 2; i++)
#pragma unroll
                for (int j = 0; j < 4; j++)
                    mma_tf32(acc[i][j], ah[i], bh[j]);
        }
        if (it < 15) __syncthreads();
    }

    const int g = lane >> 2;
    const int t = lane & 3;
#pragma unroll
    for (int i = 0; i < 2; i++) {
#pragma unroll
        for (int j = 0; j < 4; j++) {
#pragma unroll
            for (int r = 0; r < 4; r++) {
                int m = m0 + wm * 32 + i * 16 + g + (r >> 1) * 8;
                int n = n0 + wn * 32 + j * 8 + 2 * t + (r & 1);
                float v = (acc[i][j][r] + bias[n]) * oscale;
                int b = m >> 10;
                int s = m & 1023;
                if (mode == 3) {
                    out_hi[((size_t)(b * EMB + n)) * SEQ + s] = v;
                } else {
                    int h = n >> 6, d = n & 63;
                    int bh = b * NH + h;
                    size_t idx;
                    if (mode == 0)      idx = qfrag(bh, s, d);
                    else if (mode == 1) idx = kfrag64(bh, s, d);
                    else                idx = vfrag64(bh, s, d);
                    float hi = f2tf32f(v);
                    out_hi[idx] = hi;
                    out_lo[idx] = f2tf32f(v - hi);
                }
            }
        }
    }
}
#undef G_ISSUE

// ---------------------------------------------------------------------------
// Kernel: mma flash attention v2. BM=128 q rows, 64-key tiles (16), 512 thr.
// Q_hi in registers, Q_lo in smem. K/V double-buffered identity cp.async.
// Local-base softmax; running stats in registers (redundant per warp).
// Pass-major mma ordering in QK and PV. Exactly 2 __syncthreads per tile.
// smem floats: QL 0(8192) | KV 8192 (2 bufs x 16384: KH+0 KL+4096 VH+8192
//   VL+12288) | PS 40960(128*66=8448) SMAX 49408(256) SSUM 49664(256)
//   total 49920 floats = 199680 B
// ---------------------------------------------------------------------------
#define F_QL   0
#define F_KV   8192
#define F_PS   40960
#define F_SMAX 49408
#define F_SSUM 49664
#define F_SMEMB (49920 * 4)

__global__ __launch_bounds__(512) void k_flash_mma(
    const float* __restrict__ q_hi, const float* __restrict__ q_lo,
    const float* __restrict__ k_hi, const float* __restrict__ k_lo,
    const float* __restrict__ v_hi, const float* __restrict__ v_lo,
    float* __restrict__ att_hi, float* __restrict__ att_lo)
{
    extern __shared__ float sm[];
    uint32_t sbase = (uint32_t)__cvta_generic_to_shared(sm);

    const int tid  = threadIdx.x;
    const int lane = tid & 31;
    const int w    = tid >> 5;
    const int bh   = blockIdx.y;
    const int q0   = blockIdx.x * 128;
    const size_t qbase = (size_t)bh * 65536 + (size_t)(q0 >> 7) * 8192;
    const size_t kvb   = (size_t)bh * 65536;

    // prologue copies: Q_lo (2048 x16B) + KV tile 0 (4 planes x 1024 x16B)
#pragma unroll
    for (int p = 0; p < 4; p++) {
        int u = p * 512 + tid;
        cp_async16(sbase + u * 16, q_lo + qbase + u * 4);
    }
    {
        uint32_t db = sbase + 32768;   // F_KV bytes
#pragma unroll
        for (int p = 0; p < 2; p++) {
            int u = p * 512 + tid;
            cp_async16(db + u * 16,         k_hi + kvb + u * 4);
            cp_async16(db + 16384 + u * 16, k_lo + kvb + u * 4);
            cp_async16(db + 32768 + u * 16, v_hi + kvb + u * 4);
            cp_async16(db + 49152 + u * 16, v_lo + kvb + u * 4);
        }
    }
    CP_COMMIT();

    const int wm = w & 7, wn = w >> 3;   // QK: m-tile, key half
    const int nh = w >> 3;               // PV: d half
    const int t = lane & 3;
    const int qrow = lane >> 2;

    const int rA = wm * 16 + qrow, rB = rA + 8;   // rows for QK and PV

    // Q_hi fragments in registers (direct frag-layout LDG)
    uint4 qh[8];
#pragma unroll
    for (int ks = 0; ks < 8; ks++)
        qh[ks] = *(const uint4*)&q_hi[qbase + ks * 1024 + wm * 128 + lane * 4];

    // running stats in registers (redundant across t lanes and nh halves)
    float m_runA = -1e30f, m_runB = -1e30f;
    float l_runA = 0.0f,   l_runB = 0.0f;

    float o[4][4];
#pragma unroll
    for (int j = 0; j < 4; j++)
#pragma unroll
        for (int r = 0; r < 4; r++) o[j][r] = 0.0f;

    for (int ti = 0; ti < 16; ++ti) {
        CP_WAIT0();
        __syncthreads();    // syncA: tile ti ready; prev PV done with PS/SMAX/SSUM

        if (ti < 15) {
            size_t src = kvb + (size_t)(ti + 1) * 4096;
            uint32_t db = sbase + 32768 + (((ti + 1) & 1) ? 65536u : 0u);
#pragma unroll
            for (int p = 0; p < 2; p++) {
                int u = p * 512 + tid;
                cp_async16(db + u * 16,         k_hi + src + u * 4);
                cp_async16(db + 16384 + u * 16, k_lo + src + u * 4);
                cp_async16(db + 32768 + u * 16, v_hi + src + u * 4);
                cp_async16(db + 49152 + u * 16, v_lo + src + u * 4);
            }
            CP_COMMIT();
        }
        const float* KV = sm + F_KV + (ti & 1) * 16384;

        // ---- QK^T mma (3xTF32, pass-major), keys wn*32 .. wn*32+31 ----
        float sacc[4][4];
#pragma unroll
        for (int j = 0; j < 4; j++)
#pragma unroll
            for (int r = 0; r < 4; r++) sacc[j][r] = 0.0f;

#pragma unroll
        for (int ks = 0; ks < 8; ks++) {
            uint4 al = *(const uint4*)&sm[F_QL + ks * 1024 + wm * 128 + lane * 4];
            uint4 ah = qh[ks];
            uint2 bhf[4], blf[4];
#pragma unroll
            for (int j = 0; j < 4; j++) {
                int boff = ks * 512 + (wn * 4 + j) * 64 + lane * 2;
                bhf[j] = *(const uint2*)&KV[boff];
                blf[j] = *(const uint2*)&KV[4096 + boff];
            }
#pragma unroll
            for (int j = 0; j < 4; j++) mma_tf32(sacc[j], ah, blf[j]);
#pragma unroll
            for (int j = 0; j < 4; j++) mma_tf32(sacc[j], al, bhf[j]);
#pragma unroll
            for (int j = 0; j < 4; j++) mma_tf32(sacc[j], ah, bhf[j]);
        }

        // ---- local-base softmax (own half only; no cross-half wait) ----
        float mA = sacc[0][0], mB = sacc[0][2];
#pragma unroll
        for (int j = 0; j < 4; j++) {
            mA = fmaxf(mA, fmaxf(sacc[j][0], sacc[j][1]));
            mB = fmaxf(mB, fmaxf(sacc[j][2], sacc[j][3]));
        }
        mA = fmaxf(mA, __shfl_xor_sync(FULLMASK, mA, 1));
        mA = fmaxf(mA, __shfl_xor_sync(FULLMASK, mA, 2));
        mB = fmaxf(mB, __shfl_xor_sync(FULLMASK, mB, 1));
        mB = fmaxf(mB, __shfl_xor_sync(FULLMASK, mB, 2));

        float p[4][4];
        float sA = 0.0f, sB = 0.0f;
#pragma unroll
        for (int j = 0; j < 4; j++) {
            p[j][0] = __expf(sacc[j][0] - mA);
            p[j][1] = __expf(sacc[j][1] - mA);
            p[j][2] = __expf(sacc[j][2] - mB);
            p[j][3] = __expf(sacc[j][3] - mB);
            sA += p[j][0] + p[j][1];
            sB += p[j][2] + p[j][3];
        }
        sA += __shfl_xor_sync(FULLMASK, sA, 1);
        sA += __shfl_xor_sync(FULLMASK, sA, 2);
        sB += __shfl_xor_sync(FULLMASK, sB, 1);
        sB += __shfl_xor_sync(FULLMASK, sB, 2);
        if (t == 0) {
            sm[F_SMAX + wn * 128 + rA] = mA;
            sm[F_SMAX + wn * 128 + rB] = mB;
            sm[F_SSUM + wn * 128 + rA] = sA;
            sm[F_SSUM + wn * 128 + rB] = sB;
        }
#pragma unroll
        for (int j = 0; j < 4; j++) {
            int c = wn * 32 + j * 8 + 2 * t;
            *(float2*)&sm[F_PS + rA * 66 + c] = make_float2(p[j][0], p[j][1]);
            *(float2*)&sm[F_PS + rB * 66 + c] = make_float2(p[j][2], p[j][3]);
        }
        __syncthreads();    // syncB: P, SMAX, SSUM visible

        // ---- PV (3xTF32, pass-major) with per-(row,half) correction ----
        float bA0 = sm[F_SMAX + rA], bA1 = sm[F_SMAX + 128 + rA];
        float bB0 = sm[F_SMAX + rB], bB1 = sm[F_SMAX + 128 + rB];
        float ssA0 = sm[F_SSUM + rA], ssA1 = sm[F_SSUM + 128 + rA];
        float ssB0 = sm[F_SSUM + rB], ssB1 = sm[F_SSUM + 128 + rB];
        float mnA = fmaxf(m_runA, fmaxf(bA0, bA1));
        float mnB = fmaxf(m_runB, fmaxf(bB0, bB1));
        float alA = __expf(m_runA - mnA), alB = __expf(m_runB - mnB);
        float cA0 = __expf(bA0 - mnA), cA1 = __expf(bA1 - mnA);
        float cB0 = __expf(bB0 - mnB), cB1 = __expf(bB1 - mnB);
        l_runA = l_runA * alA + cA0 * ssA0 + cA1 * ssA1;
        l_runB = l_runB * alB + cB0 * ssB0 + cB1 * ssB1;
        m_runA = mnA;
        m_runB = mnB;
#pragma unroll
        for (int j = 0; j < 4; j++) {
            o[j][0] *= alA; o[j][1] *= alA;
            o[j][2] *= alB; o[j][3] *= alB;
        }
#pragma unroll
        for (int ks = 0; ks < 8; ks++) {
            float cA = (ks < 4) ? cA0 : cA1;
            float cB = (ks < 4) ? cB0 : cB1;
            float p0 = sm[F_PS + rA * 66 + ks * 8 + t]     * cA;
            float p1 = sm[F_PS + rB * 66 + ks * 8 + t]     * cB;
            float p2 = sm[F_PS + rA * 66 + ks * 8 + t + 4] * cA;
            float p3 = sm[F_PS + rB * 66 + ks * 8 + t + 4] * cB;
            uint4 ah, al;
            ah.x = f2tf32u(p0); al.x = f2tf32u(p0 - __uint_as_float(ah.x));
            ah.y = f2tf32u(p1); al.y = f2tf32u(p1 - __uint_as_float(ah.y));
            ah.z = f2tf32u(p2); al.z = f2tf32u(p2 - __uint_as_float(ah.z));
            ah.w = f2tf32u(p3); al.w = f2tf32u(p3 - __uint_as_float(ah.w));
            uint2 bhf[4], blf[4];
#pragma unroll
            for (int jl = 0; jl < 4; jl++) {
                int boff = ks * 512 + (nh * 4 + jl) * 64 + lane * 2;
                bhf[jl] = *(const uint2*)&KV[8192 + boff];
                blf[jl] = *(const uint2*)&KV[12288 + boff];
            }
#pragma unroll
            for (int jl = 0; jl < 4; jl++) mma_tf32(o[jl], ah, blf[jl]);
#pragma unroll
            for (int jl = 0; jl < 4; jl++) mma_tf32(o[jl], al, bhf[jl]);
#pragma unroll
            for (int jl = 0; jl < 4; jl++) mma_tf32(o[jl], ah, bhf[jl]);
        }
    }

    // ---- epilogue: o /= l, hi/lo split, att in A-frag layout ----
    const float invA = 1.0f / l_runA;
    const float invB = 1.0f / l_runB;
    const int b = bh >> 3, h = bh & 7;
    const int mA_g = b * SEQ + q0 + rA;
    const int mB_g = b * SEQ + q0 + rB;
#pragma unroll
    for (int jl = 0; jl < 4; jl++) {
#pragma unroll
        for (int rr = 0; rr < 2; rr++) {
            int e = h * HD + nh * 32 + jl * 8 + 2 * t + rr;
            float vA = o[jl][rr]     * invA;
            float vB = o[jl][rr + 2] * invB;
            float hA = f2tf32f(vA), hB = f2tf32f(vB);
            size_t iA = afrag_xt(mA_g, e);
            size_t iB = afrag_xt(mB_g, e);
            att_hi[iA] = hA;  att_lo[iA] = f2tf32f(vA - hA);
            att_hi[iB] = hB;  att_lo[iB] = f2tf32f(vB - hB);
        }
    }
}

// ---------------------------------------------------------------------------
extern "C" void kernel_launch(void* const* d_in, const int* in_sizes, int n_in,
                              void* d_out, int out_size)
{
    const float* x     = (const float*)d_in[0];
    const float* pos_w = (const float*)d_in[1];
    const float* pos_b = (const float*)d_in[2];
    const float* wq    = (const float*)d_in[3];
    const float* bq    = (const float*)d_in[4];
    const float* wk    = (const float*)d_in[5];
    const float* bk    = (const float*)d_in[6];
    const float* wv    = (const float*)d_in[7];
    const float* bv    = (const float*)d_in[8];
    const float* wo    = (const float*)d_in[9];
    const float* bo    = (const float*)d_in[10];
    float* out = (float*)d_out;

    void* sp = nullptr;
    cudaGetSymbolAddress(&sp, g_scratch);
    float* base   = (float*)sp;
    float* xt_hi  = base;
    float* xt_lo  = xt_hi + PLANE;
    float* q_hi   = xt_lo + PLANE;
    float* q_lo   = q_hi  + PLANE;
    float* k_hi   = q_lo  + PLANE;
    float* k_lo   = k_hi  + PLANE;
    float* v_hi   = k_lo  + PLANE;
    float* v_lo   = v_hi  + PLANE;
    float* att_hi = v_lo  + PLANE;
    float* att_lo = att_hi + PLANE;
    float* wsp    = att_lo + PLANE;
    float* wq_hi = wsp;              float* wq_lo = wq_hi + WPLANE;
    float* wk_hi = wq_lo + WPLANE;   float* wk_lo = wk_hi + WPLANE;
    float* wv_hi = wk_lo + WPLANE;   float* wv_lo = wv_hi + WPLANE;
    float* wo_hi = wv_lo + WPLANE;   float* wo_lo = wo_hi + WPLANE;

    cudaFuncSetAttribute(k_gemm, cudaFuncAttributeMaxDynamicSharedMemorySize, G_SMEMB);
    cudaFuncSetAttribute(k_flash_mma, cudaFuncAttributeMaxDynamicSharedMemorySize, F_SMEMB);

    {
        dim3 grid(EMB / 32, SEQ / 32, BATCH);
        dim3 block(32, 8);
        k_transpose_pe<<<grid, block>>>(x, pos_w, pos_b, xt_hi, xt_lo);
    }
    {
        dim3 grid((unsigned)(WPLANE / 256), 4);
        k_split4<<<grid, 256>>>(wq, wk, wv, wo, wsp);
    }
    {
        dim3 grid(EMB / 64, MTOT / 128);
        k_gemm<<<grid, 256, G_SMEMB>>>(xt_hi, xt_lo, wq_hi, wq_lo, bq, q_hi, q_lo, 0, 0.125f);
        k_gemm<<<grid, 256, G_SMEMB>>>(xt_hi, xt_lo, wk_hi, wk_lo, bk, k_hi, k_lo, 1, 1.0f);
        k_gemm<<<grid, 256, G_SMEMB>>>(xt_hi, xt_lo, wv_hi, wv_lo, bv, v_hi, v_lo, 2, 1.0f);
    }
    {
        dim3 grid(SEQ / 128, BATCH * NH);
        k_flash_mma<<<grid, 512, F_SMEMB>>>(q_hi, q_lo, k_hi, k_lo, v_hi, v_lo,
                                            att_hi, att_lo);
    }
    {
        dim3 grid(EMB / 64, MTOT / 128);
        k_gemm<<<grid, 256, G_SMEMB>>>(att_hi, att_lo, wo_hi, wo_lo, bo, out, out, 3, 1.0f);
    }
}

// round 12
// speedup vs baseline: 2.1553x; 1.0503x over previous
#include <cuda_runtime.h>
#include <cstdint>

// ---------------------------------------------------------------------------
// SelfAttentionWithPE: B=8, E=512, H=W=32 (S=1024), heads=8, head_dim=64, fp32
// 3xTF32 (hi/lo) mma.sync.m16n8k8 everywhere. All operands stored in gmem in
// FRAGMENT-PERMUTED layouts so hot-loop smem fills are identity cp.async.
// R12 (= R11 resubmit): GEMM BK16 (3 blocks/SM), flash BM=64 (2 blocks/SM).
// ---------------------------------------------------------------------------

#define BATCH 8
#define EMB   512
#define SEQ   1024
#define NH    8
#define HD    64
#define MTOT  (BATCH * SEQ)
#define FULLMASK 0xffffffffu

#define PLANE   ((size_t)MTOT * EMB)        // 4,194,304 floats
#define WPLANE  ((size_t)EMB * EMB)         // 262,144
__device__ float g_scratch[10 * 4194304 + 8 * 262144];

__device__ __forceinline__ float f2tf32f(float x)
{
    unsigned u;
    asm("cvt.rna.tf32.f32 %0, %1;" : "=r"(u) : "f"(x));
    return __uint_as_float(u);
}
__device__ __forceinline__ unsigned f2tf32u(float x)
{
    unsigned u;
    asm("cvt.rna.tf32.f32 %0, %1;" : "=r"(u) : "f"(x));
    return u;
}

__device__ __forceinline__ void mma_tf32(float* d, const uint4& a, const uint2& b)
{
    asm("mma.sync.aligned.m16n8k8.row.col.f32.tf32.tf32.f32 "
        "{%0,%1,%2,%3}, {%4,%5,%6,%7}, {%8,%9}, {%0,%1,%2,%3};\n"
        : "+f"(d[0]), "+f"(d[1]), "+f"(d[2]), "+f"(d[3])
        : "r"(a.x), "r"(a.y), "r"(a.z), "r"(a.w), "r"(b.x), "r"(b.y));
}

__device__ __forceinline__ void cp_async16(uint32_t smem_byte, const void* g)
{
    asm volatile("cp.async.cg.shared.global [%0], [%1], 16;\n"
                 :: "r"(smem_byte), "l"(g));
}
#define CP_COMMIT() asm volatile("cp.async.commit_group;\n" ::: "memory")
#define CP_WAIT0()  asm volatile("cp.async.wait_group 0;\n" ::: "memory")

// ---------------------------------------------------------------------------
// Fragment-layout address helpers.
// afrag/bfrag/qfrag validated R3..R10; kfrag/vfrag (32-key) validated R7.
// ---------------------------------------------------------------------------
__device__ __forceinline__ size_t afrag_xt(int m, int k)   // xt/att: [mblk64][ks64][8][128]
{
    return (size_t)(m >> 7) * 65536 + (size_t)(k >> 3) * 1024
         + ((m & 127) >> 4) * 128 + (m & 7) * 16
         + ((k >> 2) & 1) * 2 + ((m >> 3) & 1) + (k & 3) * 4;
}
__device__ __forceinline__ size_t bfrag_w(int k, int n)    // W: [nblk8][ks64][512]
{
    return (size_t)(n >> 6) * 32768 + (size_t)(k >> 3) * 512
         + ((n & 63) >> 3) * 64 + (((n & 7) * 4 + (k & 3)) * 2) + ((k >> 2) & 1);
}
__device__ __forceinline__ size_t qfrag(int bh, int s, int d)  // Q: [bh][sblk8][ks8][8][128]
{
    return (size_t)bh * 65536 + (size_t)(s >> 7) * 8192 + (size_t)(d >> 3) * 1024
         + ((s & 127) >> 4) * 128 + (s & 7) * 16
         + ((d >> 2) & 1) * 2 + ((s >> 3) & 1) + (d & 3) * 4;
}
__device__ __forceinline__ size_t kfrag(int bh, int s, int d)  // K: [bh][ktile32][ks8][256]
{
    return (size_t)bh * 65536 + (size_t)(s >> 5) * 2048 + (size_t)(d >> 3) * 256
         + ((s & 31) >> 3) * 64 + (((s & 7) * 4 + (d & 3)) * 2) + ((d >> 2) & 1);
}
__device__ __forceinline__ size_t vfrag(int bh, int s, int d)  // V: [bh][ktile32][vks4][8][64]
{
    return (size_t)bh * 65536 + (size_t)(s >> 5) * 2048 + ((size_t)((s & 31) >> 3)) * 512
         + (d >> 3) * 64 + (((d & 7) * 4 + (s & 3)) * 2) + ((s >> 2) & 1);
}

// ---------------------------------------------------------------------------
// Kernel: transpose + PE -> xt hi/lo in A-frag global layout
// ---------------------------------------------------------------------------
__global__ void k_transpose_pe(const float* __restrict__ x,
                               const float* __restrict__ pos_w,
                               const float* __restrict__ pos_b,
                               float* __restrict__ xt_hi,
                               float* __restrict__ xt_lo)
{
    __shared__ float tile[32][33];
    const int e0 = blockIdx.x * 32;
    const int s0 = blockIdx.y * 32;
    const int b  = blockIdx.z;
    const int tx = threadIdx.x;
    const int ty = threadIdx.y;

#pragma unroll
    for (int i = 0; i < 4; i++) {
        int el = ty + i * 8;
        tile[el][tx] = x[((size_t)(b * EMB + e0 + el)) * SEQ + s0 + tx];
    }
    __syncthreads();

    const int e = e0 + tx;
    const float pw0 = pos_w[e];
    const float pw1 = pos_w[EMB + e];
    const float pb  = pos_b[e];
#pragma unroll
    for (int i = 0; i < 4; i++) {
        int sl = ty + i * 8;
        int s  = s0 + sl;
        float row = (float)(s >> 5);
        float col = (float)(s & 31);
        float v = tile[tx][sl] + row * pw0 + col * pw1 + pb;
        size_t idx = afrag_xt(b * SEQ + s, e);
        float hi = f2tf32f(v);
        xt_hi[idx] = hi;
        xt_lo[idx] = f2tf32f(v - hi);
    }
}

// ---------------------------------------------------------------------------
// Kernel: split all 4 weight matrices into hi/lo B-frag layout, one launch.
// ---------------------------------------------------------------------------
__global__ void k_split4(const float* __restrict__ w0, const float* __restrict__ w1,
                         const float* __restrict__ w2, const float* __restrict__ w3,
                         float* __restrict__ base_hi_lo)
{
    const float* src;
    switch (blockIdx.y) {
        case 0: src = w0; break;
        case 1: src = w1; break;
        case 2: src = w2; break;
        default: src = w3; break;
    }
    float* hi = base_hi_lo + (size_t)blockIdx.y * 2 * WPLANE;
    float* lo = hi + WPLANE;
    int i = blockIdx.x * 256 + threadIdx.x;
    int k = i >> 9, n = i & 511;
    float v = src[i];
    float h = f2tf32f(v);
    size_t idx = bfrag_w(k, n);
    hi[idx] = h;
    lo[idx] = f2tf32f(v - h);
}

// ---------------------------------------------------------------------------
// Kernel: 3xTF32 GEMM. BM=128 BN=64 BK=16, cp.async double-buffered.
// Stage (floats): [A_hi 2048][A_lo 2048][B_hi 1024][B_lo 1024] = 6144
// (24576 B; 2 stages = 49152 B -> 3 blocks/SM).
// mode: 0=Q(qfrag) 1=K(kfrag) 2=V(vfrag) 3=final out[b,E,32,32]
// ---------------------------------------------------------------------------
#define G_STAGE 6144
#define G_SMEMB (2 * G_STAGE * 4)   // 49152 bytes

__global__ __launch_bounds__(256, 3) void k_gemm(
    const float* __restrict__ A_hi, const float* __restrict__ A_lo,
    const float* __restrict__ W_hi, const float* __restrict__ W_lo,
    const float* __restrict__ bias,
    float* __restrict__ out_hi, float* __restrict__ out_lo,
    int mode, float oscale)
{
    extern __shared__ float sg[];
    uint32_t sbase = (uint32_t)__cvta_generic_to_shared(sg);

    const int tid  = threadIdx.x;
    const int lane = tid & 31;
    const int w    = tid >> 5;
    const int wm   = w >> 1;
    const int wn   = w & 1;
    const int mblk = blockIdx.y;
    const int nblk = blockIdx.x;
    const int m0   = mblk * 128;
    const int n0   = nblk * 64;

#define G_ISSUE(it, st)                                                        \
    {                                                                          \
        uint32_t sb = sbase + (st) * 24576;                                    \
        size_t asrc = (size_t)mblk * 65536 + (size_t)(it) * 2048;              \
        size_t bsrc = (size_t)nblk * 32768 + (size_t)(it) * 1024;              \
        _Pragma("unroll")                                                      \
        for (int p = 0; p < 2; p++) {                                          \
            int u = p * 256 + tid;                                             \
            cp_async16(sb + u * 16,        A_hi + asrc + u * 4);               \
            cp_async16(sb + 8192 + u * 16, A_lo + asrc + u * 4);               \
        }                                                                      \
        cp_async16(sb + 16384 + tid * 16, W_hi + bsrc + tid * 4);              \
        cp_async16(sb + 20480 + tid * 16, W_lo + bsrc + tid * 4);              \
        CP_COMMIT();                                                           \
    }

    float acc[2][4][4];
#pragma unroll
    for (int i = 0; i < 2; i++)
#pragma unroll
        for (int j = 0; j < 4; j++)
#pragma unroll
            for (int r = 0; r < 4; r++) acc[i][j][r] = 0.0f;

    G_ISSUE(0, 0);

    for (int it = 0; it < 32; ++it) {
        CP_WAIT0();
        __syncthreads();
        if (it < 31) G_ISSUE(it + 1, (it + 1) & 1);

        const float* S = sg + (it & 1) * G_STAGE;
#pragma unroll
        for (int ks = 0; ks < 2; ks++) {
            uint4 ah[2], al[2];
            uint2 bh[4], bl[4];
#pragma unroll
            for (int i = 0; i < 2; i++) {
                int off = ks * 1024 + (wm * 2 + i) * 128 + lane * 4;
                ah[i] = *(const uint4*)&S[off];
                al[i] = *(const uint4*)&S[2048 + off];
            }
#pragma unroll
            for (int j = 0; j < 4; j++) {
                int off = 4096 + ks * 512 + (wn * 4 + j) * 64 + lane * 2;
                bh[j] = *(const uint2*)&S[off];
                bl[j] = *(const uint2*)&S[1024 + off];
            }
#pragma unroll
            for (int i = 0; i < 2; i++)
#pragma unroll
                for (int j = 0; j < 4; j++)
                    mma_tf32(acc[i][j], ah[i], bl[j]);
#pragma unroll
            for (int i = 0; i < 2; i++)
#pragma unroll
                for (int j = 0; j < 4; j++)
                    mma_tf32(acc[i][j], al[i], bh[j]);
#pragma unroll
            for (int i = 0; i < 2; i++)
#pragma unroll
                for (int j = 0; j < 4; j++)
                    mma_tf32(acc[i][j], ah[i], bh[j]);
        }
        if (it < 31) __syncthreads();
    }

    const int g = lane >> 2;
    const int t = lane & 3;
#pragma unroll
    for (int i = 0; i < 2; i++) {
#pragma unroll
        for (int j = 0; j < 4; j++) {
#pragma unroll
            for (int r = 0; r < 4; r++) {
                int m = m0 + wm * 32 + i * 16 + g + (r >> 1) * 8;
                int n = n0 + wn * 32 + j * 8 + 2 * t + (r & 1);
                float v = (acc[i][j][r] + bias[n]) * oscale;
                int b = m >> 10;
                int s = m & 1023;
                if (mode == 3) {
                    out_hi[((size_t)(b * EMB + n)) * SEQ + s] = v;
                } else {
                    int h = n >> 6, d = n & 63;
                    int bh = b * NH + h;
                    size_t idx;
                    if (mode == 0)      idx = qfrag(bh, s, d);
                    else if (mode == 1) idx = kfrag(bh, s, d);
                    else                idx = vfrag(bh, s, d);
                    float hi = f2tf32f(v);
                    out_hi[idx] = hi;
                    out_lo[idx] = f2tf32f(v - hi);
                }
            }
        }
    }
}
#undef G_ISSUE

// ---------------------------------------------------------------------------
// Kernel: mma flash attention v3. BM=64 q rows, 32-key tiles (32), 256 thr,
// 2 blocks/SM. Q_hi in registers, Q_lo in smem. K/V double-buffered identity
// cp.async. Local-base softmax (16-key halves), register running stats,
// 2 syncs/tile. QK warps: wm=w&3 m-tile, wn=w>>2 key half (16 keys).
// PV warps: w&3 m-tile, nh=w>>2 d half (n8 tiles nh*4+jl).
// smem floats: QL 0(4096) | KV 4096 (2 bufs x 8192: KH+0 KL+2048 VH+4096
//   VL+6144) | PS 20480(64*34=2176) SMAX 22656(128) SSUM 22784(128)
//   total 22912 floats = 91648 B
// ---------------------------------------------------------------------------
#define F_QL   0
#define F_KV   4096
#define F_PS   20480
#define F_SMAX 22656
#define F_SSUM 22784
#define F_SMEMB (22912 * 4)

__global__ __launch_bounds__(256, 2) void k_flash_mma(
    const float* __restrict__ q_hi, const float* __restrict__ q_lo,
    const float* __restrict__ k_hi, const float* __restrict__ k_lo,
    const float* __restrict__ v_hi, const float* __restrict__ v_lo,
    float* __restrict__ att_hi, float* __restrict__ att_lo)
{
    extern __shared__ float sm[];
    uint32_t sbase = (uint32_t)__cvta_generic_to_shared(sm);

    const int tid  = threadIdx.x;
    const int lane = tid & 31;
    const int w    = tid >> 5;
    const int bh   = blockIdx.y;
    const int q0   = blockIdx.x * 64;
    const size_t qbase = (size_t)bh * 65536 + (size_t)(q0 >> 7) * 8192;
    const int mtb   = ((q0 & 127) >> 4);        // m-tile base within 128-row blk
    const size_t kvb = (size_t)bh * 65536;

    // prologue: Q_lo (rows q0..q0+63 of the 128-row block) + KV tile 0
#pragma unroll
    for (int p = 0; p < 4; p++) {
        int u = p * 256 + tid;          // 0..1023 units of 16B
        int ks = u >> 7, rem = u & 127;
        cp_async16(sbase + (ks * 512 + rem * 4) * 4,
                   q_lo + qbase + ks * 1024 + mtb * 128 + rem * 4);
    }
    {
        uint32_t db = sbase + F_KV * 4;
#pragma unroll
        for (int p = 0; p < 2; p++) {
            int u = p * 256 + tid;      // 512 units per plane
            cp_async16(db + u * 16,         k_hi + kvb + u * 4);
            cp_async16(db + 8192 + u * 16,  k_lo + kvb + u * 4);
            cp_async16(db + 16384 + u * 16, v_hi + kvb + u * 4);
            cp_async16(db + 24576 + u * 16, v_lo + kvb + u * 4);
        }
    }
    CP_COMMIT();

    const int wm = w & 3, wn = w >> 2;   // QK: m-tile, 16-key half
    const int nh = w >> 2;               // PV: d half
    const int t = lane & 3;
    const int qrow = lane >> 2;

    const int rA = wm * 16 + qrow, rB = rA + 8;   // local rows 0..63

    // Q_hi fragments in registers (direct frag-layout LDG)
    uint4 qh[8];
#pragma unroll
    for (int ks = 0; ks < 8; ks++)
        qh[ks] = *(const uint4*)&q_hi[qbase + ks * 1024 + (mtb + wm) * 128 + lane * 4];

    float m_runA = -1e30f, m_runB = -1e30f;
    float l_runA = 0.0f,   l_runB = 0.0f;

    float o[4][4];
#pragma unroll
    for (int j = 0; j < 4; j++)
#pragma unroll
        for (int r = 0; r < 4; r++) o[j][r] = 0.0f;

    for (int ti = 0; ti < 32; ++ti) {
        CP_WAIT0();
        __syncthreads();    // syncA: tile ti ready; prev PV done with PS/SMAX/SSUM

        if (ti < 31) {
            size_t src = kvb + (size_t)(ti + 1) * 2048;
            uint32_t db = sbase + F_KV * 4 + (((ti + 1) & 1) ? 32768u : 0u);
#pragma unroll
            for (int p = 0; p < 2; p++) {
                int u = p * 256 + tid;
                cp_async16(db + u * 16,         k_hi + src + u * 4);
                cp_async16(db + 8192 + u * 16,  k_lo + src + u * 4);
                cp_async16(db + 16384 + u * 16, v_hi + src + u * 4);
                cp_async16(db + 24576 + u * 16, v_lo + src + u * 4);
            }
            CP_COMMIT();
        }
        const float* KV = sm + F_KV + (ti & 1) * 8192;

        // ---- QK^T mma (3xTF32, pass-major), keys wn*16 .. wn*16+15 ----
        float sacc[2][4];
#pragma unroll
        for (int j = 0; j < 2; j++)
#pragma unroll
            for (int r = 0; r < 4; r++) sacc[j][r] = 0.0f;

#pragma unroll
        for (int ks = 0; ks < 8; ks++) {
            uint4 al = *(const uint4*)&sm[F_QL + ks * 512 + wm * 128 + lane * 4];
            uint4 ah = qh[ks];
            uint2 bhf[2], blf[2];
#pragma unroll
            for (int j = 0; j < 2; j++) {
                int boff = ks * 256 + (wn * 2 + j) * 64 + lane * 2;
                bhf[j] = *(const uint2*)&KV[boff];
                blf[j] = *(const uint2*)&KV[2048 + boff];
            }
#pragma unroll
            for (int j = 0; j < 2; j++) mma_tf32(sacc[j], ah, blf[j]);
#pragma unroll
            for (int j = 0; j < 2; j++) mma_tf32(sacc[j], al, bhf[j]);
#pragma unroll
            for (int j = 0; j < 2; j++) mma_tf32(sacc[j], ah, bhf[j]);
        }

        // ---- local-base softmax (own 16-key half) ----
        float mA = fmaxf(fmaxf(sacc[0][0], sacc[0][1]), fmaxf(sacc[1][0], sacc[1][1]));
        float mB = fmaxf(fmaxf(sacc[0][2], sacc[0][3]), fmaxf(sacc[1][2], sacc[1][3]));
        mA = fmaxf(mA, __shfl_xor_sync(FULLMASK, mA, 1));
        mA = fmaxf(mA, __shfl_xor_sync(FULLMASK, mA, 2));
        mB = fmaxf(mB, __shfl_xor_sync(FULLMASK, mB, 1));
        mB = fmaxf(mB, __shfl_xor_sync(FULLMASK, mB, 2));

        float p[2][4];
        float sA = 0.0f, sB = 0.0f;
#pragma unroll
        for (int j = 0; j < 2; j++) {
            p[j][0] = __expf(sacc[j][0] - mA);
            p[j][1] = __expf(sacc[j][1] - mA);
            p[j][2] = __expf(sacc[j][2] - mB);
            p[j][3] = __expf(sacc[j][3] - mB);
            sA += p[j][0] + p[j][1];
            sB += p[j][2] + p[j][3];
        }
        sA += __shfl_xor_sync(FULLMASK, sA, 1);
        sA += __shfl_xor_sync(FULLMASK, sA, 2);
        sB += __shfl_xor_sync(FULLMASK, sB, 1);
        sB += __shfl_xor_sync(FULLMASK, sB, 2);
        if (t == 0) {
            sm[F_SMAX + wn * 64 + rA] = mA;
            sm[F_SMAX + wn * 64 + rB] = mB;
            sm[F_SSUM + wn * 64 + rA] = sA;
            sm[F_SSUM + wn * 64 + rB] = sB;
        }
#pragma unroll
        for (int j = 0; j < 2; j++) {
            int c = wn * 16 + j * 8 + 2 * t;
            *(float2*)&sm[F_PS + rA * 34 + c] = make_float2(p[j][0], p[j][1]);
            *(float2*)&sm[F_PS + rB * 34 + c] = make_float2(p[j][2], p[j][3]);
        }
        __syncthreads();    // syncB: P, SMAX, SSUM visible

        // ---- PV (3xTF32, pass-major) with per-(row,half) correction ----
        float bA0 = sm[F_SMAX + rA], bA1 = sm[F_SMAX + 64 + rA];
        float bB0 = sm[F_SMAX + rB], bB1 = sm[F_SMAX + 64 + rB];
        float ssA0 = sm[F_SSUM + rA], ssA1 = sm[F_SSUM + 64 + rA];
        float ssB0 = sm[F_SSUM + rB], ssB1 = sm[F_SSUM + 64 + rB];
        float mnA = fmaxf(m_runA, fmaxf(bA0, bA1));
        float mnB = fmaxf(m_runB, fmaxf(bB0, bB1));
        float alA = __expf(m_runA - mnA), alB = __expf(m_runB - mnB);
        float cA0 = __expf(bA0 - mnA), cA1 = __expf(bA1 - mnA);
        float cB0 = __expf(bB0 - mnB), cB1 = __expf(bB1 - mnB);
        l_runA = l_runA * alA + cA0 * ssA0 + cA1 * ssA1;
        l_runB = l_runB * alB + cB0 * ssB0 + cB1 * ssB1;
        m_runA = mnA;
        m_runB = mnB;
#pragma unroll
        for (int j = 0; j < 4; j++) {
            o[j][0] *= alA; o[j][1] *= alA;
            o[j][2] *= alB; o[j][3] *= alB;
        }
#pragma unroll
        for (int ks = 0; ks < 4; ks++) {     // key chunks of 8 (32 keys)
            float cA = (ks < 2) ? cA0 : cA1;
            float cB = (ks < 2) ? cB0 : cB1;
            float p0 = sm[F_PS + rA * 34 + ks * 8 + t]     * cA;
            float p1 = sm[F_PS + rB * 34 + ks * 8 + t]     * cB;
            float p2 = sm[F_PS + rA * 34 + ks * 8 + t + 4] * cA;
            float p3 = sm[F_PS + rB * 34 + ks * 8 + t + 4] * cB;
            uint4 ah, al;
            ah.x = f2tf32u(p0); al.x = f2tf32u(p0 - __uint_as_float(ah.x));
            ah.y = f2tf32u(p1); al.y = f2tf32u(p1 - __uint_as_float(ah.y));
            ah.z = f2tf32u(p2); al.z = f2tf32u(p2 - __uint_as_float(ah.z));
            ah.w = f2tf32u(p3); al.w = f2tf32u(p3 - __uint_as_float(ah.w));
            uint2 bhf[4], blf[4];
#pragma unroll
            for (int jl = 0; jl < 4; jl++) {
                int boff = ks * 512 + (nh * 4 + jl) * 64 + lane * 2;
                bhf[jl] = *(const uint2*)&KV[4096 + boff];
                blf[jl] = *(const uint2*)&KV[6144 + boff];
            }
#pragma unroll
            for (int jl = 0; jl < 4; jl++) mma_tf32(o[jl], ah, blf[jl]);
#pragma unroll
            for (int jl = 0; jl < 4; jl++) mma_tf32(o[jl], al, bhf[jl]);
#pragma unroll
            for (int jl = 0; jl < 4; jl++) mma_tf32(o[jl], ah, bhf[jl]);
        }
    }

    // ---- epilogue: o /= l, hi/lo split, att in A-frag layout ----
    const float invA = 1.0f / l_runA;
    const float invB = 1.0f / l_runB;
    const int b = bh >> 3, h = bh & 7;
    const int mA_g = b * SEQ + q0 + rA;
    const int mB_g = b * SEQ + q0 + rB;
#pragma unroll
    for (int jl = 0; jl < 4; jl++) {
#pragma unroll
        for (int rr = 0; rr < 2; rr++) {
            int e = h * HD + nh * 32 + jl * 8 + 2 * t + rr;
            float vA = o[jl][rr]     * invA;
            float vB = o[jl][rr + 2] * invB;
            float hA = f2tf32f(vA), hB = f2tf32f(vB);
            size_t iA = afrag_xt(mA_g, e);
            size_t iB = afrag_xt(mB_g, e);
            att_hi[iA] = hA;  att_lo[iA] = f2tf32f(vA - hA);
            att_hi[iB] = hB;  att_lo[iB] = f2tf32f(vB - hB);
        }
    }
}

// ---------------------------------------------------------------------------
extern "C" void kernel_launch(void* const* d_in, const int* in_sizes, int n_in,
                              void* d_out, int out_size)
{
    const float* x     = (const float*)d_in[0];
    const float* pos_w = (const float*)d_in[1];
    const float* pos_b = (const float*)d_in[2];
    const float* wq    = (const float*)d_in[3];
    const float* bq    = (const float*)d_in[4];
    const float* wk    = (const float*)d_in[5];
    const float* bk    = (const float*)d_in[6];
    const float* wv    = (const float*)d_in[7];
    const float* bv    = (const float*)d_in[8];
    const float* wo    = (const float*)d_in[9];
    const float* bo    = (const float*)d_in[10];
    float* out = (float*)d_out;

    void* sp = nullptr;
    cudaGetSymbolAddress(&sp, g_scratch);
    float* base   = (float*)sp;
    float* xt_hi  = base;
    float* xt_lo  = xt_hi + PLANE;
    float* q_hi   = xt_lo + PLANE;
    float* q_lo   = q_hi  + PLANE;
    float* k_hi   = q_lo  + PLANE;
    float* k_lo   = k_hi  + PLANE;
    float* v_hi   = k_lo  + PLANE;
    float* v_lo   = v_hi  + PLANE;
    float* att_hi = v_lo  + PLANE;
    float* att_lo = att_hi + PLANE;
    float* wsp    = att_lo + PLANE;
    float* wq_hi = wsp;              float* wq_lo = wq_hi + WPLANE;
    float* wk_hi = wq_lo + WPLANE;   float* wk_lo = wk_hi + WPLANE;
    float* wv_hi = wk_lo + WPLANE;   float* wv_lo = wv_hi + WPLANE;
    float* wo_hi = wv_lo + WPLANE;   float* wo_lo = wo_hi + WPLANE;

    cudaFuncSetAttribute(k_gemm, cudaFuncAttributeMaxDynamicSharedMemorySize, G_SMEMB);
    cudaFuncSetAttribute(k_flash_mma, cudaFuncAttributeMaxDynamicSharedMemorySize, F_SMEMB);

    {
        dim3 grid(EMB / 32, SEQ / 32, BATCH);
        dim3 block(32, 8);
        k_transpose_pe<<<grid, block>>>(x, pos_w, pos_b, xt_hi, xt_lo);
    }
    {
        dim3 grid((unsigned)(WPLANE / 256), 4);
        k_split4<<<grid, 256>>>(wq, wk, wv, wo, wsp);
    }
    {
        dim3 grid(EMB / 64, MTOT / 128);
        k_gemm<<<grid, 256, G_SMEMB>>>(xt_hi, xt_lo, wq_hi, wq_lo, bq, q_hi, q_lo, 0, 0.125f);
        k_gemm<<<grid, 256, G_SMEMB>>>(xt_hi, xt_lo, wk_hi, wk_lo, bk, k_hi, k_lo, 1, 1.0f);
        k_gemm<<<grid, 256, G_SMEMB>>>(xt_hi, xt_lo, wv_hi, wv_lo, bv, v_hi, v_lo, 2, 1.0f);
    }
    {
        dim3 grid(SEQ / 64, BATCH * NH);
        k_flash_mma<<<grid, 256, F_SMEMB>>>(q_hi, q_lo, k_hi, k_lo, v_hi, v_lo,
                                            att_hi, att_lo);
    }
    {
        dim3 grid(EMB / 64, MTOT / 128);
        k_gemm<<<grid, 256, G_SMEMB>>>(att_hi, att_lo, wo_hi, wo_lo, bo, out, out, 3, 1.0f);
    }
}

// round 15
// speedup vs baseline: 2.9967x; 1.3904x over previous
#include <cuda_runtime.h>
#include <cuda_bf16.h>
#include <cstdint>

// ---------------------------------------------------------------------------
// SelfAttentionWithPE: B=8, E=512, H=W=32 (S=1024), heads=8, head_dim=64, fp32
// R15 (= R13/R14 resubmit, audited): 3xBF16 (hi/lo) mma.sync.m16n8k16.
// All operands stored in gmem in FRAGMENT-PERMUTED bf16 layouts so hot-loop
// smem fills are identity cp.async. Flash: BM=64, 32-key tiles, local-base
// softmax, register running stats, 2 syncs/tile.
// ---------------------------------------------------------------------------

#define BATCH 8
#define EMB   512
#define SEQ   1024
#define NH    8
#define HD    64
#define MTOT  (BATCH * SEQ)
#define FULLMASK 0xffffffffu

#define PLANE   ((size_t)MTOT * EMB)        // 4,194,304 bf16 elems / plane
#define WPLANE  ((size_t)EMB * EMB)         // 262,144
__device__ float g_scratch[10 * 4194304 + 8 * 262144];

// ---------------------------------------------------------------------------
// bf16 helpers
// ---------------------------------------------------------------------------
__device__ __forceinline__ void split_bf16(float v, __nv_bfloat16& h, __nv_bfloat16& l)
{
    h = __float2bfloat16(v);
    l = __float2bfloat16(v - __bfloat162float(h));
}
// pack(even, odd): even -> lower 16 bits, odd -> upper 16 bits
__device__ __forceinline__ unsigned pack_bf16x2(float even, float odd)
{
    unsigned r;
    asm("cvt.rn.bf16x2.f32 %0, %1, %2;" : "=r"(r) : "f"(odd), "f"(even));
    return r;
}

__device__ __forceinline__ void mma_bf16(float* d, const uint4& a, const uint2& b)
{
    asm("mma.sync.aligned.m16n8k16.row.col.f32.bf16.bf16.f32 "
        "{%0,%1,%2,%3}, {%4,%5,%6,%7}, {%8,%9}, {%0,%1,%2,%3};\n"
        : "+f"(d[0]), "+f"(d[1]), "+f"(d[2]), "+f"(d[3])
        : "r"(a.x), "r"(a.y), "r"(a.z), "r"(a.w), "r"(b.x), "r"(b.y));
}

__device__ __forceinline__ void cp_async16(uint32_t smem_byte, const void* g)
{
    asm volatile("cp.async.cg.shared.global [%0], [%1], 16;\n"
                 :: "r"(smem_byte), "l"(g));
}
#define CP_COMMIT() asm volatile("cp.async.commit_group;\n" ::: "memory")
#define CP_WAIT0()  asm volatile("cp.async.wait_group 0;\n" ::: "memory")

// ---------------------------------------------------------------------------
// Fragment element-index helpers (bf16 element units) for m16n8k16 lane maps.
// A frag regs: a0=(g, k-lo pair) a1=(g+8, k-lo) a2=(g, k-hi) a3=(g+8, k-hi)
//   u32 index within lane block: kh*2 + mh; within-u32: k&1 (even = lower).
// B frag regs: b0=(k-lo pair, col g) b1=(k-hi pair, col g); index = kh.
// ---------------------------------------------------------------------------
__device__ __forceinline__ size_t afrag_e(int m, int k)    // xt/att: [mblk64][kc32][mt8][128u32]
{
    int mt = (m & 127) >> 4, ml = m & 15, mh = ml >> 3, g = ml & 7;
    int kl = k & 15, kq = kl >> 1, kh = kq >> 2, t = kq & 3;
    size_t u = (size_t)(m >> 7) * 32768 + (size_t)(k >> 4) * 1024
             + mt * 128 + (g * 4 + t) * 4 + kh * 2 + mh;
    return u * 2 + (kl & 1);
}
__device__ __forceinline__ size_t bfragw_e(int k, int n)   // W: [nblk8][kc32][nt8][64u32]
{
    int nt = (n & 63) >> 3, g = n & 7;
    int kq = (k & 15) >> 1, kh = kq >> 2, t = kq & 3;
    size_t u = (size_t)(n >> 6) * 16384 + (size_t)(k >> 4) * 512
             + nt * 64 + (g * 4 + t) * 2 + kh;
    return u * 2 + (k & 1);
}
__device__ __forceinline__ size_t qfrag_e(int bh, int s, int d)  // Q: [bh][sblk8][kc4][mt8][128u32]
{
    int mt = (s & 127) >> 4, ml = s & 15, mh = ml >> 3, g = ml & 7;
    int kq = (d & 15) >> 1, kh = kq >> 2, t = kq & 3;
    size_t u = (size_t)bh * 32768 + (size_t)(s >> 7) * 4096 + (d >> 4) * 1024
             + mt * 128 + (g * 4 + t) * 4 + kh * 2 + mh;
    return u * 2 + (d & 1);
}
__device__ __forceinline__ size_t kfrag_e(int bh, int s, int d)  // K: [bh][kt32][kc4][nt4][64u32]
{
    int kq = (d & 15) >> 1, kh = kq >> 2, t = kq & 3;
    size_t u = (size_t)bh * 32768 + (size_t)(s >> 5) * 1024 + (d >> 4) * 256
             + ((s & 31) >> 3) * 64 + ((s & 7) * 4 + t) * 2 + kh;
    return u * 2 + (d & 1);
}
__device__ __forceinline__ size_t vfrag_e(int bh, int s, int d)  // V: [bh][kt32][sc2][nt8][64u32]
{
    int kq = (s & 15) >> 1, kh = kq >> 2, t = kq & 3;
    size_t u = (size_t)bh * 32768 + (size_t)(s >> 5) * 1024 + ((s & 31) >> 4) * 512
             + (d >> 3) * 64 + ((d & 7) * 4 + t) * 2 + kh;
    return u * 2 + (s & 1);
}

// ---------------------------------------------------------------------------
// Kernel: transpose + PE -> xt hi/lo bf16 in A-frag global layout
// ---------------------------------------------------------------------------
__global__ void k_transpose_pe(const float* __restrict__ x,
                               const float* __restrict__ pos_w,
                               const float* __restrict__ pos_b,
                               __nv_bfloat16* __restrict__ xt_hi,
                               __nv_bfloat16* __restrict__ xt_lo)
{
    __shared__ float tile[32][33];
    const int e0 = blockIdx.x * 32;
    const int s0 = blockIdx.y * 32;
    const int b  = blockIdx.z;
    const int tx = threadIdx.x;
    const int ty = threadIdx.y;

#pragma unroll
    for (int i = 0; i < 4; i++) {
        int el = ty + i * 8;
        tile[el][tx] = x[((size_t)(b * EMB + e0 + el)) * SEQ + s0 + tx];
    }
    __syncthreads();

    const int e = e0 + tx;
    const float pw0 = pos_w[e];
    const float pw1 = pos_w[EMB + e];
    const float pb  = pos_b[e];
#pragma unroll
    for (int i = 0; i < 4; i++) {
        int sl = ty + i * 8;
        int s  = s0 + sl;
        float row = (float)(s >> 5);
        float col = (float)(s & 31);
        float v = tile[tx][sl] + row * pw0 + col * pw1 + pb;
        size_t idx = afrag_e(b * SEQ + s, e);
        __nv_bfloat16 h, l;
        split_bf16(v, h, l);
        xt_hi[idx] = h;
        xt_lo[idx] = l;
    }
}

// ---------------------------------------------------------------------------
// Kernel: split 4 weight matrices into hi/lo bf16 B-frag layout, one launch.
// ---------------------------------------------------------------------------
__global__ void k_split4(const float* __restrict__ w0, const float* __restrict__ w1,
                         const float* __restrict__ w2, const float* __restrict__ w3,
                         __nv_bfloat16* __restrict__ base_hi_lo)
{
    const float* src;
    switch (blockIdx.y) {
        case 0: src = w0; break;
        case 1: src = w1; break;
        case 2: src = w2; break;
        default: src = w3; break;
    }
    __nv_bfloat16* hi = base_hi_lo + (size_t)blockIdx.y * 2 * WPLANE;
    __nv_bfloat16* lo = hi + WPLANE;
    int i = blockIdx.x * 256 + threadIdx.x;
    int k = i >> 9, n = i & 511;
    float v = src[i];
    size_t idx = bfragw_e(k, n);
    __nv_bfloat16 h, l;
    split_bf16(v, h, l);
    hi[idx] = h;
    lo[idx] = l;
}

// ---------------------------------------------------------------------------
// Kernel: 3xBF16 GEMM. BM=128 BN=64 BK=32 (2 k16-chunks), cp.async double-buf.
// Stage (u32): [A_hi 2048][A_lo 2048][B_hi 1024][B_lo 1024] = 6144 = 24576 B.
// 2 stages = 49152 B -> 3 blocks/SM.
// mode: 0=Q(qfrag) 1=K(kfrag) 2=V(vfrag) 3=final fp32 out[b,E,32,32]
// ---------------------------------------------------------------------------
#define G_STAGE 6144                 // u32
#define G_SMEMB (2 * G_STAGE * 4)    // 49152 B

__global__ __launch_bounds__(256, 3) void k_gemm(
    const __nv_bfloat16* __restrict__ A_hi, const __nv_bfloat16* __restrict__ A_lo,
    const __nv_bfloat16* __restrict__ W_hi, const __nv_bfloat16* __restrict__ W_lo,
    const float* __restrict__ bias,
    __nv_bfloat16* __restrict__ o_hi, __nv_bfloat16* __restrict__ o_lo,
    float* __restrict__ o_f,
    int mode, float oscale)
{
    extern __shared__ uint32_t sg[];
    uint32_t sbase = (uint32_t)__cvta_generic_to_shared(sg);

    const int tid  = threadIdx.x;
    const int lane = tid & 31;
    const int w    = tid >> 5;
    const int wm   = w >> 1;
    const int wn   = w & 1;
    const int mblk = blockIdx.y;
    const int nblk = blockIdx.x;
    const int m0   = mblk * 128;
    const int n0   = nblk * 64;

    const uint32_t* Ah = (const uint32_t*)A_hi;
    const uint32_t* Al = (const uint32_t*)A_lo;
    const uint32_t* Bh = (const uint32_t*)W_hi;
    const uint32_t* Bl = (const uint32_t*)W_lo;

#define G_ISSUE(it, st)                                                        \
    {                                                                          \
        uint32_t sb = sbase + (st) * 24576;                                    \
        size_t asrc = (size_t)mblk * 32768 + (size_t)(it) * 2048;              \
        size_t bsrc = (size_t)nblk * 16384 + (size_t)(it) * 1024;              \
        _Pragma("unroll")                                                      \
        for (int p = 0; p < 2; p++) {                                          \
            int u = p * 256 + tid;                                             \
            cp_async16(sb + u * 16,        Ah + asrc + u * 4);                 \
            cp_async16(sb + 8192 + u * 16, Al + asrc + u * 4);                 \
        }                                                                      \
        cp_async16(sb + 16384 + tid * 16, Bh + bsrc + tid * 4);                \
        cp_async16(sb + 20480 + tid * 16, Bl + bsrc + tid * 4);                \
        CP_COMMIT();                                                           \
    }

    float acc[2][4][4];
#pragma unroll
    for (int i = 0; i < 2; i++)
#pragma unroll
        for (int j = 0; j < 4; j++)
#pragma unroll
            for (int r = 0; r < 4; r++) acc[i][j][r] = 0.0f;

    G_ISSUE(0, 0);

    for (int it = 0; it < 16; ++it) {
        CP_WAIT0();
        __syncthreads();
        if (it < 15) G_ISSUE(it + 1, (it + 1) & 1);

        const uint32_t* S = sg + (it & 1) * G_STAGE;
#pragma unroll
        for (int ks = 0; ks < 2; ks++) {
            uint4 ah[2], al[2];
            uint2 bh[4], bl[4];
#pragma unroll
            for (int i = 0; i < 2; i++) {
                int off = ks * 1024 + (wm * 2 + i) * 128 + lane * 4;
                ah[i] = *(const uint4*)&S[off];
                al[i] = *(const uint4*)&S[2048 + off];
            }
#pragma unroll
            for (int j = 0; j < 4; j++) {
                int off = 4096 + ks * 512 + (wn * 4 + j) * 64 + lane * 2;
                bh[j] = *(const uint2*)&S[off];
                bl[j] = *(const uint2*)&S[1024 + off];
            }
#pragma unroll
            for (int i = 0; i < 2; i++)
#pragma unroll
                for (int j = 0; j < 4; j++)
                    mma_bf16(acc[i][j], ah[i], bl[j]);
#pragma unroll
            for (int i = 0; i < 2; i++)
#pragma unroll
                for (int j = 0; j < 4; j++)
                    mma_bf16(acc[i][j], al[i], bh[j]);
#pragma unroll
            for (int i = 0; i < 2; i++)
#pragma unroll
                for (int j = 0; j < 4; j++)
                    mma_bf16(acc[i][j], ah[i], bh[j]);
        }
        if (it < 15) __syncthreads();
    }

    const int g = lane >> 2;
    const int t = lane & 3;
#pragma unroll
    for (int i = 0; i < 2; i++) {
#pragma unroll
        for (int j = 0; j < 4; j++) {
#pragma unroll
            for (int r = 0; r < 4; r++) {
                int m = m0 + wm * 32 + i * 16 + g + (r >> 1) * 8;
                int n = n0 + wn * 32 + j * 8 + 2 * t + (r & 1);
                float v = (acc[i][j][r] + bias[n]) * oscale;
                int b = m >> 10;
                int s = m & 1023;
                if (mode == 3) {
                    o_f[((size_t)(b * EMB + n)) * SEQ + s] = v;
                } else {
                    int h = n >> 6, d = n & 63;
                    int bh = b * NH + h;
                    size_t idx;
                    if (mode == 0)      idx = qfrag_e(bh, s, d);
                    else if (mode == 1) idx = kfrag_e(bh, s, d);
                    else                idx = vfrag_e(bh, s, d);
                    __nv_bfloat16 hh, ll;
                    split_bf16(v, hh, ll);
                    o_hi[idx] = hh;
                    o_lo[idx] = ll;
                }
            }
        }
    }
}
#undef G_ISSUE

// ---------------------------------------------------------------------------
// Kernel: bf16 mma flash attention. BM=64 q rows, 32-key tiles (32), 256 thr,
// 2 blocks/SM. Q_hi in registers (4x uint4), Q_lo in smem. K/V double-buffered
// identity cp.async. Local-base softmax (16-key halves = k16 chunks), register
// running stats, 2 syncs/tile. P split to bf16 hi/lo on the fly in PV.
// smem (u32/float units): QL [0,2048) | KV [2048, 2048+2*4096)
//   (per buf: KH+0 KL+1024 VH+2048 VL+3072) | PS 10240 (64*34 fl) |
//   SMAX 12416(128) SSUM 12544(128); total 12672 * 4 = 50688 B
// ---------------------------------------------------------------------------
#define F_KVU  2048
#define F_PS   10240
#define F_SMAX 12416
#define F_SSUM 12544
#define F_SMEMB (12672 * 4)

__global__ __launch_bounds__(256, 2) void k_flash_mma(
    const __nv_bfloat16* __restrict__ q_hi, const __nv_bfloat16* __restrict__ q_lo,
    const __nv_bfloat16* __restrict__ k_hi, const __nv_bfloat16* __restrict__ k_lo,
    const __nv_bfloat16* __restrict__ v_hi, const __nv_bfloat16* __restrict__ v_lo,
    __nv_bfloat16* __restrict__ att_hi, __nv_bfloat16* __restrict__ att_lo)
{
    extern __shared__ uint32_t smu[];
    float* smf = (float*)smu;
    uint32_t sbase = (uint32_t)__cvta_generic_to_shared(smu);

    const int tid  = threadIdx.x;
    const int lane = tid & 31;
    const int w    = tid >> 5;
    const int bh   = blockIdx.y;
    const int q0   = blockIdx.x * 64;
    const size_t qbase = (size_t)bh * 32768 + (size_t)(q0 >> 7) * 4096;  // u32
    const int mtb = ((q0 & 127) >> 4);   // m-tile base (0 or 4)

    const uint32_t* Kh = (const uint32_t*)k_hi;
    const uint32_t* Kl = (const uint32_t*)k_lo;
    const uint32_t* Vh = (const uint32_t*)v_hi;
    const uint32_t* Vl = (const uint32_t*)v_lo;
    const uint32_t* Qh = (const uint32_t*)q_hi;
    const uint32_t* Ql = (const uint32_t*)q_lo;

    // prologue: Q_lo (512 x16B units) + KV tile 0 (4 planes x 256 units)
#pragma unroll
    for (int p = 0; p < 2; p++) {
        int u = p * 256 + tid;
        int kc = u >> 7, rem = u & 127;
        cp_async16(sbase + (kc * 512 + rem * 4) * 4,
                   Ql + qbase + kc * 1024 + mtb * 128 + rem * 4);
    }
    {
        size_t src = (size_t)bh * 32768;
        uint32_t db = sbase + F_KVU * 4;
        cp_async16(db + tid * 16,         Kh + src + tid * 4);
        cp_async16(db + 4096 + tid * 16,  Kl + src + tid * 4);
        cp_async16(db + 8192 + tid * 16,  Vh + src + tid * 4);
        cp_async16(db + 12288 + tid * 16, Vl + src + tid * 4);
    }
    CP_COMMIT();

    const int wm = w & 3, wn = w >> 2;   // QK: m-tile, 16-key half (=k16 chunk)
    const int nh = w >> 2;               // PV: d half
    const int t = lane & 3;
    const int qrow = lane >> 2;

    const int rA = wm * 16 + qrow, rB = rA + 8;   // local rows 0..63

    // Q_hi fragments in registers
    uint4 qh[4];
#pragma unroll
    for (int kc = 0; kc < 4; kc++)
        qh[kc] = *(const uint4*)(Qh + qbase + kc * 1024 + (mtb + wm) * 128 + lane * 4);

    float m_runA = -1e30f, m_runB = -1e30f;
    float l_runA = 0.0f,   l_runB = 0.0f;

    float o[4][4];
#pragma unroll
    for (int j = 0; j < 4; j++)
#pragma unroll
        for (int r = 0; r < 4; r++) o[j][r] = 0.0f;

    for (int ti = 0; ti < 32; ++ti) {
        CP_WAIT0();
        __syncthreads();    // syncA: tile ready; prev PV done with PS/SMAX/SSUM

        if (ti < 31) {
            size_t src = (size_t)bh * 32768 + (size_t)(ti + 1) * 1024;
            uint32_t db = sbase + F_KVU * 4 + (((ti + 1) & 1) ? 16384u : 0u);
            cp_async16(db + tid * 16,         Kh + src + tid * 4);
            cp_async16(db + 4096 + tid * 16,  Kl + src + tid * 4);
            cp_async16(db + 8192 + tid * 16,  Vh + src + tid * 4);
            cp_async16(db + 12288 + tid * 16, Vl + src + tid * 4);
            CP_COMMIT();
        }
        const uint32_t* KV = smu + F_KVU + (ti & 1) * 4096;

        // ---- QK^T (3xBF16, pass-major): keys wn*16..wn*16+15, 4 d-chunks ----
        float sacc[2][4];
#pragma unroll
        for (int j = 0; j < 2; j++)
#pragma unroll
            for (int r = 0; r < 4; r++) sacc[j][r] = 0.0f;

#pragma unroll
        for (int kc = 0; kc < 4; kc++) {
            uint4 al = *(const uint4*)&smu[kc * 512 + wm * 128 + lane * 4];
            uint4 ah = qh[kc];
            uint2 bhf[2], blf[2];
#pragma unroll
            for (int j = 0; j < 2; j++) {
                int boff = kc * 256 + (wn * 2 + j) * 64 + lane * 2;
                bhf[j] = *(const uint2*)&KV[boff];
                blf[j] = *(const uint2*)&KV[1024 + boff];
            }
#pragma unroll
            for (int j = 0; j < 2; j++) mma_bf16(sacc[j], ah, blf[j]);
#pragma unroll
            for (int j = 0; j < 2; j++) mma_bf16(sacc[j], al, bhf[j]);
#pragma unroll
            for (int j = 0; j < 2; j++) mma_bf16(sacc[j], ah, bhf[j]);
        }

        // ---- local-base softmax (own 16-key half) ----
        float mA = fmaxf(fmaxf(sacc[0][0], sacc[0][1]), fmaxf(sacc[1][0], sacc[1][1]));
        float mB = fmaxf(fmaxf(sacc[0][2], sacc[0][3]), fmaxf(sacc[1][2], sacc[1][3]));
        mA = fmaxf(mA, __shfl_xor_sync(FULLMASK, mA, 1));
        mA = fmaxf(mA, __shfl_xor_sync(FULLMASK, mA, 2));
        mB = fmaxf(mB, __shfl_xor_sync(FULLMASK, mB, 1));
        mB = fmaxf(mB, __shfl_xor_sync(FULLMASK, mB, 2));

        float p[2][4];
        float sA = 0.0f, sB = 0.0f;
#pragma unroll
        for (int j = 0; j < 2; j++) {
            p[j][0] = __expf(sacc[j][0] - mA);
            p[j][1] = __expf(sacc[j][1] - mA);
            p[j][2] = __expf(sacc[j][2] - mB);
            p[j][3] = __expf(sacc[j][3] - mB);
            sA += p[j][0] + p[j][1];
            sB += p[j][2] + p[j][3];
        }
        sA += __shfl_xor_sync(FULLMASK, sA, 1);
        sA += __shfl_xor_sync(FULLMASK, sA, 2);
        sB += __shfl_xor_sync(FULLMASK, sB, 1);
        sB += __shfl_xor_sync(FULLMASK, sB, 2);
        if (t == 0) {
            smf[F_SMAX + wn * 64 + rA] = mA;
            smf[F_SMAX + wn * 64 + rB] = mB;
            smf[F_SSUM + wn * 64 + rA] = sA;
            smf[F_SSUM + wn * 64 + rB] = sB;
        }
#pragma unroll
        for (int j = 0; j < 2; j++) {
            int c = wn * 16 + j * 8 + 2 * t;
            *(float2*)&smf[F_PS + rA * 34 + c] = make_float2(p[j][0], p[j][1]);
            *(float2*)&smf[F_PS + rB * 34 + c] = make_float2(p[j][2], p[j][3]);
        }
        __syncthreads();    // syncB: P, SMAX, SSUM visible

        // ---- PV (3xBF16) with per-(row,chunk) correction; stats in regs ----
        float bA0 = smf[F_SMAX + rA], bA1 = smf[F_SMAX + 64 + rA];
        float bB0 = smf[F_SMAX + rB], bB1 = smf[F_SMAX + 64 + rB];
        float ssA0 = smf[F_SSUM + rA], ssA1 = smf[F_SSUM + 64 + rA];
        float ssB0 = smf[F_SSUM + rB], ssB1 = smf[F_SSUM + 64 + rB];
        float mnA = fmaxf(m_runA, fmaxf(bA0, bA1));
        float mnB = fmaxf(m_runB, fmaxf(bB0, bB1));
        float alA = __expf(m_runA - mnA), alB = __expf(m_runB - mnB);
        float cA0 = __expf(bA0 - mnA), cA1 = __expf(bA1 - mnA);
        float cB0 = __expf(bB0 - mnB), cB1 = __expf(bB1 - mnB);
        l_runA = l_runA * alA + cA0 * ssA0 + cA1 * ssA1;
        l_runB = l_runB * alB + cB0 * ssB0 + cB1 * ssB1;
        m_runA = mnA;
        m_runB = mnB;
#pragma unroll
        for (int j = 0; j < 4; j++) {
            o[j][0] *= alA; o[j][1] *= alA;
            o[j][2] *= alB; o[j][3] *= alB;
        }
#pragma unroll
        for (int c = 0; c < 2; c++) {       // key chunks of 16
            float cA = (c == 0) ? cA0 : cA1;
            float cB = (c == 0) ? cB0 : cB1;
            const float* PA = &smf[F_PS + rA * 34 + c * 16];
            const float* PB = &smf[F_PS + rB * 34 + c * 16];
            float pe0 = PA[2 * t]     * cA, po0 = PA[2 * t + 1] * cA;
            float pe1 = PB[2 * t]     * cB, po1 = PB[2 * t + 1] * cB;
            float pe2 = PA[2 * t + 8] * cA, po2 = PA[2 * t + 9] * cA;
            float pe3 = PB[2 * t + 8] * cB, po3 = PB[2 * t + 9] * cB;
            uint4 ah, al;
            ah.x = pack_bf16x2(pe0, po0);
            ah.y = pack_bf16x2(pe1, po1);
            ah.z = pack_bf16x2(pe2, po2);
            ah.w = pack_bf16x2(pe3, po3);
            al.x = pack_bf16x2(pe0 - __uint_as_float(ah.x << 16),
                               po0 - __uint_as_float(ah.x & 0xFFFF0000u));
            al.y = pack_bf16x2(pe1 - __uint_as_float(ah.y << 16),
                               po1 - __uint_as_float(ah.y & 0xFFFF0000u));
            al.z = pack_bf16x2(pe2 - __uint_as_float(ah.z << 16),
                               po2 - __uint_as_float(ah.z & 0xFFFF0000u));
            al.w = pack_bf16x2(pe3 - __uint_as_float(ah.w << 16),
                               po3 - __uint_as_float(ah.w & 0xFFFF0000u));
            uint2 bhf[4], blf[4];
#pragma unroll
            for (int jl = 0; jl < 4; jl++) {
                int boff = 2048 + c * 512 + (nh * 4 + jl) * 64 + lane * 2;
                bhf[jl] = *(const uint2*)&KV[boff];
                blf[jl] = *(const uint2*)&KV[1024 + boff];
            }
#pragma unroll
            for (int jl = 0; jl < 4; jl++) mma_bf16(o[jl], ah, blf[jl]);
#pragma unroll
            for (int jl = 0; jl < 4; jl++) mma_bf16(o[jl], al, bhf[jl]);
#pragma unroll
            for (int jl = 0; jl < 4; jl++) mma_bf16(o[jl], ah, bhf[jl]);
        }
    }

    // ---- epilogue: o /= l, bf16 split, att in A-frag layout ----
    const float invA = 1.0f / l_runA;
    const float invB = 1.0f / l_runB;
    const int b = bh >> 3, h = bh & 7;
    const int mA_g = b * SEQ + q0 + rA;
    const int mB_g = b * SEQ + q0 + rB;
#pragma unroll
    for (int jl = 0; jl < 4; jl++) {
#pragma unroll
        for (int rr = 0; rr < 2; rr++) {
            int e = h * HD + nh * 32 + jl * 8 + 2 * t + rr;
            float vA = o[jl][rr]     * invA;
            float vB = o[jl][rr + 2] * invB;
            __nv_bfloat16 hA, lA, hB, lB;
            split_bf16(vA, hA, lA);
            split_bf16(vB, hB, lB);
            size_t iA = afrag_e(mA_g, e);
            size_t iB = afrag_e(mB_g, e);
            att_hi[iA] = hA;  att_lo[iA] = lA;
            att_hi[iB] = hB;  att_lo[iB] = lB;
        }
    }
}

// ---------------------------------------------------------------------------
extern "C" void kernel_launch(void* const* d_in, const int* in_sizes, int n_in,
                              void* d_out, int out_size)
{
    const float* x     = (const float*)d_in[0];
    const float* pos_w = (const float*)d_in[1];
    const float* pos_b = (const float*)d_in[2];
    const float* wq    = (const float*)d_in[3];
    const float* bq    = (const float*)d_in[4];
    const float* wk    = (const float*)d_in[5];
    const float* bk    = (const float*)d_in[6];
    const float* wv    = (const float*)d_in[7];
    const float* bv    = (const float*)d_in[8];
    const float* wo    = (const float*)d_in[9];
    const float* bo    = (const float*)d_in[10];
    float* out = (float*)d_out;

    void* sp = nullptr;
    cudaGetSymbolAddress(&sp, g_scratch);
    __nv_bfloat16* base = (__nv_bfloat16*)sp;
    __nv_bfloat16* xt_hi  = base;
    __nv_bfloat16* xt_lo  = xt_hi + PLANE;
    __nv_bfloat16* q_hi   = xt_lo + PLANE;
    __nv_bfloat16* q_lo   = q_hi  + PLANE;
    __nv_bfloat16* k_hi   = q_lo  + PLANE;
    __nv_bfloat16* k_lo   = k_hi  + PLANE;
    __nv_bfloat16* v_hi   = k_lo  + PLANE;
    __nv_bfloat16* v_lo   = v_hi  + PLANE;
    __nv_bfloat16* att_hi = v_lo  + PLANE;
    __nv_bfloat16* att_lo = att_hi + PLANE;
    __nv_bfloat16* wsp    = att_lo + PLANE;
    __nv_bfloat16* wq_hi = wsp;              __nv_bfloat16* wq_lo = wq_hi + WPLANE;
    __nv_bfloat16* wk_hi = wq_lo + WPLANE;   __nv_bfloat16* wk_lo = wk_hi + WPLANE;
    __nv_bfloat16* wv_hi = wk_lo + WPLANE;   __nv_bfloat16* wv_lo = wv_hi + WPLANE;
    __nv_bfloat16* wo_hi = wv_lo + WPLANE;   __nv_bfloat16* wo_lo = wo_hi + WPLANE;

    cudaFuncSetAttribute(k_gemm, cudaFuncAttributeMaxDynamicSharedMemorySize, G_SMEMB);
    cudaFuncSetAttribute(k_flash_mma, cudaFuncAttributeMaxDynamicSharedMemorySize, F_SMEMB);

    {
        dim3 grid(EMB / 32, SEQ / 32, BATCH);
        dim3 block(32, 8);
        k_transpose_pe<<<grid, block>>>(x, pos_w, pos_b, xt_hi, xt_lo);
    }
    {
        dim3 grid((unsigned)(WPLANE / 256), 4);
        k_split4<<<grid, 256>>>(wq, wk, wv, wo, wsp);
    }
    {
        dim3 grid(EMB / 64, MTOT / 128);
        k_gemm<<<grid, 256, G_SMEMB>>>(xt_hi, xt_lo, wq_hi, wq_lo, bq, q_hi, q_lo, out, 0, 0.125f);
        k_gemm<<<grid, 256, G_SMEMB>>>(xt_hi, xt_lo, wk_hi, wk_lo, bk, k_hi, k_lo, out, 1, 1.0f);
        k_gemm<<<grid, 256, G_SMEMB>>>(xt_hi, xt_lo, wv_hi, wv_lo, bv, v_hi, v_lo, out, 2, 1.0f);
    }
    {
        dim3 grid(SEQ / 64, BATCH * NH);
        k_flash_mma<<<grid, 256, F_SMEMB>>>(q_hi, q_lo, k_hi, k_lo, v_hi, v_lo,
                                            att_hi, att_lo);
    }
    {
        dim3 grid(EMB / 64, MTOT / 128);
        k_gemm<<<grid, 256, G_SMEMB>>>(att_hi, att_lo, wo_hi, wo_lo, bo,
                                       q_hi, q_lo, out, 3, 1.0f);
    }
}

// round 16
// speedup vs baseline: 3.5224x; 1.1754x over previous
#include <cuda_runtime.h>
#include <cuda_bf16.h>
#include <cstdint>

// ---------------------------------------------------------------------------
// SelfAttentionWithPE: B=8, E=512, H=W=32 (S=1024), heads=8, head_dim=64, fp32
// 3xBF16 (hi/lo) mma.sync.m16n8k16 everywhere; fragment-permuted gmem
// layouts -> identity cp.async smem fills.
// R16: flash 64-key tiles (32 barriers total), QKV GEMMs fused in one launch.
// ---------------------------------------------------------------------------

#define BATCH 8
#define EMB   512
#define SEQ   1024
#define NH    8
#define HD    64
#define MTOT  (BATCH * SEQ)
#define FULLMASK 0xffffffffu

#define PLANE   ((size_t)MTOT * EMB)        // bf16 elems / plane
#define WPLANE  ((size_t)EMB * EMB)
__device__ float g_scratch[10 * 4194304 + 8 * 262144];

// ---------------------------------------------------------------------------
__device__ __forceinline__ void split_bf16(float v, __nv_bfloat16& h, __nv_bfloat16& l)
{
    h = __float2bfloat16(v);
    l = __float2bfloat16(v - __bfloat162float(h));
}
__device__ __forceinline__ unsigned pack_bf16x2(float even, float odd)
{
    unsigned r;
    asm("cvt.rn.bf16x2.f32 %0, %1, %2;" : "=r"(r) : "f"(odd), "f"(even));
    return r;
}
__device__ __forceinline__ void mma_bf16(float* d, const uint4& a, const uint2& b)
{
    asm("mma.sync.aligned.m16n8k16.row.col.f32.bf16.bf16.f32 "
        "{%0,%1,%2,%3}, {%4,%5,%6,%7}, {%8,%9}, {%0,%1,%2,%3};\n"
        : "+f"(d[0]), "+f"(d[1]), "+f"(d[2]), "+f"(d[3])
        : "r"(a.x), "r"(a.y), "r"(a.z), "r"(a.w), "r"(b.x), "r"(b.y));
}
__device__ __forceinline__ void cp_async16(uint32_t smem_byte, const void* g)
{
    asm volatile("cp.async.cg.shared.global [%0], [%1], 16;\n"
                 :: "r"(smem_byte), "l"(g));
}
#define CP_COMMIT() asm volatile("cp.async.commit_group;\n" ::: "memory")
#define CP_WAIT0()  asm volatile("cp.async.wait_group 0;\n" ::: "memory")

// ---------------------------------------------------------------------------
// Fragment element-index helpers (bf16 elems), m16n8k16 lane maps
// (validated by R15 pass at rel_err 4.94e-5).
// ---------------------------------------------------------------------------
__device__ __forceinline__ size_t afrag_e(int m, int k)    // xt/att
{
    int mt = (m & 127) >> 4, ml = m & 15, mh = ml >> 3, g = ml & 7;
    int kl = k & 15, kq = kl >> 1, kh = kq >> 2, t = kq & 3;
    size_t u = (size_t)(m >> 7) * 32768 + (size_t)(k >> 4) * 1024
             + mt * 128 + (g * 4 + t) * 4 + kh * 2 + mh;
    return u * 2 + (kl & 1);
}
__device__ __forceinline__ size_t bfragw_e(int k, int n)   // W
{
    int nt = (n & 63) >> 3, g = n & 7;
    int kq = (k & 15) >> 1, kh = kq >> 2, t = kq & 3;
    size_t u = (size_t)(n >> 6) * 16384 + (size_t)(k >> 4) * 512
             + nt * 64 + (g * 4 + t) * 2 + kh;
    return u * 2 + (k & 1);
}
__device__ __forceinline__ size_t qfrag_e(int bh, int s, int d)
{
    int mt = (s & 127) >> 4, ml = s & 15, mh = ml >> 3, g = ml & 7;
    int kq = (d & 15) >> 1, kh = kq >> 2, t = kq & 3;
    size_t u = (size_t)bh * 32768 + (size_t)(s >> 7) * 4096 + (d >> 4) * 1024
             + mt * 128 + (g * 4 + t) * 4 + kh * 2 + mh;
    return u * 2 + (d & 1);
}
// K for 64-key tiles: [bh][kt16][kc4][nt8*64]
__device__ __forceinline__ size_t kfrag64_e(int bh, int s, int d)
{
    int kq = (d & 15) >> 1, kh = kq >> 2, t = kq & 3;
    size_t u = (size_t)bh * 32768 + (size_t)(s >> 6) * 2048 + (d >> 4) * 512
             + ((s & 63) >> 3) * 64 + ((s & 7) * 4 + t) * 2 + kh;
    return u * 2 + (d & 1);
}
// V for 64-key tiles: [bh][kt16][sc4][nt8*64]
__device__ __forceinline__ size_t vfrag64_e(int bh, int s, int d)
{
    int kq = (s & 15) >> 1, kh = kq >> 2, t = kq & 3;
    size_t u = (size_t)bh * 32768 + (size_t)(s >> 6) * 2048 + ((size_t)((s & 63) >> 4)) * 512
             + (d >> 3) * 64 + ((d & 7) * 4 + t) * 2 + kh;
    return u * 2 + (s & 1);
}

// ---------------------------------------------------------------------------
// Kernel: transpose + PE -> xt hi/lo bf16 in A-frag layout
// ---------------------------------------------------------------------------
__global__ void k_transpose_pe(const float* __restrict__ x,
                               const float* __restrict__ pos_w,
                               const float* __restrict__ pos_b,
                               __nv_bfloat16* __restrict__ xt_hi,
                               __nv_bfloat16* __restrict__ xt_lo)
{
    __shared__ float tile[32][33];
    const int e0 = blockIdx.x * 32;
    const int s0 = blockIdx.y * 32;
    const int b  = blockIdx.z;
    const int tx = threadIdx.x;
    const int ty = threadIdx.y;

#pragma unroll
    for (int i = 0; i < 4; i++) {
        int el = ty + i * 8;
        tile[el][tx] = x[((size_t)(b * EMB + e0 + el)) * SEQ + s0 + tx];
    }
    __syncthreads();

    const int e = e0 + tx;
    const float pw0 = pos_w[e];
    const float pw1 = pos_w[EMB + e];
    const float pb  = pos_b[e];
#pragma unroll
    for (int i = 0; i < 4; i++) {
        int sl = ty + i * 8;
        int s  = s0 + sl;
        float row = (float)(s >> 5);
        float col = (float)(s & 31);
        float v = tile[tx][sl] + row * pw0 + col * pw1 + pb;
        size_t idx = afrag_e(b * SEQ + s, e);
        __nv_bfloat16 h, l;
        split_bf16(v, h, l);
        xt_hi[idx] = h;
        xt_lo[idx] = l;
    }
}

// ---------------------------------------------------------------------------
// Kernel: split 4 weight matrices into hi/lo bf16 B-frag layout.
// ---------------------------------------------------------------------------
__global__ void k_split4(const float* __restrict__ w0, const float* __restrict__ w1,
                         const float* __restrict__ w2, const float* __restrict__ w3,
                         __nv_bfloat16* __restrict__ base_hi_lo)
{
    const float* src;
    switch (blockIdx.y) {
        case 0: src = w0; break;
        case 1: src = w1; break;
        case 2: src = w2; break;
        default: src = w3; break;
    }
    __nv_bfloat16* hi = base_hi_lo + (size_t)blockIdx.y * 2 * WPLANE;
    __nv_bfloat16* lo = hi + WPLANE;
    int i = blockIdx.x * 256 + threadIdx.x;
    int k = i >> 9, n = i & 511;
    float v = src[i];
    size_t idx = bfragw_e(k, n);
    __nv_bfloat16 h, l;
    split_bf16(v, h, l);
    hi[idx] = h;
    lo[idx] = l;
}

// ---------------------------------------------------------------------------
// Kernel: 3xBF16 GEMM. BM=128 BN=64 BK=32, cp.async double-buffered,
// 3 blocks/SM. fused_mode = -1: blockIdx.z in {0,1,2} selects QKV set;
// fused_mode = 3: final fp32 output using set 0.
// ---------------------------------------------------------------------------
#define G_STAGE 6144                 // u32
#define G_SMEMB (2 * G_STAGE * 4)    // 49152 B

__global__ __launch_bounds__(256, 3) void k_gemm(
    const __nv_bfloat16* __restrict__ A_hi, const __nv_bfloat16* __restrict__ A_lo,
    const __nv_bfloat16* __restrict__ W0h, const __nv_bfloat16* __restrict__ W0l,
    const __nv_bfloat16* __restrict__ W1h, const __nv_bfloat16* __restrict__ W1l,
    const __nv_bfloat16* __restrict__ W2h, const __nv_bfloat16* __restrict__ W2l,
    const float* __restrict__ b0, const float* __restrict__ b1,
    const float* __restrict__ b2,
    __nv_bfloat16* __restrict__ o0h, __nv_bfloat16* __restrict__ o0l,
    __nv_bfloat16* __restrict__ o1h, __nv_bfloat16* __restrict__ o1l,
    __nv_bfloat16* __restrict__ o2h, __nv_bfloat16* __restrict__ o2l,
    float* __restrict__ o_f,
    int fused_mode)
{
    extern __shared__ uint32_t sgm[];
    uint32_t sbase = (uint32_t)__cvta_generic_to_shared(sgm);

    const int mode = (fused_mode < 0) ? (int)blockIdx.z : fused_mode;
    const __nv_bfloat16 *Whp, *Wlp;
    const float* bias;
    __nv_bfloat16 *ohp, *olp;
    float oscale;
    if (mode == 1)      { Whp = W1h; Wlp = W1l; bias = b1; ohp = o1h; olp = o1l; oscale = 1.0f; }
    else if (mode == 2) { Whp = W2h; Wlp = W2l; bias = b2; ohp = o2h; olp = o2l; oscale = 1.0f; }
    else                { Whp = W0h; Wlp = W0l; bias = b0; ohp = o0h; olp = o0l;
                          oscale = (mode == 0) ? 0.125f : 1.0f; }

    const int tid  = threadIdx.x;
    const int lane = tid & 31;
    const int w    = tid >> 5;
    const int wm   = w >> 1;
    const int wn   = w & 1;
    const int mblk = blockIdx.y;
    const int nblk = blockIdx.x;
    const int m0   = mblk * 128;
    const int n0   = nblk * 64;

    const uint32_t* Ah = (const uint32_t*)A_hi;
    const uint32_t* Al = (const uint32_t*)A_lo;
    const uint32_t* Bh = (const uint32_t*)Whp;
    const uint32_t* Bl = (const uint32_t*)Wlp;

#define G_ISSUE(it, st)                                                        \
    {                                                                          \
        uint32_t sb = sbase + (st) * 24576;                                    \
        size_t asrc = (size_t)mblk * 32768 + (size_t)(it) * 2048;              \
        size_t bsrc = (size_t)nblk * 16384 + (size_t)(it) * 1024;              \
        _Pragma("unroll")                                                      \
        for (int p = 0; p < 2; p++) {                                          \
            int u = p * 256 + tid;                                             \
            cp_async16(sb + u * 16,        Ah + asrc + u * 4);                 \
            cp_async16(sb + 8192 + u * 16, Al + asrc + u * 4);                 \
        }                                                                      \
        cp_async16(sb + 16384 + tid * 16, Bh + bsrc + tid * 4);                \
        cp_async16(sb + 20480 + tid * 16, Bl + bsrc + tid * 4);                \
        CP_COMMIT();                                                           \
    }

    float acc[2][4][4];
#pragma unroll
    for (int i = 0; i < 2; i++)
#pragma unroll
        for (int j = 0; j < 4; j++)
#pragma unroll
            for (int r = 0; r < 4; r++) acc[i][j][r] = 0.0f;

    G_ISSUE(0, 0);

    for (int it = 0; it < 16; ++it) {
        CP_WAIT0();
        __syncthreads();
        if (it < 15) G_ISSUE(it + 1, (it + 1) & 1);

        const uint32_t* S = sgm + (it & 1) * G_STAGE;
#pragma unroll
        for (int ks = 0; ks < 2; ks++) {
            uint4 ah[2], al[2];
            uint2 bh[4], bl[4];
#pragma unroll
            for (int i = 0; i < 2; i++) {
                int off = ks * 1024 + (wm * 2 + i) * 128 + lane * 4;
                ah[i] = *(const uint4*)&S[off];
                al[i] = *(const uint4*)&S[2048 + off];
            }
#pragma unroll
            for (int j = 0; j < 4; j++) {
                int off = 4096 + ks * 512 + (wn * 4 + j) * 64 + lane * 2;
                bh[j] = *(const uint2*)&S[off];
                bl[j] = *(const uint2*)&S[1024 + off];
            }
#pragma unroll
            for (int i = 0; i < 2; i++)
#pragma unroll
                for (int j = 0; j < 4; j++)
                    mma_bf16(acc[i][j], ah[i], bl[j]);
#pragma unroll
            for (int i = 0; i < 2; i++)
#pragma unroll
                for (int j = 0; j < 4; j++)
                    mma_bf16(acc[i][j], al[i], bh[j]);
#pragma unroll
            for (int i = 0; i < 2; i++)
#pragma unroll
                for (int j = 0; j < 4; j++)
                    mma_bf16(acc[i][j], ah[i], bh[j]);
        }
        if (it < 15) __syncthreads();
    }

    const int g = lane >> 2;
    const int t = lane & 3;
#pragma unroll
    for (int i = 0; i < 2; i++) {
#pragma unroll
        for (int j = 0; j < 4; j++) {
#pragma unroll
            for (int r = 0; r < 4; r++) {
                int m = m0 + wm * 32 + i * 16 + g + (r >> 1) * 8;
                int n = n0 + wn * 32 + j * 8 + 2 * t + (r & 1);
                float v = (acc[i][j][r] + bias[n]) * oscale;
                int b = m >> 10;
                int s = m & 1023;
                if (mode == 3) {
                    o_f[((size_t)(b * EMB + n)) * SEQ + s] = v;
                } else {
                    int h = n >> 6, d = n & 63;
                    int bh = b * NH + h;
                    size_t idx;
                    if (mode == 0)      idx = qfrag_e(bh, s, d);
                    else if (mode == 1) idx = kfrag64_e(bh, s, d);
                    else                idx = vfrag64_e(bh, s, d);
                    __nv_bfloat16 hh, ll;
                    split_bf16(v, hh, ll);
                    ohp[idx] = hh;
                    olp[idx] = ll;
                }
            }
        }
    }
}
#undef G_ISSUE

// ---------------------------------------------------------------------------
// Kernel: bf16 mma flash attention. BM=64 q rows, 64-key tiles (16), 256 thr,
// 2 blocks/SM, 2 syncs/tile (32 barriers total). Q_hi in regs, Q_lo in smem,
// K/V double-buffered identity cp.async. Local-base softmax over 32-key
// halves, register running stats. P split to bf16 hi/lo on the fly.
// smem u32: QL [0,2048) | KV 2048 (2 bufs x 8192: KH+0 KL+2048 VH+4096
//   VL+6144) | PS 18432 (64x66 fl) | SMAX 22656(128) SSUM 22784(128)
//   total 22912 u32 = 91648 B
// ---------------------------------------------------------------------------
#define F_KVU  2048
#define F_PS   18432
#define F_SMAX 22656
#define F_SSUM 22784
#define F_SMEMB (22912 * 4)

__global__ __launch_bounds__(256, 2) void k_flash_mma(
    const __nv_bfloat16* __restrict__ q_hi, const __nv_bfloat16* __restrict__ q_lo,
    const __nv_bfloat16* __restrict__ k_hi, const __nv_bfloat16* __restrict__ k_lo,
    const __nv_bfloat16* __restrict__ v_hi, const __nv_bfloat16* __restrict__ v_lo,
    __nv_bfloat16* __restrict__ att_hi, __nv_bfloat16* __restrict__ att_lo)
{
    extern __shared__ uint32_t smu[];
    float* smf = (float*)smu;
    uint32_t sbase = (uint32_t)__cvta_generic_to_shared(smu);

    const int tid  = threadIdx.x;
    const int lane = tid & 31;
    const int w    = tid >> 5;
    const int bh   = blockIdx.y;
    const int q0   = blockIdx.x * 64;
    const size_t qbase = (size_t)bh * 32768 + (size_t)(q0 >> 7) * 4096;  // u32
    const int mtb = ((q0 & 127) >> 4);

    const uint32_t* Kh = (const uint32_t*)k_hi;
    const uint32_t* Kl = (const uint32_t*)k_lo;
    const uint32_t* Vh = (const uint32_t*)v_hi;
    const uint32_t* Vl = (const uint32_t*)v_lo;
    const uint32_t* Qh = (const uint32_t*)q_hi;
    const uint32_t* Ql = (const uint32_t*)q_lo;

    // prologue: Q_lo (512 x16B) + KV tile 0 (4 planes x 512 x16B units)
#pragma unroll
    for (int p = 0; p < 2; p++) {
        int u = p * 256 + tid;
        int kc = u >> 7, rem = u & 127;
        cp_async16(sbase + (kc * 512 + rem * 4) * 4,
                   Ql + qbase + kc * 1024 + mtb * 128 + rem * 4);
    }
    {
        size_t src = (size_t)bh * 32768;
        uint32_t db = sbase + F_KVU * 4;
#pragma unroll
        for (int p = 0; p < 2; p++) {
            int u = p * 256 + tid;
            cp_async16(db + u * 16,         Kh + src + u * 4);
            cp_async16(db + 8192 + u * 16,  Kl + src + u * 4);
            cp_async16(db + 16384 + u * 16, Vh + src + u * 4);
            cp_async16(db + 24576 + u * 16, Vl + src + u * 4);
        }
    }
    CP_COMMIT();

    const int wm = w & 3, wn = w >> 2;   // QK: m-tile, 32-key half
    const int nh = w >> 2;               // PV: d half
    const int t = lane & 3;
    const int qrow = lane >> 2;

    const int rA = wm * 16 + qrow, rB = rA + 8;

    uint4 qh[4];
#pragma unroll
    for (int kc = 0; kc < 4; kc++)
        qh[kc] = *(const uint4*)(Qh + qbase + kc * 1024 + (mtb + wm) * 128 + lane * 4);

    float m_runA = -1e30f, m_runB = -1e30f;
    float l_runA = 0.0f,   l_runB = 0.0f;

    float o[4][4];
#pragma unroll
    for (int j = 0; j < 4; j++)
#pragma unroll
        for (int r = 0; r < 4; r++) o[j][r] = 0.0f;

    for (int ti = 0; ti < 16; ++ti) {
        CP_WAIT0();
        __syncthreads();    // syncA

        if (ti < 15) {
            size_t src = (size_t)bh * 32768 + (size_t)(ti + 1) * 2048;
            uint32_t db = sbase + F_KVU * 4 + (((ti + 1) & 1) ? 32768u : 0u);
#pragma unroll
            for (int p = 0; p < 2; p++) {
                int u = p * 256 + tid;
                cp_async16(db + u * 16,         Kh + src + u * 4);
                cp_async16(db + 8192 + u * 16,  Kl + src + u * 4);
                cp_async16(db + 16384 + u * 16, Vh + src + u * 4);
                cp_async16(db + 24576 + u * 16, Vl + src + u * 4);
            }
            CP_COMMIT();
        }
        const uint32_t* KV = smu + F_KVU + (ti & 1) * 8192;

        // ---- QK^T (3xBF16, pass-major): keys wn*32 .. wn*32+31 ----
        float sacc[4][4];
#pragma unroll
        for (int j = 0; j < 4; j++)
#pragma unroll
            for (int r = 0; r < 4; r++) sacc[j][r] = 0.0f;

#pragma unroll
        for (int kc = 0; kc < 4; kc++) {
            uint4 al = *(const uint4*)&smu[kc * 512 + wm * 128 + lane * 4];
            uint4 ah = qh[kc];
            uint2 bhf[4], blf[4];
#pragma unroll
            for (int j = 0; j < 4; j++) {
                int boff = kc * 512 + (wn * 4 + j) * 64 + lane * 2;
                bhf[j] = *(const uint2*)&KV[boff];
                blf[j] = *(const uint2*)&KV[2048 + boff];
            }
#pragma unroll
            for (int j = 0; j < 4; j++) mma_bf16(sacc[j], ah, blf[j]);
#pragma unroll
            for (int j = 0; j < 4; j++) mma_bf16(sacc[j], al, bhf[j]);
#pragma unroll
            for (int j = 0; j < 4; j++) mma_bf16(sacc[j], ah, bhf[j]);
        }

        // ---- local-base softmax (own 32-key half) ----
        float mA = sacc[0][0], mB = sacc[0][2];
#pragma unroll
        for (int j = 0; j < 4; j++) {
            mA = fmaxf(mA, fmaxf(sacc[j][0], sacc[j][1]));
            mB = fmaxf(mB, fmaxf(sacc[j][2], sacc[j][3]));
        }
        mA = fmaxf(mA, __shfl_xor_sync(FULLMASK, mA, 1));
        mA = fmaxf(mA, __shfl_xor_sync(FULLMASK, mA, 2));
        mB = fmaxf(mB, __shfl_xor_sync(FULLMASK, mB, 1));
        mB = fmaxf(mB, __shfl_xor_sync(FULLMASK, mB, 2));

        float p[4][4];
        float sA = 0.0f, sB = 0.0f;
#pragma unroll
        for (int j = 0; j < 4; j++) {
            p[j][0] = __expf(sacc[j][0] - mA);
            p[j][1] = __expf(sacc[j][1] - mA);
            p[j][2] = __expf(sacc[j][2] - mB);
            p[j][3] = __expf(sacc[j][3] - mB);
            sA += p[j][0] + p[j][1];
            sB += p[j][2] + p[j][3];
        }
        sA += __shfl_xor_sync(FULLMASK, sA, 1);
        sA += __shfl_xor_sync(FULLMASK, sA, 2);
        sB += __shfl_xor_sync(FULLMASK, sB, 1);
        sB += __shfl_xor_sync(FULLMASK, sB, 2);
        if (t == 0) {
            smf[F_SMAX + wn * 64 + rA] = mA;
            smf[F_SMAX + wn * 64 + rB] = mB;
            smf[F_SSUM + wn * 64 + rA] = sA;
            smf[F_SSUM + wn * 64 + rB] = sB;
        }
#pragma unroll
        for (int j = 0; j < 4; j++) {
            int c = wn * 32 + j * 8 + 2 * t;
            *(float2*)&smf[F_PS + rA * 66 + c] = make_float2(p[j][0], p[j][1]);
            *(float2*)&smf[F_PS + rB * 66 + c] = make_float2(p[j][2], p[j][3]);
        }
        __syncthreads();    // syncB

        // ---- PV (3xBF16) with per-(row, 32-key-half) correction ----
        float bA0 = smf[F_SMAX + rA], bA1 = smf[F_SMAX + 64 + rA];
        float bB0 = smf[F_SMAX + rB], bB1 = smf[F_SMAX + 64 + rB];
        float ssA0 = smf[F_SSUM + rA], ssA1 = smf[F_SSUM + 64 + rA];
        float ssB0 = smf[F_SSUM + rB], ssB1 = smf[F_SSUM + 64 + rB];
        float mnA = fmaxf(m_runA, fmaxf(bA0, bA1));
        float mnB = fmaxf(m_runB, fmaxf(bB0, bB1));
        float alA = __expf(m_runA - mnA), alB = __expf(m_runB - mnB);
        float cA0 = __expf(bA0 - mnA), cA1 = __expf(bA1 - mnA);
        float cB0 = __expf(bB0 - mnB), cB1 = __expf(bB1 - mnB);
        l_runA = l_runA * alA + cA0 * ssA0 + cA1 * ssA1;
        l_runB = l_runB * alB + cB0 * ssB0 + cB1 * ssB1;
        m_runA = mnA;
        m_runB = mnB;
#pragma unroll
        for (int j = 0; j < 4; j++) {
            o[j][0] *= alA; o[j][1] *= alA;
            o[j][2] *= alB; o[j][3] *= alB;
        }
#pragma unroll
        for (int c = 0; c < 4; c++) {       // 4 key chunks of 16
            float cA = (c < 2) ? cA0 : cA1;
            float cB = (c < 2) ? cB0 : cB1;
            const float* PA = &smf[F_PS + rA * 66 + c * 16];
            const float* PB = &smf[F_PS + rB * 66 + c * 16];
            float pe0 = PA[2 * t]     * cA, po0 = PA[2 * t + 1] * cA;
            float pe1 = PB[2 * t]     * cB, po1 = PB[2 * t + 1] * cB;
            float pe2 = PA[2 * t + 8] * cA, po2 = PA[2 * t + 9] * cA;
            float pe3 = PB[2 * t + 8] * cB, po3 = PB[2 * t + 9] * cB;
            uint4 ah, al;
            ah.x = pack_bf16x2(pe0, po0);
            ah.y = pack_bf16x2(pe1, po1);
            ah.z = pack_bf16x2(pe2, po2);
            ah.w = pack_bf16x2(pe3, po3);
            al.x = pack_bf16x2(pe0 - __uint_as_float(ah.x << 16),
                               po0 - __uint_as_float(ah.x & 0xFFFF0000u));
            al.y = pack_bf16x2(pe1 - __uint_as_float(ah.y << 16),
                               po1 - __uint_as_float(ah.y & 0xFFFF0000u));
            al.z = pack_bf16x2(pe2 - __uint_as_float(ah.z << 16),
                               po2 - __uint_as_float(ah.z & 0xFFFF0000u));
            al.w = pack_bf16x2(pe3 - __uint_as_float(ah.w << 16),
                               po3 - __uint_as_float(ah.w & 0xFFFF0000u));
            uint2 bhf[4], blf[4];
#pragma unroll
            for (int jl = 0; jl < 4; jl++) {
                int boff = 4096 + c * 512 + (nh * 4 + jl) * 64 + lane * 2;
                bhf[jl] = *(const uint2*)&KV[boff];
                blf[jl] = *(const uint2*)&KV[2048 + boff];
            }
#pragma unroll
            for (int jl = 0; jl < 4; jl++) mma_bf16(o[jl], ah, blf[jl]);
#pragma unroll
            for (int jl = 0; jl < 4; jl++) mma_bf16(o[jl], al, bhf[jl]);
#pragma unroll
            for (int jl = 0; jl < 4; jl++) mma_bf16(o[jl], ah, bhf[jl]);
        }
    }

    // ---- epilogue ----
    const float invA = 1.0f / l_runA;
    const float invB = 1.0f / l_runB;
    const int b = bh >> 3, h = bh & 7;
    const int mA_g = b * SEQ + q0 + rA;
    const int mB_g = b * SEQ + q0 + rB;
#pragma unroll
    for (int jl = 0; jl < 4; jl++) {
#pragma unroll
        for (int rr = 0; rr < 2; rr++) {
            int e = h * HD + nh * 32 + jl * 8 + 2 * t + rr;
            float vA = o[jl][rr]     * invA;
            float vB = o[jl][rr + 2] * invB;
            __nv_bfloat16 hA, lA, hB, lB;
            split_bf16(vA, hA, lA);
            split_bf16(vB, hB, lB);
            size_t iA = afrag_e(mA_g, e);
            size_t iB = afrag_e(mB_g, e);
            att_hi[iA] = hA;  att_lo[iA] = lA;
            att_hi[iB] = hB;  att_lo[iB] = lB;
        }
    }
}

// ---------------------------------------------------------------------------
extern "C" void kernel_launch(void* const* d_in, const int* in_sizes, int n_in,
                              void* d_out, int out_size)
{
    const float* x     = (const float*)d_in[0];
    const float* pos_w = (const float*)d_in[1];
    const float* pos_b = (const float*)d_in[2];
    const float* wq    = (const float*)d_in[3];
    const float* bq    = (const float*)d_in[4];
    const float* wk    = (const float*)d_in[5];
    const float* bk    = (const float*)d_in[6];
    const float* wv    = (const float*)d_in[7];
    const float* bv    = (const float*)d_in[8];
    const float* wo    = (const float*)d_in[9];
    const float* bo    = (const float*)d_in[10];
    float* out = (float*)d_out;

    void* sp = nullptr;
    cudaGetSymbolAddress(&sp, g_scratch);
    __nv_bfloat16* base = (__nv_bfloat16*)sp;
    __nv_bfloat16* xt_hi  = base;
    __nv_bfloat16* xt_lo  = xt_hi + PLANE;
    __nv_bfloat16* q_hi   = xt_lo + PLANE;
    __nv_bfloat16* q_lo   = q_hi  + PLANE;
    __nv_bfloat16* k_hi   = q_lo  + PLANE;
    __nv_bfloat16* k_lo   = k_hi  + PLANE;
    __nv_bfloat16* v_hi   = k_lo  + PLANE;
    __nv_bfloat16* v_lo   = v_hi  + PLANE;
    __nv_bfloat16* att_hi = v_lo  + PLANE;
    __nv_bfloat16* att_lo = att_hi + PLANE;
    __nv_bfloat16* wsp    = att_lo + PLANE;
    __nv_bfloat16* wq_hi = wsp;              __nv_bfloat16* wq_lo = wq_hi + WPLANE;
    __nv_bfloat16* wk_hi = wq_lo + WPLANE;   __nv_bfloat16* wk_lo = wk_hi + WPLANE;
    __nv_bfloat16* wv_hi = wk_lo + WPLANE;   __nv_bfloat16* wv_lo = wv_hi + WPLANE;
    __nv_bfloat16* wo_hi = wv_lo + WPLANE;   __nv_bfloat16* wo_lo = wo_hi + WPLANE;

    cudaFuncSetAttribute(k_gemm, cudaFuncAttributeMaxDynamicSharedMemorySize, G_SMEMB);
    cudaFuncSetAttribute(k_flash_mma, cudaFuncAttributeMaxDynamicSharedMemorySize, F_SMEMB);

    {
        dim3 grid(EMB / 32, SEQ / 32, BATCH);
        dim3 block(32, 8);
        k_transpose_pe<<<grid, block>>>(x, pos_w, pos_b, xt_hi, xt_lo);
    }
    {
        dim3 grid((unsigned)(WPLANE / 256), 4);
        k_split4<<<grid, 256>>>(wq, wk, wv, wo, wsp);
    }
    // QKV fused (z selects set; Q pre-scaled by 0.125)
    {
        dim3 grid(EMB / 64, MTOT / 128, 3);
        k_gemm<<<grid, 256, G_SMEMB>>>(xt_hi, xt_lo,
                                       wq_hi, wq_lo, wk_hi, wk_lo, wv_hi, wv_lo,
                                       bq, bk, bv,
                                       q_hi, q_lo, k_hi, k_lo, v_hi, v_lo,
                                       out, -1);
    }
    {
        dim3 grid(SEQ / 64, BATCH * NH);
        k_flash_mma<<<grid, 256, F_SMEMB>>>(q_hi, q_lo, k_hi, k_lo, v_hi, v_lo,
                                            att_hi, att_lo);
    }
    // final projection -> fp32 [b,E,32,32]
    {
        dim3 grid(EMB / 64, MTOT / 128);
        k_gemm<<<grid, 256, G_SMEMB>>>(att_hi, att_lo,
                                       wo_hi, wo_lo, wo_hi, wo_lo, wo_hi, wo_lo,
                                       bo, bo, bo,
                                       q_hi, q_lo, q_hi, q_lo, q_hi, q_lo,
                                       out, 3);
    }
}